// round 6
// baseline (speedup 1.0000x reference)
#include <cuda_runtime.h>
#include <cuda_bf16.h>
#include <math.h>
#include <cstdint>

// Problem constants
#define BB 2
#define SS 1024
#define HH 1024
#define NHH 16
#define HDD 64
#define SP_C 0.05f
#define EPS_C 1e-5f
#define SCALE_C 0.125f   // 1/sqrt(64)

#define M_TOT (BB*SS)    // 2048

// ---------------- scratch (device globals: no allocations allowed) ----------
__device__ float g_Q[M_TOT*HH];
__device__ float g_K[M_TOT*HH];
__device__ float g_V[M_TOT*HH];
__device__ float g_VT[BB*NHH*HDD*SS];   // V transposed per (b,h): [d][s]
__device__ float g_ctx[M_TOT*HH];
__device__ float g_pre[M_TOT*HH];
__device__ float g_WT[4*HH*HH];      // transposed tf32-rounded weights
__device__ float g_part[BB*32*HH];   // partial column sums of query over seq
__device__ float g_h1p[BB*8*512];    // spec layer-1 partials
__device__ float g_sp[BB*8];         // spec sigmoid-sum partials

// =====================  PTX helpers (mma.sync / cp.async)  ==================
__device__ __forceinline__ uint32_t smem_u32(const void* p) {
    uint32_t a;
    asm("{ .reg .u64 t; cvta.to.shared.u64 t, %1; cvt.u32.u64 %0, t; }"
        : "=r"(a) : "l"(p));
    return a;
}

__device__ __forceinline__ void cp16(uint32_t s, const float* g) {
    asm volatile("cp.async.cg.shared.global [%0], [%1], 16;"
                 :: "r"(s), "l"(__cvta_generic_to_global(g)));
}
#define CP_COMMIT() asm volatile("cp.async.commit_group;" ::: "memory")
#define CP_WAIT0()  asm volatile("cp.async.wait_group 0;" ::: "memory")
#define CP_WAIT1()  asm volatile("cp.async.wait_group 1;" ::: "memory")

__device__ __forceinline__ void ldsm4(uint32_t* r, uint32_t addr) {
    asm volatile("ldmatrix.sync.aligned.m8n8.x4.shared.b16 {%0,%1,%2,%3}, [%4];"
                 : "=r"(r[0]), "=r"(r[1]), "=r"(r[2]), "=r"(r[3]) : "r"(addr));
}
__device__ __forceinline__ void ldsm2(uint32_t* r, uint32_t addr) {
    asm volatile("ldmatrix.sync.aligned.m8n8.x2.shared.b16 {%0,%1}, [%2];"
                 : "=r"(r[0]), "=r"(r[1]) : "r"(addr));
}
__device__ __forceinline__ uint32_t f2tf(uint32_t x) {
    uint32_t y;
    asm("cvt.rna.tf32.f32 %0, %1;" : "=r"(y) : "r"(x));
    return y;
}
__device__ __forceinline__ float f2tf_f(float x) {
    uint32_t y;
    asm("cvt.rna.tf32.f32 %0, %1;" : "=r"(y) : "f"(x));
    return __uint_as_float(y);
}
__device__ __forceinline__ void mma8(float* d, const uint32_t* a, const uint32_t* b) {
    asm volatile("mma.sync.aligned.m16n8k8.row.col.f32.tf32.tf32.f32 "
                 "{%0,%1,%2,%3}, {%4,%5,%6,%7}, {%8,%9}, {%0,%1,%2,%3};"
                 : "+f"(d[0]), "+f"(d[1]), "+f"(d[2]), "+f"(d[3])
                 : "r"(a[0]), "r"(a[1]), "r"(a[2]), "r"(a[3]),
                   "r"(b[0]), "r"(b[1]));
}

// ======================  mma.sync tf32 GEMM body  ===========================
#define GK 1024
#define GN 1024
#define BKC 32
#define NKT (GK/BKC)
#define STAGE_B (128*36*4)    // 18432 B per matrix per stage
#define GSM_TOTAL (4*STAGE_B) // 73728 B

template<bool CVTA, bool ROUND_OUT>
__device__ __forceinline__ void gemm_body(
    char* smem, const float* __restrict__ A, const float* __restrict__ BT,
    const float* __restrict__ bias, const float* __restrict__ res,
    float* __restrict__ C, int bx, int by)
{
    uint32_t sb = smem_u32(smem);
    const int tid = threadIdx.x;
    const int lane = tid & 31;
    const int wid = tid >> 5;
    const int warp_m = wid >> 2;
    const int warp_n = wid & 3;
    const int row0 = by * 128;
    const int col0 = bx * 128;

    const float* Abase = A  + (size_t)row0 * GK;
    const float* Bbase = BT + (size_t)col0 * GK;

    auto load_stage = [&](int stage, int kt) {
        uint32_t as = sb + (stage * 2 + 0) * STAGE_B;
        uint32_t bs = sb + (stage * 2 + 1) * STAGE_B;
        const float* Ak = Abase + kt * BKC;
        const float* Bk = Bbase + kt * BKC;
        #pragma unroll
        for (int i = 0; i < 4; i++) {
            int c = tid + i * 256;
            int r = c >> 3, sg = c & 7;
            cp16(as + (uint32_t)(r * 144 + sg * 16), Ak + (size_t)r * GK + sg * 4);
            cp16(bs + (uint32_t)(r * 144 + sg * 16), Bk + (size_t)r * GK + sg * 4);
        }
        CP_COMMIT();
    };

    uint32_t a_off[4], b_off[4];
    #pragma unroll
    for (int mf = 0; mf < 4; mf++)
        a_off[mf] = (uint32_t)((warp_m * 64 + mf * 16 + (lane & 15)) * 144
                               + (lane >> 4) * 16);
    #pragma unroll
    for (int nf = 0; nf < 4; nf++)
        b_off[nf] = (uint32_t)((warp_n * 32 + nf * 8 + (lane & 7)) * 144
                               + ((lane >> 3) & 1) * 16);

    float acc[4][4][4] = {};

    load_stage(0, 0);
    int buf = 0;
    for (int kt = 0; kt < NKT; kt++) {
        if (kt + 1 < NKT) {
            load_stage(buf ^ 1, kt + 1);
            CP_WAIT1();
        } else {
            CP_WAIT0();
        }
        __syncthreads();

        uint32_t as = sb + (buf * 2 + 0) * STAGE_B;
        uint32_t bs = sb + (buf * 2 + 1) * STAGE_B;
        #pragma unroll
        for (int ks = 0; ks < 4; ks++) {
            uint32_t a[4][4], b[4][2];
            #pragma unroll
            for (int mf = 0; mf < 4; mf++) {
                ldsm4(a[mf], as + a_off[mf] + ks * 32);
                if (CVTA) {
                    #pragma unroll
                    for (int j = 0; j < 4; j++) a[mf][j] = f2tf(a[mf][j]);
                }
            }
            #pragma unroll
            for (int nf = 0; nf < 4; nf++)
                ldsm2(b[nf], bs + b_off[nf] + ks * 32);
            #pragma unroll
            for (int mf = 0; mf < 4; mf++)
                #pragma unroll
                for (int nf = 0; nf < 4; nf++)
                    mma8(acc[mf][nf], a[mf], b[nf]);
        }
        __syncthreads();
        buf ^= 1;
    }

    #pragma unroll
    for (int nf = 0; nf < 4; nf++) {
        int c = col0 + warp_n * 32 + nf * 8 + 2 * (lane & 3);
        float bx_ = __ldg(bias + c), by_ = __ldg(bias + c + 1);
        #pragma unroll
        for (int mf = 0; mf < 4; mf++) {
            int r = row0 + warp_m * 64 + mf * 16 + (lane >> 2);
            float2 v0 = make_float2(acc[mf][nf][0] + bx_, acc[mf][nf][1] + by_);
            float2 v1 = make_float2(acc[mf][nf][2] + bx_, acc[mf][nf][3] + by_);
            if (res) {
                float2 r0 = *(const float2*)(res + (size_t)r * GN + c);
                float2 r1 = *(const float2*)(res + (size_t)(r + 8) * GN + c);
                v0.x += r0.x; v0.y += r0.y;
                v1.x += r1.x; v1.y += r1.y;
            }
            if (ROUND_OUT) {
                v0.x = f2tf_f(v0.x); v0.y = f2tf_f(v0.y);
                v1.x = f2tf_f(v1.x); v1.y = f2tf_f(v1.y);
            }
            *(float2*)(C + (size_t)r * GN + c) = v0;
            *(float2*)(C + (size_t)(r + 8) * GN + c) = v1;
        }
    }
}

__global__ void __launch_bounds__(256, 1)
qkv_gemm(const float* q, const float* k, const float* v,
         const float* wq, const float* wk, const float* wv,
         const float* bq, const float* bk, const float* bv,
         float* oq, float* ok, float* ov)
{
    extern __shared__ char smem[];
    int z = blockIdx.z;
    const float* A  = (z == 0) ? q  : (z == 1) ? k  : v;
    const float* BT = (z == 0) ? wq : (z == 1) ? wk : wv;
    const float* bi = (z == 0) ? bq : (z == 1) ? bk : bv;
    float* C        = (z == 0) ? oq : (z == 1) ? ok : ov;
    gemm_body<true, true>(smem, A, BT, bi, nullptr, C, blockIdx.x, blockIdx.y);
}

__global__ void __launch_bounds__(256, 1)
o_gemm(const float* A, const float* BT, const float* bias,
       const float* res, float* C)
{
    extern __shared__ char smem[];
    gemm_body<false, false>(smem, A, BT, bias, res, C, blockIdx.x, blockIdx.y);
}

// ------------ fused weight transpose (+tf32 round) --------------------------
__global__ void trans2_kernel(const float* __restrict__ s0, float* __restrict__ d0,
                              const float* __restrict__ s1, float* __restrict__ d1)
{
    __shared__ float t[32][33];
    const float* src = blockIdx.z ? s1 : s0;
    float* dst = blockIdx.z ? d1 : d0;
    int x = blockIdx.x * 32 + threadIdx.x;
    int y0 = blockIdx.y * 32;
    #pragma unroll
    for (int i = threadIdx.y; i < 32; i += 8)
        t[i][threadIdx.x] = src[(size_t)(y0 + i) * HH + x];
    __syncthreads();
    int xo = blockIdx.y * 32 + threadIdx.x;
    int yo0 = blockIdx.x * 32;
    #pragma unroll
    for (int i = threadIdx.y; i < 32; i += 8)
        dst[(size_t)(yo0 + i) * HH + xo] = f2tf_f(t[threadIdx.x][i]);
}

// ---------------- per-(b,h) V transpose ----------------
__global__ void vtrans_kernel(const float* __restrict__ V, float* __restrict__ VT)
{
    __shared__ float t[32][33];
    int bh = blockIdx.z;
    int s0 = blockIdx.x * 32, d0 = blockIdx.y * 32;
    int b = bh >> 4, h = bh & 15;
    const float* src = V + ((size_t)b * SS + s0) * HH + h * HDD + d0;
    #pragma unroll
    for (int i = threadIdx.y; i < 32; i += 8)
        t[i][threadIdx.x] = src[(size_t)i * HH + threadIdx.x];
    __syncthreads();
    float* dst = VT + ((size_t)bh * HDD + d0) * SS + s0;
    #pragma unroll
    for (int i = threadIdx.y; i < 32; i += 8)
        dst[(size_t)i * SS + threadIdx.x] = t[threadIdx.x][i];
}

// ---------------- query column means: 64 blocks ----------------
__global__ void qmean_part(const float* __restrict__ q)
{
    int b = blockIdx.y, ch = blockIdx.x;     // 32 chunks of 32 rows
    int tid = threadIdx.x;
    for (int c = tid; c < HH; c += 256) {
        const float* base = q + ((size_t)b * SS + ch * 32) * HH + c;
        float s = 0.f;
        #pragma unroll 4
        for (int r = 0; r < 32; r++) s += base[(size_t)r * HH];
        g_part[((size_t)b * 32 + ch) * HH + c] = s;
    }
}

// -------- spec layer-1 partials: grid(8 rowchunks, 4 colgroups, BB) --------
__global__ void spec1_kernel(const float* __restrict__ Ws1)
{
    __shared__ float sin_s[128];
    int b = blockIdx.z, ch = blockIdx.x, cg = blockIdx.y;
    int tid = threadIdx.x;          // 128
    int r0 = ch * 128;
    {
        float s = 0.f;
        #pragma unroll
        for (int p = 0; p < 32; p++) s += g_part[((size_t)b * 32 + p) * HH + r0 + tid];
        sin_s[tid] = s * (1.0f / SS);
    }
    __syncthreads();
    int col = cg * 128 + tid;
    float acc = 0.f;
    #pragma unroll 4
    for (int j = 0; j < 128; j++)
        acc += sin_s[j] * Ws1[(size_t)(r0 + j) * 512 + col];
    g_h1p[(size_t)(b * 8 + ch) * 512 + col] = acc;
}

// -------- spec layer-2: grid(8 colblocks, BB); sigmoid partial sums --------
__global__ void spec2_kernel(const float* __restrict__ bs1,
                             const float* __restrict__ Ws2,
                             const float* __restrict__ bs2)
{
    __shared__ float h1[512];
    __shared__ float red[128];
    int b = blockIdx.y, cb = blockIdx.x;
    int tid = threadIdx.x;          // 128
    for (int c = tid; c < 512; c += 128) {
        float s = bs1[c];
        #pragma unroll
        for (int ch = 0; ch < 8; ch++) s += g_h1p[(size_t)(b * 8 + ch) * 512 + c];
        h1[c] = fmaxf(s, 0.f);
    }
    __syncthreads();
    int col = cb * 128 + tid;
    float z = bs2[col];
    #pragma unroll 4
    for (int i = 0; i < 512; i++) z += h1[i] * Ws2[(size_t)i * HH + col];
    red[tid] = 1.0f / (1.0f + __expf(-z));
    __syncthreads();
    for (int off = 64; off > 0; off >>= 1) {
        if (tid < off) red[tid] += red[tid + off];
        __syncthreads();
    }
    if (tid == 0) g_sp[b * 8 + cb] = red[0];
}

// ================  tensor-core flash attention (pipelined)  =================
// Q fragments in registers; K/V double-buffered; Q staged through P region.
#define ASTR 272                         // bytes per smem row (68 floats)
#define K0_OFF 0
#define K1_OFF (64*ASTR)
#define V0_OFF (2*64*ASTR)
#define V1_OFF (3*64*ASTR)
#define P_OFF  (4*64*ASTR)               // P / Q-staging: 128 rows
#define A_SMEM (P_OFF + 128*ASTR)        // 104448 bytes

__global__ void __launch_bounds__(256, 2)
attn_mma(const float* __restrict__ msb)
{
    extern __shared__ char smem[];
    __shared__ float red[256];
    __shared__ float mh_s;
    uint32_t sb = smem_u32(smem);
    const int tid = threadIdx.x;
    const int lane = tid & 31;
    const int w = tid >> 5;
    const int b = blockIdx.z, h = blockIdx.y, q0 = blockIdx.x << 7;

    const uint32_t Pa = sb + P_OFF + (uint32_t)((16 * w + (lane & 15)) * ASTR + (lane >> 4) * 16);
    const uint32_t brow = (uint32_t)(((((lane >> 4) << 3) + (lane & 7)) * ASTR) + ((lane >> 3) & 1) * 16);
    const uint32_t Kb[2] = { sb + K0_OFF + brow, sb + K1_OFF + brow };
    const uint32_t Vb[2] = { sb + V0_OFF + brow, sb + V1_OFF + brow };
    const uint32_t koff[2] = { K0_OFF, K1_OFF };
    const uint32_t voff[2] = { V0_OFF, V1_OFF };

    const float* Kg0 = g_K + (size_t)b * SS * HH + h * HDD;
    const float* Vg0 = g_VT + (size_t)(b * NHH + h) * HDD * SS;

    // ---- prologue: stage Q into P region; load K0/V0; reduce msb ----
    {
        const float* Qg = g_Q + ((size_t)b * SS + q0) * HH + h * HDD;
        #pragma unroll
        for (int i = 0; i < 8; i++) {
            int f = tid + i * 256;
            int r = f >> 4, c4 = f & 15;
            cp16(sb + P_OFF + (uint32_t)(r * ASTR + c4 * 16),
                 Qg + (size_t)r * HH + c4 * 4);
        }
        #pragma unroll
        for (int i = 0; i < 4; i++) {
            int f = tid + i * 256;
            int r = f >> 4, c4 = f & 15;
            cp16(sb + K0_OFF + (uint32_t)(r * ASTR + c4 * 16),
                 Kg0 + (size_t)r * HH + c4 * 4);
            cp16(sb + V0_OFF + (uint32_t)(r * ASTR + c4 * 16),
                 Vg0 + (size_t)r * SS + c4 * 4);
        }
        CP_COMMIT();
    }
    {
        const float* p = msb + (size_t)h * HDD * HDD;
        float s = 0.f;
        for (int i = tid; i < HDD * HDD; i += 256) s += p[i];
        red[tid] = s;
        __syncthreads();
        for (int off = 128; off > 0; off >>= 1) {
            if (tid < off) red[tid] += red[tid + off];
            __syncthreads();
        }
        if (tid == 0) mh_s = red[0] * (1.0f / (HDD * HDD));
        __syncthreads();
    }
    const float mh = mh_s;
    float sp = 0.f;
    #pragma unroll
    for (int j = 0; j < 8; j++) sp += g_sp[b * 8 + j];
    sp *= (1.0f / HH);

    CP_WAIT0();
    __syncthreads();

    // ---- Q fragments into registers (loop-invariant) ----
    uint32_t qf[8][4];
    #pragma unroll
    for (int ks = 0; ks < 8; ks++) ldsm4(qf[ks], Pa + ks * 32);
    // each warp reads only its own 16 rows of the staging area and later
    // writes P to the same rows -> warp-local hazard only (ldmatrix is
    // warp-synchronous), no extra block sync needed.

    float oacc[8][4] = {};
    float m0 = -1e30f, m1 = -1e30f, l0 = 0.f, l1 = 0.f;

    for (int kt = 0; kt < 16; kt++) {
        int cur = kt & 1;
        // prefetch kt+1 into the other buffer (overlaps all compute below)
        if (kt + 1 < 16) {
            int nxt = cur ^ 1;
            const float* Kg = Kg0 + (size_t)(kt + 1) * 64 * HH;
            const float* Vg = Vg0 + (kt + 1) * 64;
            #pragma unroll
            for (int i = 0; i < 4; i++) {
                int f = tid + i * 256;
                int r = f >> 4, c4 = f & 15;
                cp16(sb + koff[nxt] + (uint32_t)(r * ASTR + c4 * 16),
                     Kg + (size_t)r * HH + c4 * 4);
                cp16(sb + voff[nxt] + (uint32_t)(r * ASTR + c4 * 16),
                     Vg + (size_t)r * SS + c4 * 4);
            }
            CP_COMMIT();
        }

        // ---- S = Q @ K^T ----
        float sacc[8][4] = {};
        #pragma unroll
        for (int ks = 0; ks < 8; ks++) {
            #pragma unroll
            for (int kb = 0; kb < 4; kb++) {
                uint32_t bb[4];
                ldsm4(bb, Kb[cur] + kb * 16 * ASTR + ks * 32);
                mma8(sacc[2 * kb],     qf[ks], bb);
                mma8(sacc[2 * kb + 1], qf[ks], bb + 2);
            }
        }

        // ---- gate + online softmax ----
        float tm0 = -1e30f, tm1 = -1e30f;
        #pragma unroll
        for (int nf = 0; nf < 8; nf++) {
            #pragma unroll
            for (int j = 0; j < 4; j++) {
                float s0 = sacc[nf][j] * SCALE_C;
                float e = 1.0f / (1.0f + __expf(-s0 * mh));
                float p = s0 * (1.0f + e * SP_C) * sp;
                sacc[nf][j] = p;
                if (j < 2) tm0 = fmaxf(tm0, p); else tm1 = fmaxf(tm1, p);
            }
        }
        tm0 = fmaxf(tm0, __shfl_xor_sync(0xffffffff, tm0, 1));
        tm0 = fmaxf(tm0, __shfl_xor_sync(0xffffffff, tm0, 2));
        tm1 = fmaxf(tm1, __shfl_xor_sync(0xffffffff, tm1, 1));
        tm1 = fmaxf(tm1, __shfl_xor_sync(0xffffffff, tm1, 2));

        float nm0 = fmaxf(m0, tm0), nm1 = fmaxf(m1, tm1);
        float sc0 = __expf(m0 - nm0), sc1 = __expf(m1 - nm1);
        float su0 = 0.f, su1 = 0.f;
        #pragma unroll
        for (int nf = 0; nf < 8; nf++) {
            float p0 = __expf(sacc[nf][0] - nm0);
            float p1 = __expf(sacc[nf][1] - nm0);
            float p2 = __expf(sacc[nf][2] - nm1);
            float p3 = __expf(sacc[nf][3] - nm1);
            su0 += p0 + p1; su1 += p2 + p3;
            sacc[nf][0] = p0; sacc[nf][1] = p1;
            sacc[nf][2] = p2; sacc[nf][3] = p3;
        }
        su0 += __shfl_xor_sync(0xffffffff, su0, 1);
        su0 += __shfl_xor_sync(0xffffffff, su0, 2);
        su1 += __shfl_xor_sync(0xffffffff, su1, 1);
        su1 += __shfl_xor_sync(0xffffffff, su1, 2);
        l0 = l0 * sc0 + su0;
        l1 = l1 * sc1 + su1;
        m0 = nm0; m1 = nm1;

        #pragma unroll
        for (int nf = 0; nf < 8; nf++) {
            oacc[nf][0] *= sc0; oacc[nf][1] *= sc0;
            oacc[nf][2] *= sc1; oacc[nf][3] *= sc1;
        }

        // ---- write P (tf32-rounded) to warp-local rows ----
        {
            int r0 = 16 * w + (lane >> 2);
            uint32_t p0a = (uint32_t)(P_OFF + r0 * ASTR + 2 * (lane & 3) * 4);
            #pragma unroll
            for (int nf = 0; nf < 8; nf++) {
                float2 v0 = make_float2(f2tf_f(sacc[nf][0]), f2tf_f(sacc[nf][1]));
                float2 v1 = make_float2(f2tf_f(sacc[nf][2]), f2tf_f(sacc[nf][3]));
                *(float2*)(smem + p0a + nf * 32) = v0;
                *(float2*)(smem + p0a + 8 * ASTR + nf * 32) = v1;
            }
        }
        __syncwarp();

        // ---- O += P @ V ----
        #pragma unroll
        for (int ks = 0; ks < 8; ks++) {
            uint32_t a[4];
            ldsm4(a, Pa + ks * 32);
            #pragma unroll
            for (int db = 0; db < 4; db++) {
                uint32_t bb[4];
                ldsm4(bb, Vb[cur] + db * 16 * ASTR + ks * 32);
                mma8(oacc[2 * db],     a, bb);
                mma8(oacc[2 * db + 1], a, bb + 2);
            }
        }

        if (kt + 1 < 16) CP_WAIT0();
        __syncthreads();   // cur buffers free for reuse; nxt data visible
    }

    // ---- epilogue: normalize + store ctx (tf32-rounded) ----
    float inv0 = 1.0f / l0, inv1 = 1.0f / l1;
    float* Og = g_ctx + ((size_t)b * SS + q0) * HH + h * HDD;
    int r0 = 16 * w + (lane >> 2);
    #pragma unroll
    for (int nf = 0; nf < 8; nf++) {
        int c = 8 * nf + 2 * (lane & 3);
        *(float2*)&Og[(size_t)r0 * HH + c] =
            make_float2(f2tf_f(oacc[nf][0] * inv0), f2tf_f(oacc[nf][1] * inv0));
        *(float2*)&Og[(size_t)(r0 + 8) * HH + c] =
            make_float2(f2tf_f(oacc[nf][2] * inv1), f2tf_f(oacc[nf][3] * inv1));
    }
}

// ---------------- row LayerNorm ----------------
__global__ void ln_kernel(const float* __restrict__ x,
                          const float* __restrict__ g,
                          const float* __restrict__ bta,
                          float* __restrict__ out)
{
    __shared__ float r1[256];
    __shared__ float r2[256];
    int row = blockIdx.x, tid = threadIdx.x;
    const float4* xr = (const float4*)(x + (size_t)row * HH);
    float4 a = xr[tid];
    float s = a.x + a.y + a.z + a.w;
    float ss = a.x * a.x + a.y * a.y + a.z * a.z + a.w * a.w;
    r1[tid] = s; r2[tid] = ss;
    __syncthreads();
    for (int off = 128; off > 0; off >>= 1) {
        if (tid < off) { r1[tid] += r1[tid + off]; r2[tid] += r2[tid + off]; }
        __syncthreads();
    }
    float mu = r1[0] * (1.0f / HH);
    float var = r2[0] * (1.0f / HH) - mu * mu;
    float rstd = rsqrtf(var + EPS_C);
    float4 gg = ((const float4*)g)[tid];
    float4 bb = ((const float4*)bta)[tid];
    float4 o;
    o.x = (a.x - mu) * rstd * gg.x + bb.x;
    o.y = (a.y - mu) * rstd * gg.y + bb.y;
    o.z = (a.z - mu) * rstd * gg.z + bb.z;
    o.w = (a.w - mu) * rstd * gg.w + bb.w;
    ((float4*)(out + (size_t)row * HH))[tid] = o;
}

// ---------------- launch ----------------
extern "C" void kernel_launch(void* const* d_in, const int* in_sizes, int n_in,
                              void* d_out, int out_size)
{
    const float* query = (const float*)d_in[0];
    const float* key_t = (const float*)d_in[1];
    const float* value = (const float*)d_in[2];
    const float* Wq = (const float*)d_in[3];
    const float* bq = (const float*)d_in[4];
    const float* Wk = (const float*)d_in[5];
    const float* bk = (const float*)d_in[6];
    const float* Wv = (const float*)d_in[7];
    const float* bv = (const float*)d_in[8];
    const float* msb = (const float*)d_in[9];
    const float* Ws1 = (const float*)d_in[10];
    const float* bs1 = (const float*)d_in[11];
    const float* Ws2 = (const float*)d_in[12];
    const float* bs2 = (const float*)d_in[13];
    const float* Wo = (const float*)d_in[14];
    const float* bo = (const float*)d_in[15];
    const float* ln_g = (const float*)d_in[16];
    const float* ln_b = (const float*)d_in[17];

    float *pQ, *pK, *pV, *pVT, *pCtx, *pPre, *pWT;
    cudaGetSymbolAddress((void**)&pQ, g_Q);
    cudaGetSymbolAddress((void**)&pK, g_K);
    cudaGetSymbolAddress((void**)&pV, g_V);
    cudaGetSymbolAddress((void**)&pVT, g_VT);
    cudaGetSymbolAddress((void**)&pCtx, g_ctx);
    cudaGetSymbolAddress((void**)&pPre, g_pre);
    cudaGetSymbolAddress((void**)&pWT, g_WT);

    float* WTq = pWT + 0 * HH * HH;
    float* WTk = pWT + 1 * HH * HH;
    float* WTv = pWT + 2 * HH * HH;
    float* WTo = pWT + 3 * HH * HH;

    cudaFuncSetAttribute(qkv_gemm, cudaFuncAttributeMaxDynamicSharedMemorySize,
                         GSM_TOTAL);
    cudaFuncSetAttribute(o_gemm, cudaFuncAttributeMaxDynamicSharedMemorySize,
                         GSM_TOTAL);
    cudaFuncSetAttribute(attn_mma, cudaFuncAttributeMaxDynamicSharedMemorySize,
                         A_SMEM);

    dim3 tb(32, 8);
    dim3 tg2(32, 32, 2);

    // 0-1: weight transposes (+tf32 rounding)
    trans2_kernel<<<tg2, tb>>>(Wq, WTq, Wk, WTk);
    trans2_kernel<<<tg2, tb>>>(Wv, WTv, Wo, WTo);
    // 2-4: spec MLP chain (wide)
    qmean_part<<<dim3(32, BB), 256>>>(query);
    spec1_kernel<<<dim3(8, 4, BB), 128>>>(Ws1);
    spec2_kernel<<<dim3(8, BB), 128>>>(bs1, Ws2, bs2);
    // 5: fused Q/K/V projection GEMM
    qkv_gemm<<<dim3(GN / 128, M_TOT / 128, 3), 256, GSM_TOTAL>>>(
        query, key_t, value, WTq, WTk, WTv, bq, bk, bv, pQ, pK, pV);
    // 6: V transpose for attention B-operand
    vtrans_kernel<<<dim3(SS / 32, HDD / 32, BB * NHH), tb>>>(pV, pVT);
    // 7: pipelined tensor-core flash attention
    attn_mma<<<dim3(SS / 128, NHH, BB), 256, A_SMEM>>>(msb);
    // 8: output projection + bias + residual
    o_gemm<<<dim3(GN / 128, M_TOT / 128), 256, GSM_TOTAL>>>(pCtx, WTo, bo, query, pPre);
    // 9: LayerNorm -> d_out
    ln_kernel<<<M_TOT, 256>>>(pPre, ln_g, ln_b, (float*)d_out);
}

// round 7
// speedup vs baseline: 1.2717x; 1.2717x over previous
#include <cuda_runtime.h>
#include <cuda_bf16.h>
#include <math.h>
#include <cstdint>

// Problem constants
#define BB 2
#define SS 1024
#define HH 1024
#define NHH 16
#define HDD 64
#define SP_C 0.05f
#define EPS_C 1e-5f
#define SCALE_C 0.125f   // 1/sqrt(64)

#define M_TOT (BB*SS)    // 2048

// ---------------- scratch (device globals: no allocations allowed) ----------
__device__ float g_Q[M_TOT*HH];
__device__ float g_K[M_TOT*HH];
__device__ float g_V[M_TOT*HH];
__device__ float g_VT[BB*NHH*HDD*SS];   // V transposed per (b,h): [d][s]
__device__ float g_ctx[M_TOT*HH];
__device__ float g_pre[M_TOT*HH];
__device__ float g_WT[4*HH*HH];      // transposed tf32-rounded weights
__device__ float g_part[BB*32*HH];   // partial column sums of query over seq
__device__ float g_h1p[BB*32*512];   // spec layer-1 partials
__device__ float g_sp[BB*16];        // spec sigmoid-sum partials

// =====================  PTX helpers (mma.sync / cp.async)  ==================
__device__ __forceinline__ uint32_t smem_u32(const void* p) {
    uint32_t a;
    asm("{ .reg .u64 t; cvta.to.shared.u64 t, %1; cvt.u32.u64 %0, t; }"
        : "=r"(a) : "l"(p));
    return a;
}

__device__ __forceinline__ void cp16(uint32_t s, const float* g) {
    asm volatile("cp.async.cg.shared.global [%0], [%1], 16;"
                 :: "r"(s), "l"(__cvta_generic_to_global(g)));
}
#define CP_COMMIT() asm volatile("cp.async.commit_group;" ::: "memory")
#define CP_WAIT0()  asm volatile("cp.async.wait_group 0;" ::: "memory")
#define CP_WAIT1()  asm volatile("cp.async.wait_group 1;" ::: "memory")

__device__ __forceinline__ void ldsm4(uint32_t* r, uint32_t addr) {
    asm volatile("ldmatrix.sync.aligned.m8n8.x4.shared.b16 {%0,%1,%2,%3}, [%4];"
                 : "=r"(r[0]), "=r"(r[1]), "=r"(r[2]), "=r"(r[3]) : "r"(addr));
}
__device__ __forceinline__ void ldsm2(uint32_t* r, uint32_t addr) {
    asm volatile("ldmatrix.sync.aligned.m8n8.x2.shared.b16 {%0,%1}, [%2];"
                 : "=r"(r[0]), "=r"(r[1]) : "r"(addr));
}
__device__ __forceinline__ uint32_t f2tf(uint32_t x) {
    uint32_t y;
    asm("cvt.rna.tf32.f32 %0, %1;" : "=r"(y) : "r"(x));
    return y;
}
__device__ __forceinline__ float f2tf_f(float x) {
    uint32_t y;
    asm("cvt.rna.tf32.f32 %0, %1;" : "=r"(y) : "f"(x));
    return __uint_as_float(y);
}
__device__ __forceinline__ void mma8(float* d, const uint32_t* a, const uint32_t* b) {
    asm volatile("mma.sync.aligned.m16n8k8.row.col.f32.tf32.tf32.f32 "
                 "{%0,%1,%2,%3}, {%4,%5,%6,%7}, {%8,%9}, {%0,%1,%2,%3};"
                 : "+f"(d[0]), "+f"(d[1]), "+f"(d[2]), "+f"(d[3])
                 : "r"(a[0]), "r"(a[1]), "r"(a[2]), "r"(a[3]),
                   "r"(b[0]), "r"(b[1]));
}

// ======================  mma.sync tf32 GEMM body  ===========================
#define GK 1024
#define GN 1024
#define BKC 32
#define NKT (GK/BKC)
#define STAGE_B (128*36*4)    // 18432 B per matrix per stage
#define GSM_TOTAL (4*STAGE_B) // 73728 B

template<bool CVTA, bool ROUND_OUT>
__device__ __forceinline__ void gemm_body(
    char* smem, const float* __restrict__ A, const float* __restrict__ BT,
    const float* __restrict__ bias, const float* __restrict__ res,
    float* __restrict__ C, int bx, int by)
{
    uint32_t sb = smem_u32(smem);
    const int tid = threadIdx.x;
    const int lane = tid & 31;
    const int wid = tid >> 5;
    const int warp_m = wid >> 2;
    const int warp_n = wid & 3;
    const int row0 = by * 128;
    const int col0 = bx * 128;

    const float* Abase = A  + (size_t)row0 * GK;
    const float* Bbase = BT + (size_t)col0 * GK;

    auto load_stage = [&](int stage, int kt) {
        uint32_t as = sb + (stage * 2 + 0) * STAGE_B;
        uint32_t bs = sb + (stage * 2 + 1) * STAGE_B;
        const float* Ak = Abase + kt * BKC;
        const float* Bk = Bbase + kt * BKC;
        #pragma unroll
        for (int i = 0; i < 4; i++) {
            int c = tid + i * 256;
            int r = c >> 3, sg = c & 7;
            cp16(as + (uint32_t)(r * 144 + sg * 16), Ak + (size_t)r * GK + sg * 4);
            cp16(bs + (uint32_t)(r * 144 + sg * 16), Bk + (size_t)r * GK + sg * 4);
        }
        CP_COMMIT();
    };

    uint32_t a_off[4], b_off[4];
    #pragma unroll
    for (int mf = 0; mf < 4; mf++)
        a_off[mf] = (uint32_t)((warp_m * 64 + mf * 16 + (lane & 15)) * 144
                               + (lane >> 4) * 16);
    #pragma unroll
    for (int nf = 0; nf < 4; nf++)
        b_off[nf] = (uint32_t)((warp_n * 32 + nf * 8 + (lane & 7)) * 144
                               + ((lane >> 3) & 1) * 16);

    float acc[4][4][4] = {};

    load_stage(0, 0);
    int buf = 0;
    for (int kt = 0; kt < NKT; kt++) {
        if (kt + 1 < NKT) {
            load_stage(buf ^ 1, kt + 1);
            CP_WAIT1();
        } else {
            CP_WAIT0();
        }
        __syncthreads();

        uint32_t as = sb + (buf * 2 + 0) * STAGE_B;
        uint32_t bs = sb + (buf * 2 + 1) * STAGE_B;
        #pragma unroll
        for (int ks = 0; ks < 4; ks++) {
            uint32_t a[4][4], b[4][2];
            #pragma unroll
            for (int mf = 0; mf < 4; mf++) {
                ldsm4(a[mf], as + a_off[mf] + ks * 32);
                if (CVTA) {
                    #pragma unroll
                    for (int j = 0; j < 4; j++) a[mf][j] = f2tf(a[mf][j]);
                }
            }
            #pragma unroll
            for (int nf = 0; nf < 4; nf++)
                ldsm2(b[nf], bs + b_off[nf] + ks * 32);
            #pragma unroll
            for (int mf = 0; mf < 4; mf++)
                #pragma unroll
                for (int nf = 0; nf < 4; nf++)
                    mma8(acc[mf][nf], a[mf], b[nf]);
        }
        __syncthreads();
        buf ^= 1;
    }

    #pragma unroll
    for (int nf = 0; nf < 4; nf++) {
        int c = col0 + warp_n * 32 + nf * 8 + 2 * (lane & 3);
        float bx_ = __ldg(bias + c), by_ = __ldg(bias + c + 1);
        #pragma unroll
        for (int mf = 0; mf < 4; mf++) {
            int r = row0 + warp_m * 64 + mf * 16 + (lane >> 2);
            float2 v0 = make_float2(acc[mf][nf][0] + bx_, acc[mf][nf][1] + by_);
            float2 v1 = make_float2(acc[mf][nf][2] + bx_, acc[mf][nf][3] + by_);
            if (res) {
                float2 r0 = *(const float2*)(res + (size_t)r * GN + c);
                float2 r1 = *(const float2*)(res + (size_t)(r + 8) * GN + c);
                v0.x += r0.x; v0.y += r0.y;
                v1.x += r1.x; v1.y += r1.y;
            }
            if (ROUND_OUT) {
                v0.x = f2tf_f(v0.x); v0.y = f2tf_f(v0.y);
                v1.x = f2tf_f(v1.x); v1.y = f2tf_f(v1.y);
            }
            *(float2*)(C + (size_t)r * GN + c) = v0;
            *(float2*)(C + (size_t)(r + 8) * GN + c) = v1;
        }
    }
}

__global__ void __launch_bounds__(256, 2)
qkv_gemm(const float* q, const float* k, const float* v,
         const float* wq, const float* wk, const float* wv,
         const float* bq, const float* bk, const float* bv,
         float* oq, float* ok, float* ov)
{
    extern __shared__ char smem[];
    int z = blockIdx.z;
    const float* A  = (z == 0) ? q  : (z == 1) ? k  : v;
    const float* BT = (z == 0) ? wq : (z == 1) ? wk : wv;
    const float* bi = (z == 0) ? bq : (z == 1) ? bk : bv;
    float* C        = (z == 0) ? oq : (z == 1) ? ok : ov;
    gemm_body<true, true>(smem, A, BT, bi, nullptr, C, blockIdx.x, blockIdx.y);
}

__global__ void __launch_bounds__(256, 2)
o_gemm(const float* A, const float* BT, const float* bias,
       const float* res, float* C)
{
    extern __shared__ char smem[];
    gemm_body<false, false>(smem, A, BT, bias, res, C, blockIdx.x, blockIdx.y);
}

// ------------ fused weight transpose (+tf32 round) --------------------------
__global__ void trans2_kernel(const float* __restrict__ s0, float* __restrict__ d0,
                              const float* __restrict__ s1, float* __restrict__ d1)
{
    __shared__ float t[32][33];
    const float* src = blockIdx.z ? s1 : s0;
    float* dst = blockIdx.z ? d1 : d0;
    int x = blockIdx.x * 32 + threadIdx.x;
    int y0 = blockIdx.y * 32;
    #pragma unroll
    for (int i = threadIdx.y; i < 32; i += 8)
        t[i][threadIdx.x] = src[(size_t)(y0 + i) * HH + x];
    __syncthreads();
    int xo = blockIdx.y * 32 + threadIdx.x;
    int yo0 = blockIdx.x * 32;
    #pragma unroll
    for (int i = threadIdx.y; i < 32; i += 8)
        dst[(size_t)(yo0 + i) * HH + xo] = f2tf_f(t[threadIdx.x][i]);
}

// ---------------- per-(b,h) V transpose ----------------
__global__ void vtrans_kernel(const float* __restrict__ V, float* __restrict__ VT)
{
    __shared__ float t[32][33];
    int bh = blockIdx.z;
    int s0 = blockIdx.x * 32, d0 = blockIdx.y * 32;
    int b = bh >> 4, h = bh & 15;
    const float* src = V + ((size_t)b * SS + s0) * HH + h * HDD + d0;
    #pragma unroll
    for (int i = threadIdx.y; i < 32; i += 8)
        t[i][threadIdx.x] = src[(size_t)i * HH + threadIdx.x];
    __syncthreads();
    float* dst = VT + ((size_t)bh * HDD + d0) * SS + s0;
    #pragma unroll
    for (int i = threadIdx.y; i < 32; i += 8)
        dst[(size_t)i * SS + threadIdx.x] = t[threadIdx.x][i];
}

// ---------------- query column means: 64 blocks ----------------
__global__ void qmean_part(const float* __restrict__ q)
{
    int b = blockIdx.y, ch = blockIdx.x;     // 32 chunks of 32 rows
    int tid = threadIdx.x;
    for (int c = tid; c < HH; c += 256) {
        const float* base = q + ((size_t)b * SS + ch * 32) * HH + c;
        float s = 0.f;
        #pragma unroll 4
        for (int r = 0; r < 32; r++) s += base[(size_t)r * HH];
        g_part[((size_t)b * 32 + ch) * HH + c] = s;
    }
}

// -------- spec layer-1 partials: grid(32 rowchunks, 4 colgroups, BB) -------
// rowchunk = 32 rows -> 32-deep dot chain per thread; 256 blocks total.
__global__ void spec1_kernel(const float* __restrict__ Ws1)
{
    __shared__ float sin_s[32];
    int b = blockIdx.z, ch = blockIdx.x, cg = blockIdx.y;
    int tid = threadIdx.x;          // 128
    int r0 = ch * 32;
    if (tid < 32) {
        float s = 0.f;
        #pragma unroll
        for (int p = 0; p < 32; p++) s += g_part[((size_t)b * 32 + p) * HH + r0 + tid];
        sin_s[tid] = s * (1.0f / SS);
    }
    __syncthreads();
    int col = cg * 128 + tid;
    float acc = 0.f;
    #pragma unroll
    for (int j = 0; j < 32; j++)
        acc += sin_s[j] * Ws1[(size_t)(r0 + j) * 512 + col];
    g_h1p[(size_t)(b * 32 + ch) * 512 + col] = acc;
}

// -------- spec layer-2: grid(16 colblocks, BB), 256 thr --------------------
// block: 64 output cols, i-loop split 4-way (128-deep chains) + smem combine.
__global__ void spec2_kernel(const float* __restrict__ bs1,
                             const float* __restrict__ Ws2,
                             const float* __restrict__ bs2)
{
    __shared__ float h1[512];
    __shared__ float zp[4][64];
    __shared__ float red[64];
    int b = blockIdx.y, cb = blockIdx.x;
    int tid = threadIdx.x;          // 256
    for (int c = tid; c < 512; c += 256) {
        float s = bs1[c];
        #pragma unroll
        for (int ch = 0; ch < 32; ch++) s += g_h1p[(size_t)(b * 32 + ch) * 512 + c];
        h1[c] = fmaxf(s, 0.f);
    }
    __syncthreads();
    int col = cb * 64 + (tid & 63);
    int qq = tid >> 6;              // 0..3
    float z = 0.f;
    #pragma unroll 4
    for (int i = qq * 128; i < qq * 128 + 128; i++)
        z += h1[i] * Ws2[(size_t)i * HH + col];
    zp[qq][tid & 63] = z;
    __syncthreads();
    if (tid < 64) {
        float zz = bs2[cb * 64 + tid] + zp[0][tid] + zp[1][tid] + zp[2][tid] + zp[3][tid];
        red[tid] = 1.0f / (1.0f + __expf(-zz));
    }
    __syncthreads();
    for (int off = 32; off > 0; off >>= 1) {
        if (tid < off) red[tid] += red[tid + off];
        __syncthreads();
    }
    if (tid == 0) g_sp[b * 16 + cb] = red[0];
}

// ================  tensor-core flash attention (round-5 proven)  ============
#define ASTR 272                       // bytes per smem row (68 floats)
#define AQ_OFF 0                       // Q: 128 rows
#define AK_OFF (AQ_OFF + 128*ASTR)     // K: 64 rows
#define AV_OFF (AK_OFF + 64*ASTR)      // VT: 64 rows (d-major)
#define AP_OFF (AV_OFF + 64*ASTR)      // P: 128 rows
#define A_SMEM (AP_OFF + 128*ASTR)     // 104448 bytes

__global__ void __launch_bounds__(256, 2)
attn_mma(const float* __restrict__ msb)
{
    extern __shared__ char smem[];
    __shared__ float red[256];
    __shared__ float mh_s;
    uint32_t sb = smem_u32(smem);
    const int tid = threadIdx.x;
    const int lane = tid & 31;
    const int w = tid >> 5;
    const int b = blockIdx.z, h = blockIdx.y, q0 = blockIdx.x << 7;

    const uint32_t Qa = sb + AQ_OFF + (uint32_t)((16 * w + (lane & 15)) * ASTR + (lane >> 4) * 16);
    const uint32_t Pa = sb + AP_OFF + (uint32_t)((16 * w + (lane & 15)) * ASTR + (lane >> 4) * 16);
    const uint32_t Kb = sb + AK_OFF + (uint32_t)(((((lane >> 4) << 3) + (lane & 7)) * ASTR) + ((lane >> 3) & 1) * 16);
    const uint32_t Vb = sb + AV_OFF + (uint32_t)(((((lane >> 4) << 3) + (lane & 7)) * ASTR) + ((lane >> 3) & 1) * 16);

    // load Q tile (128 x 64)
    {
        const float* Qg = g_Q + ((size_t)b * SS + q0) * HH + h * HDD;
        #pragma unroll
        for (int i = 0; i < 8; i++) {
            int f = tid + i * 256;
            int r = f >> 4, c4 = f & 15;
            cp16(sb + AQ_OFF + (uint32_t)(r * ASTR + c4 * 16),
                 Qg + (size_t)r * HH + c4 * 4);
        }
        CP_COMMIT();
    }

    // per-head msb mean (block reduce, overlaps Q load)
    {
        const float* p = msb + (size_t)h * HDD * HDD;
        float s = 0.f;
        for (int i = tid; i < HDD * HDD; i += 256) s += p[i];
        red[tid] = s;
        __syncthreads();
        for (int off = 128; off > 0; off >>= 1) {
            if (tid < off) red[tid] += red[tid + off];
            __syncthreads();
        }
        if (tid == 0) mh_s = red[0] * (1.0f / (HDD * HDD));
        __syncthreads();
    }

    const float mh = mh_s;
    float sp = 0.f;
    #pragma unroll
    for (int j = 0; j < 16; j++) sp += g_sp[b * 16 + j];
    sp *= (1.0f / HH);

    float oacc[8][4] = {};
    float m0 = -1e30f, m1 = -1e30f, l0 = 0.f, l1 = 0.f;

    for (int kt = 0; kt < 16; kt++) {
        __syncthreads();
        {
            const float* Kg = g_K + ((size_t)b * SS + kt * 64) * HH + h * HDD;
            const float* Vg = g_VT + (size_t)(b * NHH + h) * HDD * SS + kt * 64;
            #pragma unroll
            for (int i = 0; i < 4; i++) {
                int f = tid + i * 256;
                int r = f >> 4, c4 = f & 15;
                cp16(sb + AK_OFF + (uint32_t)(r * ASTR + c4 * 16),
                     Kg + (size_t)r * HH + c4 * 4);
                cp16(sb + AV_OFF + (uint32_t)(r * ASTR + c4 * 16),
                     Vg + (size_t)r * SS + c4 * 4);
            }
            CP_COMMIT();
        }
        CP_WAIT0();
        __syncthreads();

        // ---- S = Q @ K^T ----
        float sacc[8][4] = {};
        #pragma unroll
        for (int ks = 0; ks < 8; ks++) {
            uint32_t a[4];
            ldsm4(a, Qa + ks * 32);
            #pragma unroll
            for (int kb = 0; kb < 4; kb++) {
                uint32_t bb[4];
                ldsm4(bb, Kb + kb * 16 * ASTR + ks * 32);
                mma8(sacc[2 * kb],     a, bb);
                mma8(sacc[2 * kb + 1], a, bb + 2);
            }
        }

        // ---- gate + online softmax ----
        float tm0 = -1e30f, tm1 = -1e30f;
        #pragma unroll
        for (int nf = 0; nf < 8; nf++) {
            #pragma unroll
            for (int j = 0; j < 4; j++) {
                float s0 = sacc[nf][j] * SCALE_C;
                float e = 1.0f / (1.0f + __expf(-s0 * mh));
                float p = s0 * (1.0f + e * SP_C) * sp;
                sacc[nf][j] = p;
                if (j < 2) tm0 = fmaxf(tm0, p); else tm1 = fmaxf(tm1, p);
            }
        }
        tm0 = fmaxf(tm0, __shfl_xor_sync(0xffffffff, tm0, 1));
        tm0 = fmaxf(tm0, __shfl_xor_sync(0xffffffff, tm0, 2));
        tm1 = fmaxf(tm1, __shfl_xor_sync(0xffffffff, tm1, 1));
        tm1 = fmaxf(tm1, __shfl_xor_sync(0xffffffff, tm1, 2));

        float nm0 = fmaxf(m0, tm0), nm1 = fmaxf(m1, tm1);
        float sc0 = __expf(m0 - nm0), sc1 = __expf(m1 - nm1);
        float su0 = 0.f, su1 = 0.f;
        #pragma unroll
        for (int nf = 0; nf < 8; nf++) {
            float p0 = __expf(sacc[nf][0] - nm0);
            float p1 = __expf(sacc[nf][1] - nm0);
            float p2 = __expf(sacc[nf][2] - nm1);
            float p3 = __expf(sacc[nf][3] - nm1);
            su0 += p0 + p1; su1 += p2 + p3;
            sacc[nf][0] = p0; sacc[nf][1] = p1;
            sacc[nf][2] = p2; sacc[nf][3] = p3;
        }
        su0 += __shfl_xor_sync(0xffffffff, su0, 1);
        su0 += __shfl_xor_sync(0xffffffff, su0, 2);
        su1 += __shfl_xor_sync(0xffffffff, su1, 1);
        su1 += __shfl_xor_sync(0xffffffff, su1, 2);
        l0 = l0 * sc0 + su0;
        l1 = l1 * sc1 + su1;
        m0 = nm0; m1 = nm1;

        #pragma unroll
        for (int nf = 0; nf < 8; nf++) {
            oacc[nf][0] *= sc0; oacc[nf][1] *= sc0;
            oacc[nf][2] *= sc1; oacc[nf][3] *= sc1;
        }

        // ---- write P (tf32-rounded) to smem ----
        {
            int r0 = 16 * w + (lane >> 2);
            uint32_t p0a = (uint32_t)(AP_OFF + r0 * ASTR + 2 * (lane & 3) * 4);
            #pragma unroll
            for (int nf = 0; nf < 8; nf++) {
                float2 v0 = make_float2(f2tf_f(sacc[nf][0]), f2tf_f(sacc[nf][1]));
                float2 v1 = make_float2(f2tf_f(sacc[nf][2]), f2tf_f(sacc[nf][3]));
                *(float2*)(smem + p0a + nf * 32) = v0;
                *(float2*)(smem + p0a + 8 * ASTR + nf * 32) = v1;
            }
        }
        __syncwarp();

        // ---- O += P @ V ----
        #pragma unroll
        for (int ks = 0; ks < 8; ks++) {
            uint32_t a[4];
            ldsm4(a, Pa + ks * 32);
            #pragma unroll
            for (int db = 0; db < 4; db++) {
                uint32_t bb[4];
                ldsm4(bb, Vb + db * 16 * ASTR + ks * 32);
                mma8(oacc[2 * db],     a, bb);
                mma8(oacc[2 * db + 1], a, bb + 2);
            }
        }
    }

    // ---- epilogue: normalize + store ctx (tf32-rounded) ----
    float inv0 = 1.0f / l0, inv1 = 1.0f / l1;
    float* Og = g_ctx + ((size_t)b * SS + q0) * HH + h * HDD;
    int r0 = 16 * w + (lane >> 2);
    #pragma unroll
    for (int nf = 0; nf < 8; nf++) {
        int c = 8 * nf + 2 * (lane & 3);
        *(float2*)&Og[(size_t)r0 * HH + c] =
            make_float2(f2tf_f(oacc[nf][0] * inv0), f2tf_f(oacc[nf][1] * inv0));
        *(float2*)&Og[(size_t)(r0 + 8) * HH + c] =
            make_float2(f2tf_f(oacc[nf][2] * inv1), f2tf_f(oacc[nf][3] * inv1));
    }
}

// ---------------- row LayerNorm ----------------
__global__ void ln_kernel(const float* __restrict__ x,
                          const float* __restrict__ g,
                          const float* __restrict__ bta,
                          float* __restrict__ out)
{
    __shared__ float r1[256];
    __shared__ float r2[256];
    int row = blockIdx.x, tid = threadIdx.x;
    const float4* xr = (const float4*)(x + (size_t)row * HH);
    float4 a = xr[tid];
    float s = a.x + a.y + a.z + a.w;
    float ss = a.x * a.x + a.y * a.y + a.z * a.z + a.w * a.w;
    r1[tid] = s; r2[tid] = ss;
    __syncthreads();
    for (int off = 128; off > 0; off >>= 1) {
        if (tid < off) { r1[tid] += r1[tid + off]; r2[tid] += r2[tid + off]; }
        __syncthreads();
    }
    float mu = r1[0] * (1.0f / HH);
    float var = r2[0] * (1.0f / HH) - mu * mu;
    float rstd = rsqrtf(var + EPS_C);
    float4 gg = ((const float4*)g)[tid];
    float4 bb = ((const float4*)bta)[tid];
    float4 o;
    o.x = (a.x - mu) * rstd * gg.x + bb.x;
    o.y = (a.y - mu) * rstd * gg.y + bb.y;
    o.z = (a.z - mu) * rstd * gg.z + bb.z;
    o.w = (a.w - mu) * rstd * gg.w + bb.w;
    ((float4*)(out + (size_t)row * HH))[tid] = o;
}

// ---------------- launch ----------------
extern "C" void kernel_launch(void* const* d_in, const int* in_sizes, int n_in,
                              void* d_out, int out_size)
{
    const float* query = (const float*)d_in[0];
    const float* key_t = (const float*)d_in[1];
    const float* value = (const float*)d_in[2];
    const float* Wq = (const float*)d_in[3];
    const float* bq = (const float*)d_in[4];
    const float* Wk = (const float*)d_in[5];
    const float* bk = (const float*)d_in[6];
    const float* Wv = (const float*)d_in[7];
    const float* bv = (const float*)d_in[8];
    const float* msb = (const float*)d_in[9];
    const float* Ws1 = (const float*)d_in[10];
    const float* bs1 = (const float*)d_in[11];
    const float* Ws2 = (const float*)d_in[12];
    const float* bs2 = (const float*)d_in[13];
    const float* Wo = (const float*)d_in[14];
    const float* bo = (const float*)d_in[15];
    const float* ln_g = (const float*)d_in[16];
    const float* ln_b = (const float*)d_in[17];

    float *pQ, *pK, *pV, *pVT, *pCtx, *pPre, *pWT;
    cudaGetSymbolAddress((void**)&pQ, g_Q);
    cudaGetSymbolAddress((void**)&pK, g_K);
    cudaGetSymbolAddress((void**)&pV, g_V);
    cudaGetSymbolAddress((void**)&pVT, g_VT);
    cudaGetSymbolAddress((void**)&pCtx, g_ctx);
    cudaGetSymbolAddress((void**)&pPre, g_pre);
    cudaGetSymbolAddress((void**)&pWT, g_WT);

    float* WTq = pWT + 0 * HH * HH;
    float* WTk = pWT + 1 * HH * HH;
    float* WTv = pWT + 2 * HH * HH;
    float* WTo = pWT + 3 * HH * HH;

    cudaFuncSetAttribute(qkv_gemm, cudaFuncAttributeMaxDynamicSharedMemorySize,
                         GSM_TOTAL);
    cudaFuncSetAttribute(o_gemm, cudaFuncAttributeMaxDynamicSharedMemorySize,
                         GSM_TOTAL);
    cudaFuncSetAttribute(attn_mma, cudaFuncAttributeMaxDynamicSharedMemorySize,
                         A_SMEM);

    dim3 tb(32, 8);
    dim3 tg2(32, 32, 2);

    // 0-1: weight transposes (+tf32 rounding)
    trans2_kernel<<<tg2, tb>>>(Wq, WTq, Wk, WTk);
    trans2_kernel<<<tg2, tb>>>(Wv, WTv, Wo, WTo);
    // 2-4: spec MLP chain (wide, short chains)
    qmean_part<<<dim3(32, BB), 256>>>(query);
    spec1_kernel<<<dim3(32, 4, BB), 128>>>(Ws1);
    spec2_kernel<<<dim3(16, BB), 256>>>(bs1, Ws2, bs2);
    // 5 (ncu -s 5 profiles this): fused Q/K/V projection GEMM, occ 2
    qkv_gemm<<<dim3(GN / 128, M_TOT / 128, 3), 256, GSM_TOTAL>>>(
        query, key_t, value, WTq, WTk, WTv, bq, bk, bv, pQ, pK, pV);
    // 6: V transpose for attention B-operand
    vtrans_kernel<<<dim3(SS / 32, HDD / 32, BB * NHH), tb>>>(pV, pVT);
    // 7: tensor-core flash attention (round-5 proven config)
    attn_mma<<<dim3(SS / 128, NHH, BB), 256, A_SMEM>>>(msb);
    // 8: output projection + bias + residual, occ 2
    o_gemm<<<dim3(GN / 128, M_TOT / 128), 256, GSM_TOTAL>>>(pCtx, WTo, bo, query, pPre);
    // 9: LayerNorm -> d_out
    ln_kernel<<<M_TOT, 256>>>(pPre, ln_g, ln_b, (float*)d_out);
}

// round 8
// speedup vs baseline: 1.3206x; 1.0385x over previous
#include <cuda_runtime.h>
#include <cuda_bf16.h>
#include <math.h>
#include <cstdint>

// Problem constants
#define BB 2
#define SS 1024
#define HH 1024
#define NHH 16
#define HDD 64
#define SP_C 0.05f
#define EPS_C 1e-5f
#define SCALE_C 0.125f   // 1/sqrt(64)

#define M_TOT (BB*SS)    // 2048

// ---------------- scratch (device globals: no allocations allowed) ----------
__device__ float g_Q[M_TOT*HH];
__device__ float g_K[M_TOT*HH];
__device__ float g_V[M_TOT*HH];
__device__ float g_VT[BB*NHH*HDD*SS];   // V transposed per (b,h): [d][s]
__device__ float g_ctx[M_TOT*HH];
__device__ float g_pre[M_TOT*HH];
__device__ float g_WT[4*HH*HH];      // transposed tf32-rounded weights
__device__ float g_part[BB*32*HH];   // partial column sums of query over seq
__device__ float g_h1p[BB*32*512];   // spec layer-1 partials
__device__ float g_sp[BB*16];        // spec sigmoid-sum partials

// =====================  PTX helpers (mma.sync / cp.async)  ==================
__device__ __forceinline__ uint32_t smem_u32(const void* p) {
    uint32_t a;
    asm("{ .reg .u64 t; cvta.to.shared.u64 t, %1; cvt.u32.u64 %0, t; }"
        : "=r"(a) : "l"(p));
    return a;
}

__device__ __forceinline__ void cp16(uint32_t s, const float* g) {
    asm volatile("cp.async.cg.shared.global [%0], [%1], 16;"
                 :: "r"(s), "l"(__cvta_generic_to_global(g)));
}
#define CP_COMMIT() asm volatile("cp.async.commit_group;" ::: "memory")
#define CP_WAIT0()  asm volatile("cp.async.wait_group 0;" ::: "memory")
#define CP_WAIT1()  asm volatile("cp.async.wait_group 1;" ::: "memory")

__device__ __forceinline__ void ldsm4(uint32_t* r, uint32_t addr) {
    asm volatile("ldmatrix.sync.aligned.m8n8.x4.shared.b16 {%0,%1,%2,%3}, [%4];"
                 : "=r"(r[0]), "=r"(r[1]), "=r"(r[2]), "=r"(r[3]) : "r"(addr));
}
__device__ __forceinline__ void ldsm2(uint32_t* r, uint32_t addr) {
    asm volatile("ldmatrix.sync.aligned.m8n8.x2.shared.b16 {%0,%1}, [%2];"
                 : "=r"(r[0]), "=r"(r[1]) : "r"(addr));
}
__device__ __forceinline__ float f2tf_f(float x) {
    uint32_t y;
    asm("cvt.rna.tf32.f32 %0, %1;" : "=r"(y) : "f"(x));
    return __uint_as_float(y);
}
// NOTE: mma.sync tf32 reads only the top 19 bits of the operand registers,
// so raw fp32 operands are implicitly truncated to tf32 by HW. We pre-round
// only the weights (RNA, free in transpose); activations ride HW truncation.
__device__ __forceinline__ void mma8(float* d, const uint32_t* a, const uint32_t* b) {
    asm volatile("mma.sync.aligned.m16n8k8.row.col.f32.tf32.tf32.f32 "
                 "{%0,%1,%2,%3}, {%4,%5,%6,%7}, {%8,%9}, {%0,%1,%2,%3};"
                 : "+f"(d[0]), "+f"(d[1]), "+f"(d[2]), "+f"(d[3])
                 : "r"(a[0]), "r"(a[1]), "r"(a[2]), "r"(a[3]),
                   "r"(b[0]), "r"(b[1]));
}

// ======================  mma.sync tf32 GEMM body  ===========================
#define GK 1024
#define GN 1024
#define BKC 32
#define NKT (GK/BKC)
#define STAGE_B (128*36*4)    // 18432 B per matrix per stage
#define GSM_TOTAL (4*STAGE_B) // 73728 B

__device__ __forceinline__ void gemm_body(
    char* smem, const float* __restrict__ A, const float* __restrict__ BT,
    const float* __restrict__ bias, const float* __restrict__ res,
    float* __restrict__ C, int bx, int by)
{
    uint32_t sb = smem_u32(smem);
    const int tid = threadIdx.x;
    const int lane = tid & 31;
    const int wid = tid >> 5;
    const int warp_m = wid >> 2;
    const int warp_n = wid & 3;
    const int row0 = by * 128;
    const int col0 = bx * 128;

    const float* Abase = A  + (size_t)row0 * GK;
    const float* Bbase = BT + (size_t)col0 * GK;

    auto load_stage = [&](int stage, int kt) {
        uint32_t as = sb + (stage * 2 + 0) * STAGE_B;
        uint32_t bs = sb + (stage * 2 + 1) * STAGE_B;
        const float* Ak = Abase + kt * BKC;
        const float* Bk = Bbase + kt * BKC;
        #pragma unroll
        for (int i = 0; i < 4; i++) {
            int c = tid + i * 256;
            int r = c >> 3, sg = c & 7;
            cp16(as + (uint32_t)(r * 144 + sg * 16), Ak + (size_t)r * GK + sg * 4);
            cp16(bs + (uint32_t)(r * 144 + sg * 16), Bk + (size_t)r * GK + sg * 4);
        }
        CP_COMMIT();
    };

    uint32_t a_off[4], b_off[4];
    #pragma unroll
    for (int mf = 0; mf < 4; mf++)
        a_off[mf] = (uint32_t)((warp_m * 64 + mf * 16 + (lane & 15)) * 144
                               + (lane >> 4) * 16);
    #pragma unroll
    for (int nf = 0; nf < 4; nf++)
        b_off[nf] = (uint32_t)((warp_n * 32 + nf * 8 + (lane & 7)) * 144
                               + ((lane >> 3) & 1) * 16);

    float acc[4][4][4] = {};

    load_stage(0, 0);
    int buf = 0;
    for (int kt = 0; kt < NKT; kt++) {
        if (kt + 1 < NKT) {
            load_stage(buf ^ 1, kt + 1);
            CP_WAIT1();
        } else {
            CP_WAIT0();
        }
        __syncthreads();

        uint32_t as = sb + (buf * 2 + 0) * STAGE_B;
        uint32_t bs = sb + (buf * 2 + 1) * STAGE_B;
        #pragma unroll
        for (int ks = 0; ks < 4; ks++) {
            uint32_t a[4][4], b[4][2];
            #pragma unroll
            for (int mf = 0; mf < 4; mf++)
                ldsm4(a[mf], as + a_off[mf] + ks * 32);
            #pragma unroll
            for (int nf = 0; nf < 4; nf++)
                ldsm2(b[nf], bs + b_off[nf] + ks * 32);
            #pragma unroll
            for (int mf = 0; mf < 4; mf++)
                #pragma unroll
                for (int nf = 0; nf < 4; nf++)
                    mma8(acc[mf][nf], a[mf], b[nf]);
        }
        __syncthreads();
        buf ^= 1;
    }

    #pragma unroll
    for (int nf = 0; nf < 4; nf++) {
        int c = col0 + warp_n * 32 + nf * 8 + 2 * (lane & 3);
        float bx_ = __ldg(bias + c), by_ = __ldg(bias + c + 1);
        #pragma unroll
        for (int mf = 0; mf < 4; mf++) {
            int r = row0 + warp_m * 64 + mf * 16 + (lane >> 2);
            float2 v0 = make_float2(acc[mf][nf][0] + bx_, acc[mf][nf][1] + by_);
            float2 v1 = make_float2(acc[mf][nf][2] + bx_, acc[mf][nf][3] + by_);
            if (res) {
                float2 r0 = *(const float2*)(res + (size_t)r * GN + c);
                float2 r1 = *(const float2*)(res + (size_t)(r + 8) * GN + c);
                v0.x += r0.x; v0.y += r0.y;
                v1.x += r1.x; v1.y += r1.y;
            }
            *(float2*)(C + (size_t)r * GN + c) = v0;
            *(float2*)(C + (size_t)(r + 8) * GN + c) = v1;
        }
    }
}

__global__ void __launch_bounds__(256, 2)
qkv_gemm(const float* q, const float* k, const float* v,
         const float* wq, const float* wk, const float* wv,
         const float* bq, const float* bk, const float* bv,
         float* oq, float* ok, float* ov)
{
    extern __shared__ char smem[];
    int z = blockIdx.z;
    const float* A  = (z == 0) ? q  : (z == 1) ? k  : v;
    const float* BT = (z == 0) ? wq : (z == 1) ? wk : wv;
    const float* bi = (z == 0) ? bq : (z == 1) ? bk : bv;
    float* C        = (z == 0) ? oq : (z == 1) ? ok : ov;
    gemm_body(smem, A, BT, bi, nullptr, C, blockIdx.x, blockIdx.y);
}

__global__ void __launch_bounds__(256, 2)
o_gemm(const float* A, const float* BT, const float* bias,
       const float* res, float* C)
{
    extern __shared__ char smem[];
    gemm_body(smem, A, BT, bias, res, C, blockIdx.x, blockIdx.y);
}

// ------------ fused weight transpose (+tf32 RNA round): all 4 weights -------
__global__ void trans4_kernel(const float* __restrict__ s0, float* __restrict__ d0,
                              const float* __restrict__ s1, float* __restrict__ d1,
                              const float* __restrict__ s2, float* __restrict__ d2,
                              const float* __restrict__ s3, float* __restrict__ d3)
{
    __shared__ float t[32][33];
    int zz = blockIdx.z;
    const float* src = (zz == 0) ? s0 : (zz == 1) ? s1 : (zz == 2) ? s2 : s3;
    float* dst       = (zz == 0) ? d0 : (zz == 1) ? d1 : (zz == 2) ? d2 : d3;
    int x = blockIdx.x * 32 + threadIdx.x;
    int y0 = blockIdx.y * 32;
    #pragma unroll
    for (int i = threadIdx.y; i < 32; i += 8)
        t[i][threadIdx.x] = src[(size_t)(y0 + i) * HH + x];
    __syncthreads();
    int xo = blockIdx.y * 32 + threadIdx.x;
    int yo0 = blockIdx.x * 32;
    #pragma unroll
    for (int i = threadIdx.y; i < 32; i += 8)
        dst[(size_t)(yo0 + i) * HH + xo] = f2tf_f(t[threadIdx.x][i]);
}

// ---------------- per-(b,h) V transpose ----------------
__global__ void vtrans_kernel(const float* __restrict__ V, float* __restrict__ VT)
{
    __shared__ float t[32][33];
    int bh = blockIdx.z;
    int s0 = blockIdx.x * 32, d0 = blockIdx.y * 32;
    int b = bh >> 4, h = bh & 15;
    const float* src = V + ((size_t)b * SS + s0) * HH + h * HDD + d0;
    #pragma unroll
    for (int i = threadIdx.y; i < 32; i += 8)
        t[i][threadIdx.x] = src[(size_t)i * HH + threadIdx.x];
    __syncthreads();
    float* dst = VT + ((size_t)bh * HDD + d0) * SS + s0;
    #pragma unroll
    for (int i = threadIdx.y; i < 32; i += 8)
        dst[(size_t)i * SS + threadIdx.x] = t[threadIdx.x][i];
}

// ---------------- query column means: 64 blocks ----------------
__global__ void qmean_part(const float* __restrict__ q)
{
    int b = blockIdx.y, ch = blockIdx.x;     // 32 chunks of 32 rows
    int tid = threadIdx.x;
    for (int c = tid; c < HH; c += 256) {
        const float* base = q + ((size_t)b * SS + ch * 32) * HH + c;
        float s = 0.f;
        #pragma unroll 4
        for (int r = 0; r < 32; r++) s += base[(size_t)r * HH];
        g_part[((size_t)b * 32 + ch) * HH + c] = s;
    }
}

// -------- spec layer-1 partials: grid(32 rowchunks, 4 colgroups, BB) -------
__global__ void spec1_kernel(const float* __restrict__ Ws1)
{
    __shared__ float sin_s[32];
    int b = blockIdx.z, ch = blockIdx.x, cg = blockIdx.y;
    int tid = threadIdx.x;          // 128
    int r0 = ch * 32;
    if (tid < 32) {
        float s = 0.f;
        #pragma unroll
        for (int p = 0; p < 32; p++) s += g_part[((size_t)b * 32 + p) * HH + r0 + tid];
        sin_s[tid] = s * (1.0f / SS);
    }
    __syncthreads();
    int col = cg * 128 + tid;
    float acc = 0.f;
    #pragma unroll
    for (int j = 0; j < 32; j++)
        acc += sin_s[j] * Ws1[(size_t)(r0 + j) * 512 + col];
    g_h1p[(size_t)(b * 32 + ch) * 512 + col] = acc;
}

// -------- spec layer-2: grid(16 colblocks, BB), 256 thr --------------------
__global__ void spec2_kernel(const float* __restrict__ bs1,
                             const float* __restrict__ Ws2,
                             const float* __restrict__ bs2)
{
    __shared__ float h1[512];
    __shared__ float zp[4][64];
    __shared__ float red[64];
    int b = blockIdx.y, cb = blockIdx.x;
    int tid = threadIdx.x;          // 256
    for (int c = tid; c < 512; c += 256) {
        float s = bs1[c];
        #pragma unroll
        for (int ch = 0; ch < 32; ch++) s += g_h1p[(size_t)(b * 32 + ch) * 512 + c];
        h1[c] = fmaxf(s, 0.f);
    }
    __syncthreads();
    int col = cb * 64 + (tid & 63);
    int qq = tid >> 6;              // 0..3
    float z = 0.f;
    #pragma unroll 4
    for (int i = qq * 128; i < qq * 128 + 128; i++)
        z += h1[i] * Ws2[(size_t)i * HH + col];
    zp[qq][tid & 63] = z;
    __syncthreads();
    if (tid < 64) {
        float zz = bs2[cb * 64 + tid] + zp[0][tid] + zp[1][tid] + zp[2][tid] + zp[3][tid];
        red[tid] = 1.0f / (1.0f + __expf(-zz));
    }
    __syncthreads();
    for (int off = 32; off > 0; off >>= 1) {
        if (tid < off) red[tid] += red[tid + off];
        __syncthreads();
    }
    if (tid == 0) g_sp[b * 16 + cb] = red[0];
}

// ================  tensor-core flash attention  =============================
#define ASTR 272                       // bytes per smem row (68 floats)
#define AQ_OFF 0                       // Q: 128 rows
#define AK_OFF (AQ_OFF + 128*ASTR)     // K: 64 rows
#define AV_OFF (AK_OFF + 64*ASTR)      // VT: 64 rows (d-major)
#define AP_OFF (AV_OFF + 64*ASTR)      // P: 128 rows
#define A_SMEM (AP_OFF + 128*ASTR)     // 104448 bytes

__global__ void __launch_bounds__(256, 2)
attn_mma(const float* __restrict__ msb)
{
    extern __shared__ char smem[];
    __shared__ float red[256];
    __shared__ float mh_s;
    uint32_t sb = smem_u32(smem);
    const int tid = threadIdx.x;
    const int lane = tid & 31;
    const int w = tid >> 5;
    const int b = blockIdx.z, h = blockIdx.y, q0 = blockIdx.x << 7;

    const uint32_t Qa = sb + AQ_OFF + (uint32_t)((16 * w + (lane & 15)) * ASTR + (lane >> 4) * 16);
    const uint32_t Pa = sb + AP_OFF + (uint32_t)((16 * w + (lane & 15)) * ASTR + (lane >> 4) * 16);
    const uint32_t Kb = sb + AK_OFF + (uint32_t)(((((lane >> 4) << 3) + (lane & 7)) * ASTR) + ((lane >> 3) & 1) * 16);
    const uint32_t Vb = sb + AV_OFF + (uint32_t)(((((lane >> 4) << 3) + (lane & 7)) * ASTR) + ((lane >> 3) & 1) * 16);

    // load Q tile (128 x 64)
    {
        const float* Qg = g_Q + ((size_t)b * SS + q0) * HH + h * HDD;
        #pragma unroll
        for (int i = 0; i < 8; i++) {
            int f = tid + i * 256;
            int r = f >> 4, c4 = f & 15;
            cp16(sb + AQ_OFF + (uint32_t)(r * ASTR + c4 * 16),
                 Qg + (size_t)r * HH + c4 * 4);
        }
        CP_COMMIT();
    }

    // per-head msb mean (block reduce, overlaps Q load)
    {
        const float* p = msb + (size_t)h * HDD * HDD;
        float s = 0.f;
        for (int i = tid; i < HDD * HDD; i += 256) s += p[i];
        red[tid] = s;
        __syncthreads();
        for (int off = 128; off > 0; off >>= 1) {
            if (tid < off) red[tid] += red[tid + off];
            __syncthreads();
        }
        if (tid == 0) mh_s = red[0] * (1.0f / (HDD * HDD));
        __syncthreads();
    }

    const float mh = mh_s;
    float sp = 0.f;
    #pragma unroll
    for (int j = 0; j < 16; j++) sp += g_sp[b * 16 + j];
    sp *= (1.0f / HH);

    float oacc[8][4] = {};
    float m0 = -1e30f, m1 = -1e30f, l0 = 0.f, l1 = 0.f;

    for (int kt = 0; kt < 16; kt++) {
        __syncthreads();
        {
            const float* Kg = g_K + ((size_t)b * SS + kt * 64) * HH + h * HDD;
            const float* Vg = g_VT + (size_t)(b * NHH + h) * HDD * SS + kt * 64;
            #pragma unroll
            for (int i = 0; i < 4; i++) {
                int f = tid + i * 256;
                int r = f >> 4, c4 = f & 15;
                cp16(sb + AK_OFF + (uint32_t)(r * ASTR + c4 * 16),
                     Kg + (size_t)r * HH + c4 * 4);
                cp16(sb + AV_OFF + (uint32_t)(r * ASTR + c4 * 16),
                     Vg + (size_t)r * SS + c4 * 4);
            }
            CP_COMMIT();
        }
        CP_WAIT0();
        __syncthreads();

        // ---- S = Q @ K^T ----
        float sacc[8][4] = {};
        #pragma unroll
        for (int ks = 0; ks < 8; ks++) {
            uint32_t a[4];
            ldsm4(a, Qa + ks * 32);
            #pragma unroll
            for (int kb = 0; kb < 4; kb++) {
                uint32_t bb[4];
                ldsm4(bb, Kb + kb * 16 * ASTR + ks * 32);
                mma8(sacc[2 * kb],     a, bb);
                mma8(sacc[2 * kb + 1], a, bb + 2);
            }
        }

        // ---- gate + online softmax ----
        float tm0 = -1e30f, tm1 = -1e30f;
        #pragma unroll
        for (int nf = 0; nf < 8; nf++) {
            #pragma unroll
            for (int j = 0; j < 4; j++) {
                float s0 = sacc[nf][j] * SCALE_C;
                float e = 1.0f / (1.0f + __expf(-s0 * mh));
                float p = s0 * (1.0f + e * SP_C) * sp;
                sacc[nf][j] = p;
                if (j < 2) tm0 = fmaxf(tm0, p); else tm1 = fmaxf(tm1, p);
            }
        }
        tm0 = fmaxf(tm0, __shfl_xor_sync(0xffffffff, tm0, 1));
        tm0 = fmaxf(tm0, __shfl_xor_sync(0xffffffff, tm0, 2));
        tm1 = fmaxf(tm1, __shfl_xor_sync(0xffffffff, tm1, 1));
        tm1 = fmaxf(tm1, __shfl_xor_sync(0xffffffff, tm1, 2));

        float nm0 = fmaxf(m0, tm0), nm1 = fmaxf(m1, tm1);
        float sc0 = __expf(m0 - nm0), sc1 = __expf(m1 - nm1);
        float su0 = 0.f, su1 = 0.f;
        #pragma unroll
        for (int nf = 0; nf < 8; nf++) {
            float p0 = __expf(sacc[nf][0] - nm0);
            float p1 = __expf(sacc[nf][1] - nm0);
            float p2 = __expf(sacc[nf][2] - nm1);
            float p3 = __expf(sacc[nf][3] - nm1);
            su0 += p0 + p1; su1 += p2 + p3;
            sacc[nf][0] = p0; sacc[nf][1] = p1;
            sacc[nf][2] = p2; sacc[nf][3] = p3;
        }
        su0 += __shfl_xor_sync(0xffffffff, su0, 1);
        su0 += __shfl_xor_sync(0xffffffff, su0, 2);
        su1 += __shfl_xor_sync(0xffffffff, su1, 1);
        su1 += __shfl_xor_sync(0xffffffff, su1, 2);
        l0 = l0 * sc0 + su0;
        l1 = l1 * sc1 + su1;
        m0 = nm0; m1 = nm1;

        #pragma unroll
        for (int nf = 0; nf < 8; nf++) {
            oacc[nf][0] *= sc0; oacc[nf][1] *= sc0;
            oacc[nf][2] *= sc1; oacc[nf][3] *= sc1;
        }

        // ---- write P to smem (HW truncates to tf32 at the mma) ----
        {
            int r0 = 16 * w + (lane >> 2);
            uint32_t p0a = (uint32_t)(AP_OFF + r0 * ASTR + 2 * (lane & 3) * 4);
            #pragma unroll
            for (int nf = 0; nf < 8; nf++) {
                *(float2*)(smem + p0a + nf * 32) =
                    make_float2(sacc[nf][0], sacc[nf][1]);
                *(float2*)(smem + p0a + 8 * ASTR + nf * 32) =
                    make_float2(sacc[nf][2], sacc[nf][3]);
            }
        }
        __syncwarp();

        // ---- O += P @ V ----
        #pragma unroll
        for (int ks = 0; ks < 8; ks++) {
            uint32_t a[4];
            ldsm4(a, Pa + ks * 32);
            #pragma unroll
            for (int db = 0; db < 4; db++) {
                uint32_t bb[4];
                ldsm4(bb, Vb + db * 16 * ASTR + ks * 32);
                mma8(oacc[2 * db],     a, bb);
                mma8(oacc[2 * db + 1], a, bb + 2);
            }
        }
    }

    // ---- epilogue: normalize + store ctx ----
    float inv0 = 1.0f / l0, inv1 = 1.0f / l1;
    float* Og = g_ctx + ((size_t)b * SS + q0) * HH + h * HDD;
    int r0 = 16 * w + (lane >> 2);
    #pragma unroll
    for (int nf = 0; nf < 8; nf++) {
        int c = 8 * nf + 2 * (lane & 3);
        *(float2*)&Og[(size_t)r0 * HH + c] =
            make_float2(oacc[nf][0] * inv0, oacc[nf][1] * inv0);
        *(float2*)&Og[(size_t)(r0 + 8) * HH + c] =
            make_float2(oacc[nf][2] * inv1, oacc[nf][3] * inv1);
    }
}

// ---------------- row LayerNorm ----------------
__global__ void ln_kernel(const float* __restrict__ x,
                          const float* __restrict__ g,
                          const float* __restrict__ bta,
                          float* __restrict__ out)
{
    __shared__ float r1[256];
    __shared__ float r2[256];
    int row = blockIdx.x, tid = threadIdx.x;
    const float4* xr = (const float4*)(x + (size_t)row * HH);
    float4 a = xr[tid];
    float s = a.x + a.y + a.z + a.w;
    float ss = a.x * a.x + a.y * a.y + a.z * a.z + a.w * a.w;
    r1[tid] = s; r2[tid] = ss;
    __syncthreads();
    for (int off = 128; off > 0; off >>= 1) {
        if (tid < off) { r1[tid] += r1[tid + off]; r2[tid] += r2[tid + off]; }
        __syncthreads();
    }
    float mu = r1[0] * (1.0f / HH);
    float var = r2[0] * (1.0f / HH) - mu * mu;
    float rstd = rsqrtf(var + EPS_C);
    float4 gg = ((const float4*)g)[tid];
    float4 bb = ((const float4*)bta)[tid];
    float4 o;
    o.x = (a.x - mu) * rstd * gg.x + bb.x;
    o.y = (a.y - mu) * rstd * gg.y + bb.y;
    o.z = (a.z - mu) * rstd * gg.z + bb.z;
    o.w = (a.w - mu) * rstd * gg.w + bb.w;
    ((float4*)(out + (size_t)row * HH))[tid] = o;
}

// ---------------- launch ----------------
extern "C" void kernel_launch(void* const* d_in, const int* in_sizes, int n_in,
                              void* d_out, int out_size)
{
    const float* query = (const float*)d_in[0];
    const float* key_t = (const float*)d_in[1];
    const float* value = (const float*)d_in[2];
    const float* Wq = (const float*)d_in[3];
    const float* bq = (const float*)d_in[4];
    const float* Wk = (const float*)d_in[5];
    const float* bk = (const float*)d_in[6];
    const float* Wv = (const float*)d_in[7];
    const float* bv = (const float*)d_in[8];
    const float* msb = (const float*)d_in[9];
    const float* Ws1 = (const float*)d_in[10];
    const float* bs1 = (const float*)d_in[11];
    const float* Ws2 = (const float*)d_in[12];
    const float* bs2 = (const float*)d_in[13];
    const float* Wo = (const float*)d_in[14];
    const float* bo = (const float*)d_in[15];
    const float* ln_g = (const float*)d_in[16];
    const float* ln_b = (const float*)d_in[17];

    float *pQ, *pK, *pV, *pVT, *pCtx, *pPre, *pWT;
    cudaGetSymbolAddress((void**)&pQ, g_Q);
    cudaGetSymbolAddress((void**)&pK, g_K);
    cudaGetSymbolAddress((void**)&pV, g_V);
    cudaGetSymbolAddress((void**)&pVT, g_VT);
    cudaGetSymbolAddress((void**)&pCtx, g_ctx);
    cudaGetSymbolAddress((void**)&pPre, g_pre);
    cudaGetSymbolAddress((void**)&pWT, g_WT);

    float* WTq = pWT + 0 * HH * HH;
    float* WTk = pWT + 1 * HH * HH;
    float* WTv = pWT + 2 * HH * HH;
    float* WTo = pWT + 3 * HH * HH;

    cudaFuncSetAttribute(qkv_gemm, cudaFuncAttributeMaxDynamicSharedMemorySize,
                         GSM_TOTAL);
    cudaFuncSetAttribute(o_gemm, cudaFuncAttributeMaxDynamicSharedMemorySize,
                         GSM_TOTAL);
    cudaFuncSetAttribute(attn_mma, cudaFuncAttributeMaxDynamicSharedMemorySize,
                         A_SMEM);

    dim3 tb(32, 8);
    dim3 tg4(32, 32, 4);

    // 0: all 4 weight transposes (+tf32 RNA rounding)
    trans4_kernel<<<tg4, tb>>>(Wq, WTq, Wk, WTk, Wv, WTv, Wo, WTo);
    // 1: query column sums
    qmean_part<<<dim3(32, BB), 256>>>(query);
    // 2: spec layer-1 partials
    spec1_kernel<<<dim3(32, 4, BB), 128>>>(Ws1);
    // 3 (profiled slot): fused Q/K/V projection GEMM
    qkv_gemm<<<dim3(GN / 128, M_TOT / 128, 3), 256, GSM_TOTAL>>>(
        query, key_t, value, WTq, WTk, WTv, bq, bk, bv, pQ, pK, pV);
    // 4: spec layer-2
    spec2_kernel<<<dim3(16, BB), 256>>>(bs1, Ws2, bs2);
    // 5: V transpose for attention B-operand
    vtrans_kernel<<<dim3(SS / 32, HDD / 32, BB * NHH), tb>>>(pV, pVT);
    // 6: tensor-core flash attention
    attn_mma<<<dim3(SS / 128, NHH, BB), 256, A_SMEM>>>(msb);
    // 7: output projection + bias + residual
    o_gemm<<<dim3(GN / 128, M_TOT / 128), 256, GSM_TOTAL>>>(pCtx, WTo, bo, query, pPre);
    // 8: LayerNorm -> d_out
    ln_kernel<<<M_TOT, 256>>>(pPre, ln_g, ln_b, (float*)d_out);
}

// round 9
// speedup vs baseline: 1.3224x; 1.0013x over previous
#include <cuda_runtime.h>
#include <cuda_bf16.h>
#include <math.h>
#include <cstdint>

// Problem constants
#define BB 2
#define SS 1024
#define HH 1024
#define NHH 16
#define HDD 64
#define SP_C 0.05f
#define EPS_C 1e-5f
#define SCALE_C 0.125f   // 1/sqrt(64)

#define M_TOT (BB*SS)    // 2048

// ---------------- scratch (device globals: no allocations allowed) ----------
__device__ float g_Q[M_TOT*HH];
__device__ float g_K[M_TOT*HH];
__device__ float g_VT[BB*NHH*HDD*SS];   // V transposed per (b,h): [d][s]
__device__ float g_ctx[M_TOT*HH];
__device__ float g_pre[M_TOT*HH];
__device__ float g_WT[4*HH*HH];      // transposed tf32-rounded weights
__device__ float g_part[BB*32*HH];   // partial column sums of query over seq
__device__ float g_h1p[BB*32*512];   // spec layer-1 partials
__device__ float g_sp[BB*16];        // spec sigmoid-sum partials

// =====================  PTX helpers (mma.sync / cp.async)  ==================
__device__ __forceinline__ uint32_t smem_u32(const void* p) {
    uint32_t a;
    asm("{ .reg .u64 t; cvta.to.shared.u64 t, %1; cvt.u32.u64 %0, t; }"
        : "=r"(a) : "l"(p));
    return a;
}

__device__ __forceinline__ void cp16(uint32_t s, const float* g) {
    asm volatile("cp.async.cg.shared.global [%0], [%1], 16;"
                 :: "r"(s), "l"(__cvta_generic_to_global(g)));
}
#define CP_COMMIT() asm volatile("cp.async.commit_group;" ::: "memory")
#define CP_WAIT0()  asm volatile("cp.async.wait_group 0;" ::: "memory")
#define CP_WAIT1()  asm volatile("cp.async.wait_group 1;" ::: "memory")

__device__ __forceinline__ void ldsm4(uint32_t* r, uint32_t addr) {
    asm volatile("ldmatrix.sync.aligned.m8n8.x4.shared.b16 {%0,%1,%2,%3}, [%4];"
                 : "=r"(r[0]), "=r"(r[1]), "=r"(r[2]), "=r"(r[3]) : "r"(addr));
}
__device__ __forceinline__ void ldsm2(uint32_t* r, uint32_t addr) {
    asm volatile("ldmatrix.sync.aligned.m8n8.x2.shared.b16 {%0,%1}, [%2];"
                 : "=r"(r[0]), "=r"(r[1]) : "r"(addr));
}
__device__ __forceinline__ float f2tf_f(float x) {
    uint32_t y;
    asm("cvt.rna.tf32.f32 %0, %1;" : "=r"(y) : "f"(x));
    return __uint_as_float(y);
}
// mma.sync tf32 reads only the top 19 bits of operand registers (HW
// truncation); only weights are pre-rounded (RNA, free in transpose).
__device__ __forceinline__ void mma8(float* d, const uint32_t* a, const uint32_t* b) {
    asm volatile("mma.sync.aligned.m16n8k8.row.col.f32.tf32.tf32.f32 "
                 "{%0,%1,%2,%3}, {%4,%5,%6,%7}, {%8,%9}, {%0,%1,%2,%3};"
                 : "+f"(d[0]), "+f"(d[1]), "+f"(d[2]), "+f"(d[3])
                 : "r"(a[0]), "r"(a[1]), "r"(a[2]), "r"(a[3]),
                   "r"(b[0]), "r"(b[1]));
}

// ======================  mma.sync tf32 GEMM body (3-stage)  =================
#define GK 1024
#define GN 1024
#define BKC 32
#define NKT (GK/BKC)
#define STAGE_B (128*36*4)    // 18432 B per matrix per stage
#define GSM_TOTAL (6*STAGE_B) // 3 stages x (A+B) = 110592 B

// If toVT != nullptr, epilogue writes the per-(b,h)-transposed V layout
// VT[(b*16+h)*64+d][s] instead of row-major C.
__device__ __forceinline__ void gemm_body(
    char* smem, const float* __restrict__ A, const float* __restrict__ BT,
    const float* __restrict__ bias, const float* __restrict__ res,
    float* __restrict__ C, float* __restrict__ toVT, int bx, int by)
{
    uint32_t sb = smem_u32(smem);
    const int tid = threadIdx.x;
    const int lane = tid & 31;
    const int wid = tid >> 5;
    const int warp_m = wid >> 2;
    const int warp_n = wid & 3;
    const int row0 = by * 128;
    const int col0 = bx * 128;

    const float* Abase = A  + (size_t)row0 * GK;
    const float* Bbase = BT + (size_t)col0 * GK;

    auto load_stage = [&](int stage, int kt) {
        uint32_t as = sb + (stage * 2 + 0) * STAGE_B;
        uint32_t bs = sb + (stage * 2 + 1) * STAGE_B;
        const float* Ak = Abase + kt * BKC;
        const float* Bk = Bbase + kt * BKC;
        #pragma unroll
        for (int i = 0; i < 4; i++) {
            int c = tid + i * 256;
            int r = c >> 3, sg = c & 7;
            cp16(as + (uint32_t)(r * 144 + sg * 16), Ak + (size_t)r * GK + sg * 4);
            cp16(bs + (uint32_t)(r * 144 + sg * 16), Bk + (size_t)r * GK + sg * 4);
        }
        CP_COMMIT();
    };

    uint32_t a_off[4], b_off[4];
    #pragma unroll
    for (int mf = 0; mf < 4; mf++)
        a_off[mf] = (uint32_t)((warp_m * 64 + mf * 16 + (lane & 15)) * 144
                               + (lane >> 4) * 16);
    #pragma unroll
    for (int nf = 0; nf < 4; nf++)
        b_off[nf] = (uint32_t)((warp_n * 32 + nf * 8 + (lane & 7)) * 144
                               + ((lane >> 3) & 1) * 16);

    float acc[4][4][4] = {};

    load_stage(0, 0);
    load_stage(1, 1);
    int st = 0;                 // stage holding tile kt
    for (int kt = 0; kt < NKT; kt++) {
        if (kt + 1 < NKT) { CP_WAIT1(); } else { CP_WAIT0(); }
        __syncthreads();        // single barrier per iteration:
                                // - tile kt data visible to all warps
                                // - all warps done computing tile kt-1, so
                                //   its stage is free for tile kt+2's loads
        if (kt + 2 < NKT) {
            int ns = st + 2; if (ns >= 3) ns -= 3;
            load_stage(ns, kt + 2);
        }

        uint32_t as = sb + (st * 2 + 0) * STAGE_B;
        uint32_t bs = sb + (st * 2 + 1) * STAGE_B;
        #pragma unroll
        for (int ks = 0; ks < 4; ks++) {
            uint32_t a[4][4], b[4][2];
            #pragma unroll
            for (int mf = 0; mf < 4; mf++)
                ldsm4(a[mf], as + a_off[mf] + ks * 32);
            #pragma unroll
            for (int nf = 0; nf < 4; nf++)
                ldsm2(b[nf], bs + b_off[nf] + ks * 32);
            #pragma unroll
            for (int mf = 0; mf < 4; mf++)
                #pragma unroll
                for (int nf = 0; nf < 4; nf++)
                    mma8(acc[mf][nf], a[mf], b[nf]);
        }
        if (++st >= 3) st -= 3;
    }

    #pragma unroll
    for (int nf = 0; nf < 4; nf++) {
        int c = col0 + warp_n * 32 + nf * 8 + 2 * (lane & 3);
        float bx_ = __ldg(bias + c), by_ = __ldg(bias + c + 1);
        #pragma unroll
        for (int mf = 0; mf < 4; mf++) {
            int r = row0 + warp_m * 64 + mf * 16 + (lane >> 2);
            float2 v0 = make_float2(acc[mf][nf][0] + bx_, acc[mf][nf][1] + by_);
            float2 v1 = make_float2(acc[mf][nf][2] + bx_, acc[mf][nf][3] + by_);
            if (res) {
                float2 r0 = *(const float2*)(res + (size_t)r * GN + c);
                float2 r1 = *(const float2*)(res + (size_t)(r + 8) * GN + c);
                v0.x += r0.x; v0.y += r0.y;
                v1.x += r1.x; v1.y += r1.y;
            }
            if (toVT) {
                // transposed V layout: VT[(b*16+h)*64+d][s]
                int b_ = r >> 10, s = r & 1023;
                int h_ = c >> 6, d = c & 63;
                size_t i0 = ((size_t)((b_ * 16 + h_) * 64 + d)) << 10;
                toVT[i0 + s]            = v0.x;
                toVT[i0 + 1024 + s]     = v0.y;
                toVT[i0 + s + 8]        = v1.x;
                toVT[i0 + 1024 + s + 8] = v1.y;
            } else {
                *(float2*)(C + (size_t)r * GN + c) = v0;
                *(float2*)(C + (size_t)(r + 8) * GN + c) = v1;
            }
        }
    }
}

__global__ void __launch_bounds__(256, 2)
qkv_gemm(const float* q, const float* k, const float* v,
         const float* wq, const float* wk, const float* wv,
         const float* bq, const float* bk, const float* bv,
         float* oq, float* ok, float* ovt)
{
    extern __shared__ char smem[];
    int z = blockIdx.z;
    const float* A  = (z == 0) ? q  : (z == 1) ? k  : v;
    const float* BT = (z == 0) ? wq : (z == 1) ? wk : wv;
    const float* bi = (z == 0) ? bq : (z == 1) ? bk : bv;
    float* C        = (z == 0) ? oq : (z == 1) ? ok : nullptr;
    float* VT       = (z == 2) ? ovt : nullptr;
    gemm_body(smem, A, BT, bi, nullptr, C, VT, blockIdx.x, blockIdx.y);
}

__global__ void __launch_bounds__(256, 2)
o_gemm(const float* A, const float* BT, const float* bias,
       const float* res, float* C)
{
    extern __shared__ char smem[];
    gemm_body(smem, A, BT, bias, res, C, nullptr, blockIdx.x, blockIdx.y);
}

// ------------ fused weight transpose (+tf32 RNA round): all 4 weights -------
__global__ void trans4_kernel(const float* __restrict__ s0, float* __restrict__ d0,
                              const float* __restrict__ s1, float* __restrict__ d1,
                              const float* __restrict__ s2, float* __restrict__ d2,
                              const float* __restrict__ s3, float* __restrict__ d3)
{
    __shared__ float t[32][33];
    int zz = blockIdx.z;
    const float* src = (zz == 0) ? s0 : (zz == 1) ? s1 : (zz == 2) ? s2 : s3;
    float* dst       = (zz == 0) ? d0 : (zz == 1) ? d1 : (zz == 2) ? d2 : d3;
    int x = blockIdx.x * 32 + threadIdx.x;
    int y0 = blockIdx.y * 32;
    #pragma unroll
    for (int i = threadIdx.y; i < 32; i += 8)
        t[i][threadIdx.x] = src[(size_t)(y0 + i) * HH + x];
    __syncthreads();
    int xo = blockIdx.y * 32 + threadIdx.x;
    int yo0 = blockIdx.x * 32;
    #pragma unroll
    for (int i = threadIdx.y; i < 32; i += 8)
        dst[(size_t)(yo0 + i) * HH + xo] = f2tf_f(t[threadIdx.x][i]);
}

// ---------------- query column means: 64 blocks ----------------
__global__ void qmean_part(const float* __restrict__ q)
{
    int b = blockIdx.y, ch = blockIdx.x;     // 32 chunks of 32 rows
    int tid = threadIdx.x;
    for (int c = tid; c < HH; c += 256) {
        const float* base = q + ((size_t)b * SS + ch * 32) * HH + c;
        float s = 0.f;
        #pragma unroll 4
        for (int r = 0; r < 32; r++) s += base[(size_t)r * HH];
        g_part[((size_t)b * 32 + ch) * HH + c] = s;
    }
}

// -------- spec layer-1 partials: grid(32 rowchunks, 4 colgroups, BB) -------
__global__ void spec1_kernel(const float* __restrict__ Ws1)
{
    __shared__ float sin_s[32];
    int b = blockIdx.z, ch = blockIdx.x, cg = blockIdx.y;
    int tid = threadIdx.x;          // 128
    int r0 = ch * 32;
    if (tid < 32) {
        float s = 0.f;
        #pragma unroll
        for (int p = 0; p < 32; p++) s += g_part[((size_t)b * 32 + p) * HH + r0 + tid];
        sin_s[tid] = s * (1.0f / SS);
    }
    __syncthreads();
    int col = cg * 128 + tid;
    float acc = 0.f;
    #pragma unroll
    for (int j = 0; j < 32; j++)
        acc += sin_s[j] * Ws1[(size_t)(r0 + j) * 512 + col];
    g_h1p[(size_t)(b * 32 + ch) * 512 + col] = acc;
}

// -------- spec layer-2: grid(16 colblocks, BB), 256 thr --------------------
__global__ void spec2_kernel(const float* __restrict__ bs1,
                             const float* __restrict__ Ws2,
                             const float* __restrict__ bs2)
{
    __shared__ float h1[512];
    __shared__ float zp[4][64];
    __shared__ float red[64];
    int b = blockIdx.y, cb = blockIdx.x;
    int tid = threadIdx.x;          // 256
    for (int c = tid; c < 512; c += 256) {
        float s = bs1[c];
        #pragma unroll
        for (int ch = 0; ch < 32; ch++) s += g_h1p[(size_t)(b * 32 + ch) * 512 + c];
        h1[c] = fmaxf(s, 0.f);
    }
    __syncthreads();
    int col = cb * 64 + (tid & 63);
    int qq = tid >> 6;              // 0..3
    float z = 0.f;
    #pragma unroll 4
    for (int i = qq * 128; i < qq * 128 + 128; i++)
        z += h1[i] * Ws2[(size_t)i * HH + col];
    zp[qq][tid & 63] = z;
    __syncthreads();
    if (tid < 64) {
        float zz = bs2[cb * 64 + tid] + zp[0][tid] + zp[1][tid] + zp[2][tid] + zp[3][tid];
        red[tid] = 1.0f / (1.0f + __expf(-zz));
    }
    __syncthreads();
    for (int off = 32; off > 0; off >>= 1) {
        if (tid < off) red[tid] += red[tid + off];
        __syncthreads();
    }
    if (tid == 0) g_sp[b * 16 + cb] = red[0];
}

// ================  tensor-core flash attention  =============================
#define ASTR 272                       // bytes per smem row (68 floats)
#define AQ_OFF 0                       // Q: 128 rows
#define AK_OFF (AQ_OFF + 128*ASTR)     // K: 64 rows
#define AV_OFF (AK_OFF + 64*ASTR)      // VT: 64 rows (d-major)
#define AP_OFF (AV_OFF + 64*ASTR)      // P: 128 rows
#define A_SMEM (AP_OFF + 128*ASTR)     // 104448 bytes

__global__ void __launch_bounds__(256, 2)
attn_mma(const float* __restrict__ msb)
{
    extern __shared__ char smem[];
    __shared__ float red[256];
    __shared__ float mh_s;
    uint32_t sb = smem_u32(smem);
    const int tid = threadIdx.x;
    const int lane = tid & 31;
    const int w = tid >> 5;
    const int b = blockIdx.z, h = blockIdx.y, q0 = blockIdx.x << 7;

    const uint32_t Qa = sb + AQ_OFF + (uint32_t)((16 * w + (lane & 15)) * ASTR + (lane >> 4) * 16);
    const uint32_t Pa = sb + AP_OFF + (uint32_t)((16 * w + (lane & 15)) * ASTR + (lane >> 4) * 16);
    const uint32_t Kb = sb + AK_OFF + (uint32_t)(((((lane >> 4) << 3) + (lane & 7)) * ASTR) + ((lane >> 3) & 1) * 16);
    const uint32_t Vb = sb + AV_OFF + (uint32_t)(((((lane >> 4) << 3) + (lane & 7)) * ASTR) + ((lane >> 3) & 1) * 16);

    // load Q tile (128 x 64)
    {
        const float* Qg = g_Q + ((size_t)b * SS + q0) * HH + h * HDD;
        #pragma unroll
        for (int i = 0; i < 8; i++) {
            int f = tid + i * 256;
            int r = f >> 4, c4 = f & 15;
            cp16(sb + AQ_OFF + (uint32_t)(r * ASTR + c4 * 16),
                 Qg + (size_t)r * HH + c4 * 4);
        }
        CP_COMMIT();
    }

    // per-head msb mean (block reduce, overlaps Q load)
    {
        const float* p = msb + (size_t)h * HDD * HDD;
        float s = 0.f;
        for (int i = tid; i < HDD * HDD; i += 256) s += p[i];
        red[tid] = s;
        __syncthreads();
        for (int off = 128; off > 0; off >>= 1) {
            if (tid < off) red[tid] += red[tid + off];
            __syncthreads();
        }
        if (tid == 0) mh_s = red[0] * (1.0f / (HDD * HDD));
        __syncthreads();
    }

    const float mh = mh_s;
    float sp = 0.f;
    #pragma unroll
    for (int j = 0; j < 16; j++) sp += g_sp[b * 16 + j];
    sp *= (1.0f / HH);

    float oacc[8][4] = {};
    float m0 = -1e30f, m1 = -1e30f, l0 = 0.f, l1 = 0.f;

    for (int kt = 0; kt < 16; kt++) {
        __syncthreads();
        {
            const float* Kg = g_K + ((size_t)b * SS + kt * 64) * HH + h * HDD;
            const float* Vg = g_VT + (size_t)(b * NHH + h) * HDD * SS + kt * 64;
            #pragma unroll
            for (int i = 0; i < 4; i++) {
                int f = tid + i * 256;
                int r = f >> 4, c4 = f & 15;
                cp16(sb + AK_OFF + (uint32_t)(r * ASTR + c4 * 16),
                     Kg + (size_t)r * HH + c4 * 4);
                cp16(sb + AV_OFF + (uint32_t)(r * ASTR + c4 * 16),
                     Vg + (size_t)r * SS + c4 * 4);
            }
            CP_COMMIT();
        }
        CP_WAIT0();
        __syncthreads();

        // ---- S = Q @ K^T ----
        float sacc[8][4] = {};
        #pragma unroll
        for (int ks = 0; ks < 8; ks++) {
            uint32_t a[4];
            ldsm4(a, Qa + ks * 32);
            #pragma unroll
            for (int kb = 0; kb < 4; kb++) {
                uint32_t bb[4];
                ldsm4(bb, Kb + kb * 16 * ASTR + ks * 32);
                mma8(sacc[2 * kb],     a, bb);
                mma8(sacc[2 * kb + 1], a, bb + 2);
            }
        }

        // ---- gate + online softmax ----
        float tm0 = -1e30f, tm1 = -1e30f;
        #pragma unroll
        for (int nf = 0; nf < 8; nf++) {
            #pragma unroll
            for (int j = 0; j < 4; j++) {
                float s0 = sacc[nf][j] * SCALE_C;
                float e = 1.0f / (1.0f + __expf(-s0 * mh));
                float p = s0 * (1.0f + e * SP_C) * sp;
                sacc[nf][j] = p;
                if (j < 2) tm0 = fmaxf(tm0, p); else tm1 = fmaxf(tm1, p);
            }
        }
        tm0 = fmaxf(tm0, __shfl_xor_sync(0xffffffff, tm0, 1));
        tm0 = fmaxf(tm0, __shfl_xor_sync(0xffffffff, tm0, 2));
        tm1 = fmaxf(tm1, __shfl_xor_sync(0xffffffff, tm1, 1));
        tm1 = fmaxf(tm1, __shfl_xor_sync(0xffffffff, tm1, 2));

        float nm0 = fmaxf(m0, tm0), nm1 = fmaxf(m1, tm1);
        float sc0 = __expf(m0 - nm0), sc1 = __expf(m1 - nm1);
        float su0 = 0.f, su1 = 0.f;
        #pragma unroll
        for (int nf = 0; nf < 8; nf++) {
            float p0 = __expf(sacc[nf][0] - nm0);
            float p1 = __expf(sacc[nf][1] - nm0);
            float p2 = __expf(sacc[nf][2] - nm1);
            float p3 = __expf(sacc[nf][3] - nm1);
            su0 += p0 + p1; su1 += p2 + p3;
            sacc[nf][0] = p0; sacc[nf][1] = p1;
            sacc[nf][2] = p2; sacc[nf][3] = p3;
        }
        su0 += __shfl_xor_sync(0xffffffff, su0, 1);
        su0 += __shfl_xor_sync(0xffffffff, su0, 2);
        su1 += __shfl_xor_sync(0xffffffff, su1, 1);
        su1 += __shfl_xor_sync(0xffffffff, su1, 2);
        l0 = l0 * sc0 + su0;
        l1 = l1 * sc1 + su1;
        m0 = nm0; m1 = nm1;

        #pragma unroll
        for (int nf = 0; nf < 8; nf++) {
            oacc[nf][0] *= sc0; oacc[nf][1] *= sc0;
            oacc[nf][2] *= sc1; oacc[nf][3] *= sc1;
        }

        // ---- write P to smem (HW truncates to tf32 at the mma) ----
        {
            int r0 = 16 * w + (lane >> 2);
            uint32_t p0a = (uint32_t)(AP_OFF + r0 * ASTR + 2 * (lane & 3) * 4);
            #pragma unroll
            for (int nf = 0; nf < 8; nf++) {
                *(float2*)(smem + p0a + nf * 32) =
                    make_float2(sacc[nf][0], sacc[nf][1]);
                *(float2*)(smem + p0a + 8 * ASTR + nf * 32) =
                    make_float2(sacc[nf][2], sacc[nf][3]);
            }
        }
        __syncwarp();

        // ---- O += P @ V ----
        #pragma unroll
        for (int ks = 0; ks < 8; ks++) {
            uint32_t a[4];
            ldsm4(a, Pa + ks * 32);
            #pragma unroll
            for (int db = 0; db < 4; db++) {
                uint32_t bb[4];
                ldsm4(bb, Vb + db * 16 * ASTR + ks * 32);
                mma8(oacc[2 * db],     a, bb);
                mma8(oacc[2 * db + 1], a, bb + 2);
            }
        }
    }

    // ---- epilogue: normalize + store ctx ----
    float inv0 = 1.0f / l0, inv1 = 1.0f / l1;
    float* Og = g_ctx + ((size_t)b * SS + q0) * HH + h * HDD;
    int r0 = 16 * w + (lane >> 2);
    #pragma unroll
    for (int nf = 0; nf < 8; nf++) {
        int c = 8 * nf + 2 * (lane & 3);
        *(float2*)&Og[(size_t)r0 * HH + c] =
            make_float2(oacc[nf][0] * inv0, oacc[nf][1] * inv0);
        *(float2*)&Og[(size_t)(r0 + 8) * HH + c] =
            make_float2(oacc[nf][2] * inv1, oacc[nf][3] * inv1);
    }
}

// ---------------- row LayerNorm ----------------
__global__ void ln_kernel(const float* __restrict__ x,
                          const float* __restrict__ g,
                          const float* __restrict__ bta,
                          float* __restrict__ out)
{
    __shared__ float r1[256];
    __shared__ float r2[256];
    int row = blockIdx.x, tid = threadIdx.x;
    const float4* xr = (const float4*)(x + (size_t)row * HH);
    float4 a = xr[tid];
    float s = a.x + a.y + a.z + a.w;
    float ss = a.x * a.x + a.y * a.y + a.z * a.z + a.w * a.w;
    r1[tid] = s; r2[tid] = ss;
    __syncthreads();
    for (int off = 128; off > 0; off >>= 1) {
        if (tid < off) { r1[tid] += r1[tid + off]; r2[tid] += r2[tid + off]; }
        __syncthreads();
    }
    float mu = r1[0] * (1.0f / HH);
    float var = r2[0] * (1.0f / HH) - mu * mu;
    float rstd = rsqrtf(var + EPS_C);
    float4 gg = ((const float4*)g)[tid];
    float4 bb = ((const float4*)bta)[tid];
    float4 o;
    o.x = (a.x - mu) * rstd * gg.x + bb.x;
    o.y = (a.y - mu) * rstd * gg.y + bb.y;
    o.z = (a.z - mu) * rstd * gg.z + bb.z;
    o.w = (a.w - mu) * rstd * gg.w + bb.w;
    ((float4*)(out + (size_t)row * HH))[tid] = o;
}

// ---------------- launch ----------------
extern "C" void kernel_launch(void* const* d_in, const int* in_sizes, int n_in,
                              void* d_out, int out_size)
{
    const float* query = (const float*)d_in[0];
    const float* key_t = (const float*)d_in[1];
    const float* value = (const float*)d_in[2];
    const float* Wq = (const float*)d_in[3];
    const float* bq = (const float*)d_in[4];
    const float* Wk = (const float*)d_in[5];
    const float* bk = (const float*)d_in[6];
    const float* Wv = (const float*)d_in[7];
    const float* bv = (const float*)d_in[8];
    const float* msb = (const float*)d_in[9];
    const float* Ws1 = (const float*)d_in[10];
    const float* bs1 = (const float*)d_in[11];
    const float* Ws2 = (const float*)d_in[12];
    const float* bs2 = (const float*)d_in[13];
    const float* Wo = (const float*)d_in[14];
    const float* bo = (const float*)d_in[15];
    const float* ln_g = (const float*)d_in[16];
    const float* ln_b = (const float*)d_in[17];

    float *pQ, *pK, *pVT, *pCtx, *pPre, *pWT;
    cudaGetSymbolAddress((void**)&pQ, g_Q);
    cudaGetSymbolAddress((void**)&pK, g_K);
    cudaGetSymbolAddress((void**)&pVT, g_VT);
    cudaGetSymbolAddress((void**)&pCtx, g_ctx);
    cudaGetSymbolAddress((void**)&pPre, g_pre);
    cudaGetSymbolAddress((void**)&pWT, g_WT);

    float* WTq = pWT + 0 * HH * HH;
    float* WTk = pWT + 1 * HH * HH;
    float* WTv = pWT + 2 * HH * HH;
    float* WTo = pWT + 3 * HH * HH;

    cudaFuncSetAttribute(qkv_gemm, cudaFuncAttributeMaxDynamicSharedMemorySize,
                         GSM_TOTAL);
    cudaFuncSetAttribute(o_gemm, cudaFuncAttributeMaxDynamicSharedMemorySize,
                         GSM_TOTAL);
    cudaFuncSetAttribute(attn_mma, cudaFuncAttributeMaxDynamicSharedMemorySize,
                         A_SMEM);

    dim3 tb(32, 8);
    dim3 tg4(32, 32, 4);

    // 0: all 4 weight transposes (+tf32 RNA rounding)
    trans4_kernel<<<tg4, tb>>>(Wq, WTq, Wk, WTk, Wv, WTv, Wo, WTo);
    // 1: query column sums
    qmean_part<<<dim3(32, BB), 256>>>(query);
    // 2: spec layer-1 partials
    spec1_kernel<<<dim3(32, 4, BB), 128>>>(Ws1);
    // 3 (profiled slot): fused Q/K/V projection GEMM (V written transposed)
    qkv_gemm<<<dim3(GN / 128, M_TOT / 128, 3), 256, GSM_TOTAL>>>(
        query, key_t, value, WTq, WTk, WTv, bq, bk, bv, pQ, pK, pVT);
    // 4: spec layer-2
    spec2_kernel<<<dim3(16, BB), 256>>>(bs1, Ws2, bs2);
    // 5: tensor-core flash attention
    attn_mma<<<dim3(SS / 128, NHH, BB), 256, A_SMEM>>>(msb);
    // 6: output projection + bias + residual
    o_gemm<<<dim3(GN / 128, M_TOT / 128), 256, GSM_TOTAL>>>(pCtx, WTo, bo, query, pPre);
    // 7: LayerNorm -> d_out
    ln_kernel<<<M_TOT, 256>>>(pPre, ln_g, ln_b, (float*)d_out);
}

// round 10
// speedup vs baseline: 1.3254x; 1.0023x over previous
#include <cuda_runtime.h>
#include <cuda_bf16.h>
#include <math.h>
#include <cstdint>

// Problem constants
#define BB 2
#define SS 1024
#define HH 1024
#define NHH 16
#define HDD 64
#define SP_C 0.05f
#define EPS_C 1e-5f
#define SCALE_C 0.125f   // 1/sqrt(64)

#define M_TOT (BB*SS)    // 2048

// ---------------- scratch (device globals: no allocations allowed) ----------
__device__ float g_Q[M_TOT*HH];
__device__ float g_K[M_TOT*HH];
__device__ float g_VT[BB*NHH*HDD*SS];   // V transposed per (b,h): [d][s]
__device__ float g_ctx[M_TOT*HH];
__device__ float g_pre[M_TOT*HH];
__device__ float g_WT[4*HH*HH];      // transposed tf32-rounded weights
__device__ float g_part[BB*32*HH];   // partial column sums of query over seq
__device__ float g_h1p[BB*32*512];   // spec layer-1 partials
__device__ float g_sp[BB*16];        // spec sigmoid-sum partials

// =====================  PTX helpers (mma.sync / cp.async)  ==================
__device__ __forceinline__ uint32_t smem_u32(const void* p) {
    uint32_t a;
    asm("{ .reg .u64 t; cvta.to.shared.u64 t, %1; cvt.u32.u64 %0, t; }"
        : "=r"(a) : "l"(p));
    return a;
}

__device__ __forceinline__ void cp16(uint32_t s, const float* g) {
    asm volatile("cp.async.cg.shared.global [%0], [%1], 16;"
                 :: "r"(s), "l"(__cvta_generic_to_global(g)));
}
#define CP_COMMIT() asm volatile("cp.async.commit_group;" ::: "memory")
#define CP_WAIT0()  asm volatile("cp.async.wait_group 0;" ::: "memory")
#define CP_WAIT1()  asm volatile("cp.async.wait_group 1;" ::: "memory")

__device__ __forceinline__ void ldsm4(uint32_t* r, uint32_t addr) {
    asm volatile("ldmatrix.sync.aligned.m8n8.x4.shared.b16 {%0,%1,%2,%3}, [%4];"
                 : "=r"(r[0]), "=r"(r[1]), "=r"(r[2]), "=r"(r[3]) : "r"(addr));
}
__device__ __forceinline__ void ldsm2(uint32_t* r, uint32_t addr) {
    asm volatile("ldmatrix.sync.aligned.m8n8.x2.shared.b16 {%0,%1}, [%2];"
                 : "=r"(r[0]), "=r"(r[1]) : "r"(addr));
}
__device__ __forceinline__ float f2tf_f(float x) {
    uint32_t y;
    asm("cvt.rna.tf32.f32 %0, %1;" : "=r"(y) : "f"(x));
    return __uint_as_float(y);
}
// mma.sync tf32 reads only the top 19 bits of operand registers (HW
// truncation); only weights are pre-rounded (RNA, free in transpose).
__device__ __forceinline__ void mma8(float* d, const uint32_t* a, const uint32_t* b) {
    asm volatile("mma.sync.aligned.m16n8k8.row.col.f32.tf32.tf32.f32 "
                 "{%0,%1,%2,%3}, {%4,%5,%6,%7}, {%8,%9}, {%0,%1,%2,%3};"
                 : "+f"(d[0]), "+f"(d[1]), "+f"(d[2]), "+f"(d[3])
                 : "r"(a[0]), "r"(a[1]), "r"(a[2]), "r"(a[3]),
                   "r"(b[0]), "r"(b[1]));
}

// ======================  mma.sync tf32 GEMM body (2-stage, proven) ==========
#define GK 1024
#define GN 1024
#define BKC 32
#define NKT (GK/BKC)
#define STAGE_B (128*36*4)    // 18432 B per matrix per stage
#define GSM_TOTAL (4*STAGE_B) // 73728 B

// If toVT != nullptr, epilogue writes the per-(b,h)-transposed V layout.
__device__ __forceinline__ void gemm_body(
    char* smem, const float* __restrict__ A, const float* __restrict__ BT,
    const float* __restrict__ bias, const float* __restrict__ res,
    float* __restrict__ C, float* __restrict__ toVT, int bx, int by)
{
    uint32_t sb = smem_u32(smem);
    const int tid = threadIdx.x;
    const int lane = tid & 31;
    const int wid = tid >> 5;
    const int warp_m = wid >> 2;
    const int warp_n = wid & 3;
    const int row0 = by * 128;
    const int col0 = bx * 128;

    const float* Abase = A  + (size_t)row0 * GK;
    const float* Bbase = BT + (size_t)col0 * GK;

    auto load_stage = [&](int stage, int kt) {
        uint32_t as = sb + (stage * 2 + 0) * STAGE_B;
        uint32_t bs = sb + (stage * 2 + 1) * STAGE_B;
        const float* Ak = Abase + kt * BKC;
        const float* Bk = Bbase + kt * BKC;
        #pragma unroll
        for (int i = 0; i < 4; i++) {
            int c = tid + i * 256;
            int r = c >> 3, sg = c & 7;
            cp16(as + (uint32_t)(r * 144 + sg * 16), Ak + (size_t)r * GK + sg * 4);
            cp16(bs + (uint32_t)(r * 144 + sg * 16), Bk + (size_t)r * GK + sg * 4);
        }
        CP_COMMIT();
    };

    uint32_t a_off[4], b_off[4];
    #pragma unroll
    for (int mf = 0; mf < 4; mf++)
        a_off[mf] = (uint32_t)((warp_m * 64 + mf * 16 + (lane & 15)) * 144
                               + (lane >> 4) * 16);
    #pragma unroll
    for (int nf = 0; nf < 4; nf++)
        b_off[nf] = (uint32_t)((warp_n * 32 + nf * 8 + (lane & 7)) * 144
                               + ((lane >> 3) & 1) * 16);

    float acc[4][4][4] = {};

    load_stage(0, 0);
    int buf = 0;
    for (int kt = 0; kt < NKT; kt++) {
        if (kt + 1 < NKT) {
            load_stage(buf ^ 1, kt + 1);
            CP_WAIT1();
        } else {
            CP_WAIT0();
        }
        __syncthreads();

        uint32_t as = sb + (buf * 2 + 0) * STAGE_B;
        uint32_t bs = sb + (buf * 2 + 1) * STAGE_B;
        #pragma unroll
        for (int ks = 0; ks < 4; ks++) {
            uint32_t a[4][4], b[4][2];
            #pragma unroll
            for (int mf = 0; mf < 4; mf++)
                ldsm4(a[mf], as + a_off[mf] + ks * 32);
            #pragma unroll
            for (int nf = 0; nf < 4; nf++)
                ldsm2(b[nf], bs + b_off[nf] + ks * 32);
            #pragma unroll
            for (int mf = 0; mf < 4; mf++)
                #pragma unroll
                for (int nf = 0; nf < 4; nf++)
                    mma8(acc[mf][nf], a[mf], b[nf]);
        }
        __syncthreads();
        buf ^= 1;
    }

    #pragma unroll
    for (int nf = 0; nf < 4; nf++) {
        int c = col0 + warp_n * 32 + nf * 8 + 2 * (lane & 3);
        float bx_ = __ldg(bias + c), by_ = __ldg(bias + c + 1);
        #pragma unroll
        for (int mf = 0; mf < 4; mf++) {
            int r = row0 + warp_m * 64 + mf * 16 + (lane >> 2);
            float2 v0 = make_float2(acc[mf][nf][0] + bx_, acc[mf][nf][1] + by_);
            float2 v1 = make_float2(acc[mf][nf][2] + bx_, acc[mf][nf][3] + by_);
            if (res) {
                float2 r0 = *(const float2*)(res + (size_t)r * GN + c);
                float2 r1 = *(const float2*)(res + (size_t)(r + 8) * GN + c);
                v0.x += r0.x; v0.y += r0.y;
                v1.x += r1.x; v1.y += r1.y;
            }
            if (toVT) {
                int b_ = r >> 10, s = r & 1023;
                int h_ = c >> 6, d = c & 63;
                size_t i0 = ((size_t)((b_ * 16 + h_) * 64 + d)) << 10;
                toVT[i0 + s]            = v0.x;
                toVT[i0 + 1024 + s]     = v0.y;
                toVT[i0 + s + 8]        = v1.x;
                toVT[i0 + 1024 + s + 8] = v1.y;
            } else {
                *(float2*)(C + (size_t)r * GN + c) = v0;
                *(float2*)(C + (size_t)(r + 8) * GN + c) = v1;
            }
        }
    }
}

__global__ void __launch_bounds__(256, 2)
qkv_gemm(const float* q, const float* k, const float* v,
         const float* wq, const float* wk, const float* wv,
         const float* bq, const float* bk, const float* bv,
         float* oq, float* ok, float* ovt)
{
    extern __shared__ char smem[];
    int z = blockIdx.z;
    const float* A  = (z == 0) ? q  : (z == 1) ? k  : v;
    const float* BT = (z == 0) ? wq : (z == 1) ? wk : wv;
    const float* bi = (z == 0) ? bq : (z == 1) ? bk : bv;
    float* C        = (z == 0) ? oq : (z == 1) ? ok : nullptr;
    float* VT       = (z == 2) ? ovt : nullptr;
    gemm_body(smem, A, BT, bi, nullptr, C, VT, blockIdx.x, blockIdx.y);
}

__global__ void __launch_bounds__(256, 2)
o_gemm(const float* A, const float* BT, const float* bias,
       const float* res, float* C)
{
    extern __shared__ char smem[];
    gemm_body(smem, A, BT, bias, res, C, nullptr, blockIdx.x, blockIdx.y);
}

// ------------ fused weight transpose (+tf32 RNA round): all 4 weights -------
__global__ void trans4_kernel(const float* __restrict__ s0, float* __restrict__ d0,
                              const float* __restrict__ s1, float* __restrict__ d1,
                              const float* __restrict__ s2, float* __restrict__ d2,
                              const float* __restrict__ s3, float* __restrict__ d3)
{
    __shared__ float t[32][33];
    int zz = blockIdx.z;
    const float* src = (zz == 0) ? s0 : (zz == 1) ? s1 : (zz == 2) ? s2 : s3;
    float* dst       = (zz == 0) ? d0 : (zz == 1) ? d1 : (zz == 2) ? d2 : d3;
    int x = blockIdx.x * 32 + threadIdx.x;
    int y0 = blockIdx.y * 32;
    #pragma unroll
    for (int i = threadIdx.y; i < 32; i += 8)
        t[i][threadIdx.x] = src[(size_t)(y0 + i) * HH + x];
    __syncthreads();
    int xo = blockIdx.y * 32 + threadIdx.x;
    int yo0 = blockIdx.x * 32;
    #pragma unroll
    for (int i = threadIdx.y; i < 32; i += 8)
        dst[(size_t)(yo0 + i) * HH + xo] = f2tf_f(t[threadIdx.x][i]);
}

// ---------------- query column means: 64 blocks ----------------
__global__ void qmean_part(const float* __restrict__ q)
{
    int b = blockIdx.y, ch = blockIdx.x;     // 32 chunks of 32 rows
    int tid = threadIdx.x;
    for (int c = tid; c < HH; c += 256) {
        const float* base = q + ((size_t)b * SS + ch * 32) * HH + c;
        float s = 0.f;
        #pragma unroll 4
        for (int r = 0; r < 32; r++) s += base[(size_t)r * HH];
        g_part[((size_t)b * 32 + ch) * HH + c] = s;
    }
}

// -------- spec layer-1 partials: grid(32 rowchunks, 4 colgroups, BB) -------
__global__ void spec1_kernel(const float* __restrict__ Ws1)
{
    __shared__ float sin_s[32];
    int b = blockIdx.z, ch = blockIdx.x, cg = blockIdx.y;
    int tid = threadIdx.x;          // 128
    int r0 = ch * 32;
    if (tid < 32) {
        float s = 0.f;
        #pragma unroll
        for (int p = 0; p < 32; p++) s += g_part[((size_t)b * 32 + p) * HH + r0 + tid];
        sin_s[tid] = s * (1.0f / SS);
    }
    __syncthreads();
    int col = cg * 128 + tid;
    float acc = 0.f;
    #pragma unroll
    for (int j = 0; j < 32; j++)
        acc += sin_s[j] * Ws1[(size_t)(r0 + j) * 512 + col];
    g_h1p[(size_t)(b * 32 + ch) * 512 + col] = acc;
}

// -------- spec layer-2: grid(16 colblocks, BB), 256 thr --------------------
__global__ void spec2_kernel(const float* __restrict__ bs1,
                             const float* __restrict__ Ws2,
                             const float* __restrict__ bs2)
{
    __shared__ float h1[512];
    __shared__ float zp[4][64];
    __shared__ float red[64];
    int b = blockIdx.y, cb = blockIdx.x;
    int tid = threadIdx.x;          // 256
    for (int c = tid; c < 512; c += 256) {
        float s = bs1[c];
        #pragma unroll
        for (int ch = 0; ch < 32; ch++) s += g_h1p[(size_t)(b * 32 + ch) * 512 + c];
        h1[c] = fmaxf(s, 0.f);
    }
    __syncthreads();
    int col = cb * 64 + (tid & 63);
    int qq = tid >> 6;              // 0..3
    float z = 0.f;
    #pragma unroll 4
    for (int i = qq * 128; i < qq * 128 + 128; i++)
        z += h1[i] * Ws2[(size_t)i * HH + col];
    zp[qq][tid & 63] = z;
    __syncthreads();
    if (tid < 64) {
        float zz = bs2[cb * 64 + tid] + zp[0][tid] + zp[1][tid] + zp[2][tid] + zp[3][tid];
        red[tid] = 1.0f / (1.0f + __expf(-zz));
    }
    __syncthreads();
    for (int off = 32; off > 0; off >>= 1) {
        if (tid < off) red[tid] += red[tid + off];
        __syncthreads();
    }
    if (tid == 0) g_sp[b * 16 + cb] = red[0];
}

// ========  tensor-core flash attention: 32-key tiles, double-buffered  ======
// smem: Q(128x272B) K0/K1(32x272B) V0/V1(64x144B) P(128x144B) = 89088 B
#define ASTR 272                       // Q/K row stride (68 floats)
#define PSTR 144                       // P/V row stride (36 floats)
#define AQ_OFF 0
#define K0_OFF 34816
#define K1_OFF 43520
#define V0_OFF 52224
#define V1_OFF 61440
#define P_OFF  70656
#define A_SMEM 89088

__global__ void __launch_bounds__(256, 2)
attn_mma(const float* __restrict__ msb)
{
    extern __shared__ char smem[];
    __shared__ float red[256];
    __shared__ float mh_s;
    uint32_t sb = smem_u32(smem);
    const int tid = threadIdx.x;
    const int lane = tid & 31;
    const int w = tid >> 5;
    const int b = blockIdx.z, h = blockIdx.y, q0 = blockIdx.x << 7;

    const uint32_t Qa = sb + AQ_OFF + (uint32_t)((16 * w + (lane & 15)) * ASTR + (lane >> 4) * 16);
    const uint32_t Pa = sb + P_OFF  + (uint32_t)((16 * w + (lane & 15)) * PSTR + (lane >> 4) * 16);
    const uint32_t krow = (uint32_t)(((((lane >> 4) << 3) + (lane & 7)) * ASTR) + ((lane >> 3) & 1) * 16);
    const uint32_t vrow = (uint32_t)(((((lane >> 4) << 3) + (lane & 7)) * PSTR) + ((lane >> 3) & 1) * 16);
    const uint32_t Kb[2] = { sb + K0_OFF + krow, sb + K1_OFF + krow };
    const uint32_t Vb[2] = { sb + V0_OFF + vrow, sb + V1_OFF + vrow };
    const uint32_t koff[2] = { K0_OFF, K1_OFF };
    const uint32_t voff[2] = { V0_OFF, V1_OFF };

    const float* Kg0 = g_K + (size_t)b * SS * HH + h * HDD;
    const float* Vg0 = g_VT + (size_t)(b * NHH + h) * HDD * SS;

    // K tile load: 32 rows x 64 floats; V tile: 64 rows x 32 floats.
    auto load_tile = [&](int bufsel, int kt) {
        const float* Kg = Kg0 + (size_t)kt * 32 * HH;
        const float* Vg = Vg0 + kt * 32;
        #pragma unroll
        for (int i = 0; i < 2; i++) {
            int f = tid + i * 256;
            int rk = f >> 4, ck = f & 15;          // K: 32 rows, 16 segs
            cp16(sb + koff[bufsel] + (uint32_t)(rk * ASTR + ck * 16),
                 Kg + (size_t)rk * HH + ck * 4);
            int rv = f >> 3, cv = f & 7;           // V: 64 rows, 8 segs
            cp16(sb + voff[bufsel] + (uint32_t)(rv * PSTR + cv * 16),
                 Vg + (size_t)rv * SS + cv * 4);
        }
        CP_COMMIT();
    };

    // ---- prologue: Q + tile 0, msb reduce ----
    {
        const float* Qg = g_Q + ((size_t)b * SS + q0) * HH + h * HDD;
        #pragma unroll
        for (int i = 0; i < 8; i++) {
            int f = tid + i * 256;
            int r = f >> 4, c4 = f & 15;
            cp16(sb + AQ_OFF + (uint32_t)(r * ASTR + c4 * 16),
                 Qg + (size_t)r * HH + c4 * 4);
        }
        load_tile(0, 0);
    }
    {
        const float* p = msb + (size_t)h * HDD * HDD;
        float s = 0.f;
        for (int i = tid; i < HDD * HDD; i += 256) s += p[i];
        red[tid] = s;
        __syncthreads();
        for (int off = 128; off > 0; off >>= 1) {
            if (tid < off) red[tid] += red[tid + off];
            __syncthreads();
        }
        if (tid == 0) mh_s = red[0] * (1.0f / (HDD * HDD));
    }
    CP_WAIT0();
    __syncthreads();

    const float mh = mh_s;
    float sp = 0.f;
    #pragma unroll
    for (int j = 0; j < 16; j++) sp += g_sp[b * 16 + j];
    sp *= (1.0f / HH);

    float oacc[8][4] = {};
    float m0 = -1e30f, m1 = -1e30f, l0 = 0.f, l1 = 0.f;

    for (int kt = 0; kt < 32; kt++) {
        int cur = kt & 1;
        if (kt + 1 < 32) load_tile(cur ^ 1, kt + 1);   // overlaps compute

        // ---- S = Q @ K^T  (16 q-rows x 32 keys) ----
        float sacc[4][4] = {};
        #pragma unroll
        for (int ks = 0; ks < 8; ks++) {
            uint32_t a[4];
            ldsm4(a, Qa + ks * 32);
            #pragma unroll
            for (int kb = 0; kb < 2; kb++) {
                uint32_t bb[4];
                ldsm4(bb, Kb[cur] + kb * 16 * ASTR + ks * 32);
                mma8(sacc[2 * kb],     a, bb);
                mma8(sacc[2 * kb + 1], a, bb + 2);
            }
        }

        // ---- gate + online softmax ----
        float tm0 = -1e30f, tm1 = -1e30f;
        #pragma unroll
        for (int nf = 0; nf < 4; nf++) {
            #pragma unroll
            for (int j = 0; j < 4; j++) {
                float s0 = sacc[nf][j] * SCALE_C;
                float e = 1.0f / (1.0f + __expf(-s0 * mh));
                float p = s0 * (1.0f + e * SP_C) * sp;
                sacc[nf][j] = p;
                if (j < 2) tm0 = fmaxf(tm0, p); else tm1 = fmaxf(tm1, p);
            }
        }
        tm0 = fmaxf(tm0, __shfl_xor_sync(0xffffffff, tm0, 1));
        tm0 = fmaxf(tm0, __shfl_xor_sync(0xffffffff, tm0, 2));
        tm1 = fmaxf(tm1, __shfl_xor_sync(0xffffffff, tm1, 1));
        tm1 = fmaxf(tm1, __shfl_xor_sync(0xffffffff, tm1, 2));

        float nm0 = fmaxf(m0, tm0), nm1 = fmaxf(m1, tm1);
        float sc0 = __expf(m0 - nm0), sc1 = __expf(m1 - nm1);
        float su0 = 0.f, su1 = 0.f;
        #pragma unroll
        for (int nf = 0; nf < 4; nf++) {
            float p0 = __expf(sacc[nf][0] - nm0);
            float p1 = __expf(sacc[nf][1] - nm0);
            float p2 = __expf(sacc[nf][2] - nm1);
            float p3 = __expf(sacc[nf][3] - nm1);
            su0 += p0 + p1; su1 += p2 + p3;
            sacc[nf][0] = p0; sacc[nf][1] = p1;
            sacc[nf][2] = p2; sacc[nf][3] = p3;
        }
        su0 += __shfl_xor_sync(0xffffffff, su0, 1);
        su0 += __shfl_xor_sync(0xffffffff, su0, 2);
        su1 += __shfl_xor_sync(0xffffffff, su1, 1);
        su1 += __shfl_xor_sync(0xffffffff, su1, 2);
        l0 = l0 * sc0 + su0;
        l1 = l1 * sc1 + su1;
        m0 = nm0; m1 = nm1;

        #pragma unroll
        for (int nf = 0; nf < 8; nf++) {
            oacc[nf][0] *= sc0; oacc[nf][1] *= sc0;
            oacc[nf][2] *= sc1; oacc[nf][3] *= sc1;
        }

        // ---- write P to smem (warp-local rows; ldmatrix is warp-sync) ----
        {
            int r0 = 16 * w + (lane >> 2);
            uint32_t p0a = (uint32_t)(P_OFF + r0 * PSTR + 2 * (lane & 3) * 4);
            #pragma unroll
            for (int nf = 0; nf < 4; nf++) {
                *(float2*)(smem + p0a + nf * 32) =
                    make_float2(sacc[nf][0], sacc[nf][1]);
                *(float2*)(smem + p0a + 8 * PSTR + nf * 32) =
                    make_float2(sacc[nf][2], sacc[nf][3]);
            }
        }
        __syncwarp();

        // ---- O += P @ V ----
        #pragma unroll
        for (int ks = 0; ks < 4; ks++) {
            uint32_t a[4];
            ldsm4(a, Pa + ks * 32);
            #pragma unroll
            for (int db = 0; db < 4; db++) {
                uint32_t bb[4];
                ldsm4(bb, Vb[cur] + db * 16 * PSTR + ks * 32);
                mma8(oacc[2 * db],     a, bb);
                mma8(oacc[2 * db + 1], a, bb + 2);
            }
        }

        if (kt + 1 < 32) CP_WAIT0();
        __syncthreads();   // next tile visible; cur buffers free for reuse
    }

    // ---- epilogue: normalize + store ctx ----
    float inv0 = 1.0f / l0, inv1 = 1.0f / l1;
    float* Og = g_ctx + ((size_t)b * SS + q0) * HH + h * HDD;
    int r0 = 16 * w + (lane >> 2);
    #pragma unroll
    for (int nf = 0; nf < 8; nf++) {
        int c = 8 * nf + 2 * (lane & 3);
        *(float2*)&Og[(size_t)r0 * HH + c] =
            make_float2(oacc[nf][0] * inv0, oacc[nf][1] * inv0);
        *(float2*)&Og[(size_t)(r0 + 8) * HH + c] =
            make_float2(oacc[nf][2] * inv1, oacc[nf][3] * inv1);
    }
}

// ---------------- row LayerNorm ----------------
__global__ void ln_kernel(const float* __restrict__ x,
                          const float* __restrict__ g,
                          const float* __restrict__ bta,
                          float* __restrict__ out)
{
    __shared__ float r1[256];
    __shared__ float r2[256];
    int row = blockIdx.x, tid = threadIdx.x;
    const float4* xr = (const float4*)(x + (size_t)row * HH);
    float4 a = xr[tid];
    float s = a.x + a.y + a.z + a.w;
    float ss = a.x * a.x + a.y * a.y + a.z * a.z + a.w * a.w;
    r1[tid] = s; r2[tid] = ss;
    __syncthreads();
    for (int off = 128; off > 0; off >>= 1) {
        if (tid < off) { r1[tid] += r1[tid + off]; r2[tid] += r2[tid + off]; }
        __syncthreads();
    }
    float mu = r1[0] * (1.0f / HH);
    float var = r2[0] * (1.0f / HH) - mu * mu;
    float rstd = rsqrtf(var + EPS_C);
    float4 gg = ((const float4*)g)[tid];
    float4 bb = ((const float4*)bta)[tid];
    float4 o;
    o.x = (a.x - mu) * rstd * gg.x + bb.x;
    o.y = (a.y - mu) * rstd * gg.y + bb.y;
    o.z = (a.z - mu) * rstd * gg.z + bb.z;
    o.w = (a.w - mu) * rstd * gg.w + bb.w;
    ((float4*)(out + (size_t)row * HH))[tid] = o;
}

// ---------------- launch ----------------
extern "C" void kernel_launch(void* const* d_in, const int* in_sizes, int n_in,
                              void* d_out, int out_size)
{
    const float* query = (const float*)d_in[0];
    const float* key_t = (const float*)d_in[1];
    const float* value = (const float*)d_in[2];
    const float* Wq = (const float*)d_in[3];
    const float* bq = (const float*)d_in[4];
    const float* Wk = (const float*)d_in[5];
    const float* bk = (const float*)d_in[6];
    const float* Wv = (const float*)d_in[7];
    const float* bv = (const float*)d_in[8];
    const float* msb = (const float*)d_in[9];
    const float* Ws1 = (const float*)d_in[10];
    const float* bs1 = (const float*)d_in[11];
    const float* Ws2 = (const float*)d_in[12];
    const float* bs2 = (const float*)d_in[13];
    const float* Wo = (const float*)d_in[14];
    const float* bo = (const float*)d_in[15];
    const float* ln_g = (const float*)d_in[16];
    const float* ln_b = (const float*)d_in[17];

    float *pQ, *pK, *pVT, *pCtx, *pPre, *pWT;
    cudaGetSymbolAddress((void**)&pQ, g_Q);
    cudaGetSymbolAddress((void**)&pK, g_K);
    cudaGetSymbolAddress((void**)&pVT, g_VT);
    cudaGetSymbolAddress((void**)&pCtx, g_ctx);
    cudaGetSymbolAddress((void**)&pPre, g_pre);
    cudaGetSymbolAddress((void**)&pWT, g_WT);

    float* WTq = pWT + 0 * HH * HH;
    float* WTk = pWT + 1 * HH * HH;
    float* WTv = pWT + 2 * HH * HH;
    float* WTo = pWT + 3 * HH * HH;

    cudaFuncSetAttribute(qkv_gemm, cudaFuncAttributeMaxDynamicSharedMemorySize,
                         GSM_TOTAL);
    cudaFuncSetAttribute(o_gemm, cudaFuncAttributeMaxDynamicSharedMemorySize,
                         GSM_TOTAL);
    cudaFuncSetAttribute(attn_mma, cudaFuncAttributeMaxDynamicSharedMemorySize,
                         A_SMEM);

    dim3 tb(32, 8);
    dim3 tg4(32, 32, 4);

    // 0: all 4 weight transposes (+tf32 RNA rounding)
    trans4_kernel<<<tg4, tb>>>(Wq, WTq, Wk, WTk, Wv, WTv, Wo, WTo);
    // 1: query column sums
    qmean_part<<<dim3(32, BB), 256>>>(query);
    // 2: spec layer-1 partials
    spec1_kernel<<<dim3(32, 4, BB), 128>>>(Ws1);
    // 3 (profiled slot): fused Q/K/V projection GEMM (V written transposed)
    qkv_gemm<<<dim3(GN / 128, M_TOT / 128, 3), 256, GSM_TOTAL>>>(
        query, key_t, value, WTq, WTk, WTv, bq, bk, bv, pQ, pK, pVT);
    // 4: spec layer-2
    spec2_kernel<<<dim3(16, BB), 256>>>(bs1, Ws2, bs2);
    // 5: pipelined tensor-core flash attention
    attn_mma<<<dim3(SS / 128, NHH, BB), 256, A_SMEM>>>(msb);
    // 6: output projection + bias + residual
    o_gemm<<<dim3(GN / 128, M_TOT / 128), 256, GSM_TOTAL>>>(pCtx, WTo, bo, query, pPre);
    // 7: LayerNorm -> d_out
    ln_kernel<<<M_TOT, 256>>>(pPre, ln_g, ln_b, (float*)d_out);
}

// round 11
// speedup vs baseline: 1.3668x; 1.0312x over previous
#include <cuda_runtime.h>
#include <cuda_bf16.h>
#include <math.h>
#include <cstdint>

// Problem constants
#define BB 2
#define SS 1024
#define HH 1024
#define NHH 16
#define HDD 64
#define SP_C 0.05f
#define EPS_C 1e-5f
#define SCALE_C 0.125f   // 1/sqrt(64)

#define M_TOT (BB*SS)    // 2048

// ---------------- scratch (device globals: no allocations allowed) ----------
__device__ float g_Q[M_TOT*HH];
__device__ float g_K[M_TOT*HH];
__device__ float g_VT[BB*NHH*HDD*SS];   // V transposed per (b,h): [d][s]
__device__ float g_ctx[M_TOT*HH];
__device__ float g_pre[M_TOT*HH];
__device__ float g_WT[4*HH*HH];      // transposed tf32-rounded weights
__device__ float g_part[BB*32*HH];   // partial column sums of query over seq
__device__ float g_h1p[BB*32*512];   // spec layer-1 partials
__device__ float g_sp[BB*16];        // spec sigmoid-sum partials

// =====================  PTX helpers (mma.sync / cp.async)  ==================
__device__ __forceinline__ uint32_t smem_u32(const void* p) {
    uint32_t a;
    asm("{ .reg .u64 t; cvta.to.shared.u64 t, %1; cvt.u32.u64 %0, t; }"
        : "=r"(a) : "l"(p));
    return a;
}

__device__ __forceinline__ void cp16(uint32_t s, const float* g) {
    asm volatile("cp.async.cg.shared.global [%0], [%1], 16;"
                 :: "r"(s), "l"(__cvta_generic_to_global(g)));
}
#define CP_COMMIT() asm volatile("cp.async.commit_group;" ::: "memory")
#define CP_WAIT0()  asm volatile("cp.async.wait_group 0;" ::: "memory")
#define CP_WAIT1()  asm volatile("cp.async.wait_group 1;" ::: "memory")

__device__ __forceinline__ void ldsm4(uint32_t* r, uint32_t addr) {
    asm volatile("ldmatrix.sync.aligned.m8n8.x4.shared.b16 {%0,%1,%2,%3}, [%4];"
                 : "=r"(r[0]), "=r"(r[1]), "=r"(r[2]), "=r"(r[3]) : "r"(addr));
}
__device__ __forceinline__ float f2tf_f(float x) {
    uint32_t y;
    asm("cvt.rna.tf32.f32 %0, %1;" : "=r"(y) : "f"(x));
    return __uint_as_float(y);
}
// mma.sync tf32 reads only the top 19 bits of operand registers (HW
// truncation); only weights are pre-rounded (RNA, free in transpose).
__device__ __forceinline__ void mma8(float* d, const uint32_t* a, const uint32_t* b) {
    asm volatile("mma.sync.aligned.m16n8k8.row.col.f32.tf32.tf32.f32 "
                 "{%0,%1,%2,%3}, {%4,%5,%6,%7}, {%8,%9}, {%0,%1,%2,%3};"
                 : "+f"(d[0]), "+f"(d[1]), "+f"(d[2]), "+f"(d[3])
                 : "r"(a[0]), "r"(a[1]), "r"(a[2]), "r"(a[3]),
                   "r"(b[0]), "r"(b[1]));
}

// ======================  mma.sync tf32 GEMM body (2-stage)  =================
#define GK 1024
#define GN 1024
#define BKC 32
#define NKT (GK/BKC)
#define STAGE_B (128*36*4)    // 18432 B per matrix per stage
#define GSM_TOTAL (4*STAGE_B) // 73728 B

// If toVT != nullptr, epilogue writes the per-(b,h)-transposed V layout.
__device__ __forceinline__ void gemm_body(
    char* smem, const float* __restrict__ A, const float* __restrict__ BT,
    const float* __restrict__ bias, const float* __restrict__ res,
    float* __restrict__ C, float* __restrict__ toVT, int bx, int by)
{
    uint32_t sb = smem_u32(smem);
    const int tid = threadIdx.x;
    const int lane = tid & 31;
    const int wid = tid >> 5;
    const int warp_m = wid >> 2;
    const int warp_n = wid & 3;
    const int row0 = by * 128;
    const int col0 = bx * 128;

    const float* Abase = A  + (size_t)row0 * GK;
    const float* Bbase = BT + (size_t)col0 * GK;

    auto load_stage = [&](int stage, int kt) {
        uint32_t as = sb + (stage * 2 + 0) * STAGE_B;
        uint32_t bs = sb + (stage * 2 + 1) * STAGE_B;
        const float* Ak = Abase + kt * BKC;
        const float* Bk = Bbase + kt * BKC;
        #pragma unroll
        for (int i = 0; i < 4; i++) {
            int c = tid + i * 256;
            int r = c >> 3, sg = c & 7;
            cp16(as + (uint32_t)(r * 144 + sg * 16), Ak + (size_t)r * GK + sg * 4);
            cp16(bs + (uint32_t)(r * 144 + sg * 16), Bk + (size_t)r * GK + sg * 4);
        }
        CP_COMMIT();
    };

    // A: ldsm4 per 16-row M-fragment (as before).
    // B: paired ldsm4 — one x4 covers two adjacent 8-row N-fragments
    //    (lanes 0-15 address rows p*16..+8 seg0/1; lanes 16-31 rows +8).
    uint32_t a_off[4], bp_off[2];
    #pragma unroll
    for (int mf = 0; mf < 4; mf++)
        a_off[mf] = (uint32_t)((warp_m * 64 + mf * 16 + (lane & 15)) * 144
                               + (lane >> 4) * 16);
    #pragma unroll
    for (int p = 0; p < 2; p++)
        bp_off[p] = (uint32_t)((warp_n * 32 + p * 16 + ((lane >> 4) << 3) + (lane & 7)) * 144
                               + ((lane >> 3) & 1) * 16);

    float acc[4][4][4] = {};

    load_stage(0, 0);
    int buf = 0;
    for (int kt = 0; kt < NKT; kt++) {
        if (kt + 1 < NKT) {
            load_stage(buf ^ 1, kt + 1);
            CP_WAIT1();
        } else {
            CP_WAIT0();
        }
        __syncthreads();

        uint32_t as = sb + (buf * 2 + 0) * STAGE_B;
        uint32_t bs = sb + (buf * 2 + 1) * STAGE_B;
        #pragma unroll
        for (int ks = 0; ks < 4; ks++) {
            uint32_t a[4][4], bfr[2][4];
            #pragma unroll
            for (int mf = 0; mf < 4; mf++)
                ldsm4(a[mf], as + a_off[mf] + ks * 32);
            #pragma unroll
            for (int p = 0; p < 2; p++)
                ldsm4(bfr[p], bs + bp_off[p] + ks * 32);
            #pragma unroll
            for (int mf = 0; mf < 4; mf++) {
                mma8(acc[mf][0], a[mf], &bfr[0][0]);
                mma8(acc[mf][1], a[mf], &bfr[0][2]);
                mma8(acc[mf][2], a[mf], &bfr[1][0]);
                mma8(acc[mf][3], a[mf], &bfr[1][2]);
            }
        }
        __syncthreads();
        buf ^= 1;
    }

    #pragma unroll
    for (int nf = 0; nf < 4; nf++) {
        int c = col0 + warp_n * 32 + nf * 8 + 2 * (lane & 3);
        float bx_ = __ldg(bias + c), by_ = __ldg(bias + c + 1);
        #pragma unroll
        for (int mf = 0; mf < 4; mf++) {
            int r = row0 + warp_m * 64 + mf * 16 + (lane >> 2);
            float2 v0 = make_float2(acc[mf][nf][0] + bx_, acc[mf][nf][1] + by_);
            float2 v1 = make_float2(acc[mf][nf][2] + bx_, acc[mf][nf][3] + by_);
            if (res) {
                float2 r0 = *(const float2*)(res + (size_t)r * GN + c);
                float2 r1 = *(const float2*)(res + (size_t)(r + 8) * GN + c);
                v0.x += r0.x; v0.y += r0.y;
                v1.x += r1.x; v1.y += r1.y;
            }
            if (toVT) {
                int b_ = r >> 10, s = r & 1023;
                int h_ = c >> 6, d = c & 63;
                size_t i0 = ((size_t)((b_ * 16 + h_) * 64 + d)) << 10;
                toVT[i0 + s]            = v0.x;
                toVT[i0 + 1024 + s]     = v0.y;
                toVT[i0 + s + 8]        = v1.x;
                toVT[i0 + 1024 + s + 8] = v1.y;
            } else {
                *(float2*)(C + (size_t)r * GN + c) = v0;
                *(float2*)(C + (size_t)(r + 8) * GN + c) = v1;
            }
        }
    }
}

__global__ void __launch_bounds__(256, 2)
qkv_gemm(const float* q, const float* k, const float* v,
         const float* wq, const float* wk, const float* wv,
         const float* bq, const float* bk, const float* bv,
         float* oq, float* ok, float* ovt)
{
    extern __shared__ char smem[];
    int z = blockIdx.z;
    const float* A  = (z == 0) ? q  : (z == 1) ? k  : v;
    const float* BT = (z == 0) ? wq : (z == 1) ? wk : wv;
    const float* bi = (z == 0) ? bq : (z == 1) ? bk : bv;
    float* C        = (z == 0) ? oq : (z == 1) ? ok : nullptr;
    float* VT       = (z == 2) ? ovt : nullptr;
    gemm_body(smem, A, BT, bi, nullptr, C, VT, blockIdx.x, blockIdx.y);
}

__global__ void __launch_bounds__(256, 2)
o_gemm(const float* A, const float* BT, const float* bias,
       const float* res, float* C)
{
    extern __shared__ char smem[];
    gemm_body(smem, A, BT, bias, res, C, nullptr, blockIdx.x, blockIdx.y);
}

// ------------ fused weight transpose (+tf32 RNA round): all 4 weights -------
__global__ void trans4_kernel(const float* __restrict__ s0, float* __restrict__ d0,
                              const float* __restrict__ s1, float* __restrict__ d1,
                              const float* __restrict__ s2, float* __restrict__ d2,
                              const float* __restrict__ s3, float* __restrict__ d3)
{
    __shared__ float t[32][33];
    int zz = blockIdx.z;
    const float* src = (zz == 0) ? s0 : (zz == 1) ? s1 : (zz == 2) ? s2 : s3;
    float* dst       = (zz == 0) ? d0 : (zz == 1) ? d1 : (zz == 2) ? d2 : d3;
    int x = blockIdx.x * 32 + threadIdx.x;
    int y0 = blockIdx.y * 32;
    #pragma unroll
    for (int i = threadIdx.y; i < 32; i += 8)
        t[i][threadIdx.x] = src[(size_t)(y0 + i) * HH + x];
    __syncthreads();
    int xo = blockIdx.y * 32 + threadIdx.x;
    int yo0 = blockIdx.x * 32;
    #pragma unroll
    for (int i = threadIdx.y; i < 32; i += 8)
        dst[(size_t)(yo0 + i) * HH + xo] = f2tf_f(t[threadIdx.x][i]);
}

// ---------------- query column means: 64 blocks ----------------
__global__ void qmean_part(const float* __restrict__ q)
{
    int b = blockIdx.y, ch = blockIdx.x;     // 32 chunks of 32 rows
    int tid = threadIdx.x;
    for (int c = tid; c < HH; c += 256) {
        const float* base = q + ((size_t)b * SS + ch * 32) * HH + c;
        float s = 0.f;
        #pragma unroll 4
        for (int r = 0; r < 32; r++) s += base[(size_t)r * HH];
        g_part[((size_t)b * 32 + ch) * HH + c] = s;
    }
}

// -------- spec layer-1 partials: grid(32 rowchunks, 4 colgroups, BB) -------
__global__ void spec1_kernel(const float* __restrict__ Ws1)
{
    __shared__ float sin_s[32];
    int b = blockIdx.z, ch = blockIdx.x, cg = blockIdx.y;
    int tid = threadIdx.x;          // 128
    int r0 = ch * 32;
    if (tid < 32) {
        float s = 0.f;
        #pragma unroll
        for (int p = 0; p < 32; p++) s += g_part[((size_t)b * 32 + p) * HH + r0 + tid];
        sin_s[tid] = s * (1.0f / SS);
    }
    __syncthreads();
    int col = cg * 128 + tid;
    float acc = 0.f;
    #pragma unroll
    for (int j = 0; j < 32; j++)
        acc += sin_s[j] * Ws1[(size_t)(r0 + j) * 512 + col];
    g_h1p[(size_t)(b * 32 + ch) * 512 + col] = acc;
}

// -------- spec layer-2: grid(16 colblocks, BB), 256 thr --------------------
__global__ void spec2_kernel(const float* __restrict__ bs1,
                             const float* __restrict__ Ws2,
                             const float* __restrict__ bs2)
{
    __shared__ float h1[512];
    __shared__ float zp[4][64];
    __shared__ float red[64];
    int b = blockIdx.y, cb = blockIdx.x;
    int tid = threadIdx.x;          // 256
    for (int c = tid; c < 512; c += 256) {
        float s = bs1[c];
        #pragma unroll
        for (int ch = 0; ch < 32; ch++) s += g_h1p[(size_t)(b * 32 + ch) * 512 + c];
        h1[c] = fmaxf(s, 0.f);
    }
    __syncthreads();
    int col = cb * 64 + (tid & 63);
    int qq = tid >> 6;              // 0..3
    float z = 0.f;
    #pragma unroll 4
    for (int i = qq * 128; i < qq * 128 + 128; i++)
        z += h1[i] * Ws2[(size_t)i * HH + col];
    zp[qq][tid & 63] = z;
    __syncthreads();
    if (tid < 64) {
        float zz = bs2[cb * 64 + tid] + zp[0][tid] + zp[1][tid] + zp[2][tid] + zp[3][tid];
        red[tid] = 1.0f / (1.0f + __expf(-zz));
    }
    __syncthreads();
    for (int off = 32; off > 0; off >>= 1) {
        if (tid < off) red[tid] += red[tid + off];
        __syncthreads();
    }
    if (tid == 0) g_sp[b * 16 + cb] = red[0];
}

// ==  flash attention: Q in registers, 32-key tiles, double-buffered K/V  ====
// smem: K0,K1 (32x272B) V0,V1 (64x144B) P (128x144B) = 54272 B
// Q staged through [0, 34816) at prologue only (overlaps K/V buffers).
#define ASTR 272                       // Q-staging / K row stride
#define PSTR 144                       // P / V row stride
#define K0_OFF 0
#define K1_OFF 8704
#define V0_OFF 17408
#define V1_OFF 26624
#define P_OFF  35840
#define A_SMEM 54272

__global__ void __launch_bounds__(256, 2)
attn_mma(const float* __restrict__ msb)
{
    extern __shared__ char smem[];
    __shared__ float red[256];
    __shared__ float mh_s;
    uint32_t sb = smem_u32(smem);
    const int tid = threadIdx.x;
    const int lane = tid & 31;
    const int w = tid >> 5;
    const int b = blockIdx.z, h = blockIdx.y, q0 = blockIdx.x << 7;

    const uint32_t Pa = sb + P_OFF + (uint32_t)((16 * w + (lane & 15)) * PSTR + (lane >> 4) * 16);
    const uint32_t krow = (uint32_t)(((((lane >> 4) << 3) + (lane & 7)) * ASTR) + ((lane >> 3) & 1) * 16);
    const uint32_t vrow = (uint32_t)(((((lane >> 4) << 3) + (lane & 7)) * PSTR) + ((lane >> 3) & 1) * 16);
    const uint32_t Kb[2] = { sb + K0_OFF + krow, sb + K1_OFF + krow };
    const uint32_t Vb[2] = { sb + V0_OFF + vrow, sb + V1_OFF + vrow };
    const uint32_t koff[2] = { K0_OFF, K1_OFF };
    const uint32_t voff[2] = { V0_OFF, V1_OFF };

    const float* Kg0 = g_K + (size_t)b * SS * HH + h * HDD;
    const float* Vg0 = g_VT + (size_t)(b * NHH + h) * HDD * SS;

    // K tile: 32 rows x 64 floats (ASTR); V tile: 64 rows x 32 floats (PSTR).
    auto load_tile = [&](int bufsel, int kt) {
        const float* Kg = Kg0 + (size_t)kt * 32 * HH;
        const float* Vg = Vg0 + kt * 32;
        #pragma unroll
        for (int i = 0; i < 2; i++) {
            int f = tid + i * 256;
            int rk = f >> 4, ck = f & 15;
            cp16(sb + koff[bufsel] + (uint32_t)(rk * ASTR + ck * 16),
                 Kg + (size_t)rk * HH + ck * 4);
            int rv = f >> 3, cv = f & 7;
            cp16(sb + voff[bufsel] + (uint32_t)(rv * PSTR + cv * 16),
                 Vg + (size_t)rv * SS + cv * 4);
        }
        CP_COMMIT();
    };

    // ---- prologue: stage Q into smem[0..34816), msb reduce, Q -> regs ----
    {
        const float* Qg = g_Q + ((size_t)b * SS + q0) * HH + h * HDD;
        #pragma unroll
        for (int i = 0; i < 8; i++) {
            int f = tid + i * 256;
            int r = f >> 4, c4 = f & 15;
            cp16(sb + (uint32_t)(r * ASTR + c4 * 16),
                 Qg + (size_t)r * HH + c4 * 4);
        }
        CP_COMMIT();
    }
    {
        const float* p = msb + (size_t)h * HDD * HDD;
        float s = 0.f;
        for (int i = tid; i < HDD * HDD; i += 256) s += p[i];
        red[tid] = s;
        __syncthreads();
        for (int off = 128; off > 0; off >>= 1) {
            if (tid < off) red[tid] += red[tid + off];
            __syncthreads();
        }
        if (tid == 0) mh_s = red[0] * (1.0f / (HDD * HDD));
    }
    CP_WAIT0();
    __syncthreads();

    uint32_t qf[8][4];
    {
        uint32_t Qa = sb + (uint32_t)((16 * w + (lane & 15)) * ASTR + (lane >> 4) * 16);
        #pragma unroll
        for (int ks = 0; ks < 8; ks++) ldsm4(qf[ks], Qa + ks * 32);
    }
    __syncthreads();            // all warps done reading Q staging
    load_tile(0, 0);

    const float mh = mh_s;
    float sp = 0.f;
    #pragma unroll
    for (int j = 0; j < 16; j++) sp += g_sp[b * 16 + j];
    sp *= (1.0f / HH);

    CP_WAIT0();
    __syncthreads();

    float oacc[8][4] = {};
    float m0 = -1e30f, m1 = -1e30f, l0 = 0.f, l1 = 0.f;

    for (int kt = 0; kt < 32; kt++) {
        int cur = kt & 1;
        if (kt + 1 < 32) load_tile(cur ^ 1, kt + 1);   // overlaps compute

        // ---- S = Q @ K^T  (16 q-rows x 32 keys) ----
        float sacc[4][4] = {};
        #pragma unroll
        for (int ks = 0; ks < 8; ks++) {
            #pragma unroll
            for (int kb = 0; kb < 2; kb++) {
                uint32_t bb[4];
                ldsm4(bb, Kb[cur] + kb * 16 * ASTR + ks * 32);
                mma8(sacc[2 * kb],     qf[ks], bb);
                mma8(sacc[2 * kb + 1], qf[ks], bb + 2);
            }
        }

        // ---- gate + online softmax ----
        float tm0 = -1e30f, tm1 = -1e30f;
        #pragma unroll
        for (int nf = 0; nf < 4; nf++) {
            #pragma unroll
            for (int j = 0; j < 4; j++) {
                float s0 = sacc[nf][j] * SCALE_C;
                float e = 1.0f / (1.0f + __expf(-s0 * mh));
                float p = s0 * (1.0f + e * SP_C) * sp;
                sacc[nf][j] = p;
                if (j < 2) tm0 = fmaxf(tm0, p); else tm1 = fmaxf(tm1, p);
            }
        }
        tm0 = fmaxf(tm0, __shfl_xor_sync(0xffffffff, tm0, 1));
        tm0 = fmaxf(tm0, __shfl_xor_sync(0xffffffff, tm0, 2));
        tm1 = fmaxf(tm1, __shfl_xor_sync(0xffffffff, tm1, 1));
        tm1 = fmaxf(tm1, __shfl_xor_sync(0xffffffff, tm1, 2));

        float nm0 = fmaxf(m0, tm0), nm1 = fmaxf(m1, tm1);
        float sc0 = __expf(m0 - nm0), sc1 = __expf(m1 - nm1);
        float su0 = 0.f, su1 = 0.f;
        #pragma unroll
        for (int nf = 0; nf < 4; nf++) {
            float p0 = __expf(sacc[nf][0] - nm0);
            float p1 = __expf(sacc[nf][1] - nm0);
            float p2 = __expf(sacc[nf][2] - nm1);
            float p3 = __expf(sacc[nf][3] - nm1);
            su0 += p0 + p1; su1 += p2 + p3;
            sacc[nf][0] = p0; sacc[nf][1] = p1;
            sacc[nf][2] = p2; sacc[nf][3] = p3;
        }
        su0 += __shfl_xor_sync(0xffffffff, su0, 1);
        su0 += __shfl_xor_sync(0xffffffff, su0, 2);
        su1 += __shfl_xor_sync(0xffffffff, su1, 1);
        su1 += __shfl_xor_sync(0xffffffff, su1, 2);
        l0 = l0 * sc0 + su0;
        l1 = l1 * sc1 + su1;
        m0 = nm0; m1 = nm1;

        #pragma unroll
        for (int nf = 0; nf < 8; nf++) {
            oacc[nf][0] *= sc0; oacc[nf][1] *= sc0;
            oacc[nf][2] *= sc1; oacc[nf][3] *= sc1;
        }

        // ---- write P to smem (warp-local rows; ldmatrix is warp-sync) ----
        {
            int r0 = 16 * w + (lane >> 2);
            uint32_t p0a = (uint32_t)(P_OFF + r0 * PSTR + 2 * (lane & 3) * 4);
            #pragma unroll
            for (int nf = 0; nf < 4; nf++) {
                *(float2*)(smem + p0a + nf * 32) =
                    make_float2(sacc[nf][0], sacc[nf][1]);
                *(float2*)(smem + p0a + 8 * PSTR + nf * 32) =
                    make_float2(sacc[nf][2], sacc[nf][3]);
            }
        }
        __syncwarp();

        // ---- O += P @ V ----
        #pragma unroll
        for (int ks = 0; ks < 4; ks++) {
            uint32_t a[4];
            ldsm4(a, Pa + ks * 32);
            #pragma unroll
            for (int db = 0; db < 4; db++) {
                uint32_t bb[4];
                ldsm4(bb, Vb[cur] + db * 16 * PSTR + ks * 32);
                mma8(oacc[2 * db],     a, bb);
                mma8(oacc[2 * db + 1], a, bb + 2);
            }
        }

        if (kt + 1 < 32) CP_WAIT0();
        __syncthreads();   // next tile visible; cur buffers free for reuse
    }

    // ---- epilogue: normalize + store ctx ----
    float inv0 = 1.0f / l0, inv1 = 1.0f / l1;
    float* Og = g_ctx + ((size_t)b * SS + q0) * HH + h * HDD;
    int r0 = 16 * w + (lane >> 2);
    #pragma unroll
    for (int nf = 0; nf < 8; nf++) {
        int c = 8 * nf + 2 * (lane & 3);
        *(float2*)&Og[(size_t)r0 * HH + c] =
            make_float2(oacc[nf][0] * inv0, oacc[nf][1] * inv0);
        *(float2*)&Og[(size_t)(r0 + 8) * HH + c] =
            make_float2(oacc[nf][2] * inv1, oacc[nf][3] * inv1);
    }
}

// ---------------- row LayerNorm ----------------
__global__ void ln_kernel(const float* __restrict__ x,
                          const float* __restrict__ g,
                          const float* __restrict__ bta,
                          float* __restrict__ out)
{
    __shared__ float r1[256];
    __shared__ float r2[256];
    int row = blockIdx.x, tid = threadIdx.x;
    const float4* xr = (const float4*)(x + (size_t)row * HH);
    float4 a = xr[tid];
    float s = a.x + a.y + a.z + a.w;
    float ss = a.x * a.x + a.y * a.y + a.z * a.z + a.w * a.w;
    r1[tid] = s; r2[tid] = ss;
    __syncthreads();
    for (int off = 128; off > 0; off >>= 1) {
        if (tid < off) { r1[tid] += r1[tid + off]; r2[tid] += r2[tid + off]; }
        __syncthreads();
    }
    float mu = r1[0] * (1.0f / HH);
    float var = r2[0] * (1.0f / HH) - mu * mu;
    float rstd = rsqrtf(var + EPS_C);
    float4 gg = ((const float4*)g)[tid];
    float4 bb = ((const float4*)bta)[tid];
    float4 o;
    o.x = (a.x - mu) * rstd * gg.x + bb.x;
    o.y = (a.y - mu) * rstd * gg.y + bb.y;
    o.z = (a.z - mu) * rstd * gg.z + bb.z;
    o.w = (a.w - mu) * rstd * gg.w + bb.w;
    ((float4*)(out + (size_t)row * HH))[tid] = o;
}

// ---------------- launch ----------------
extern "C" void kernel_launch(void* const* d_in, const int* in_sizes, int n_in,
                              void* d_out, int out_size)
{
    const float* query = (const float*)d_in[0];
    const float* key_t = (const float*)d_in[1];
    const float* value = (const float*)d_in[2];
    const float* Wq = (const float*)d_in[3];
    const float* bq = (const float*)d_in[4];
    const float* Wk = (const float*)d_in[5];
    const float* bk = (const float*)d_in[6];
    const float* Wv = (const float*)d_in[7];
    const float* bv = (const float*)d_in[8];
    const float* msb = (const float*)d_in[9];
    const float* Ws1 = (const float*)d_in[10];
    const float* bs1 = (const float*)d_in[11];
    const float* Ws2 = (const float*)d_in[12];
    const float* bs2 = (const float*)d_in[13];
    const float* Wo = (const float*)d_in[14];
    const float* bo = (const float*)d_in[15];
    const float* ln_g = (const float*)d_in[16];
    const float* ln_b = (const float*)d_in[17];

    float *pQ, *pK, *pVT, *pCtx, *pPre, *pWT;
    cudaGetSymbolAddress((void**)&pQ, g_Q);
    cudaGetSymbolAddress((void**)&pK, g_K);
    cudaGetSymbolAddress((void**)&pVT, g_VT);
    cudaGetSymbolAddress((void**)&pCtx, g_ctx);
    cudaGetSymbolAddress((void**)&pPre, g_pre);
    cudaGetSymbolAddress((void**)&pWT, g_WT);

    float* WTq = pWT + 0 * HH * HH;
    float* WTk = pWT + 1 * HH * HH;
    float* WTv = pWT + 2 * HH * HH;
    float* WTo = pWT + 3 * HH * HH;

    cudaFuncSetAttribute(qkv_gemm, cudaFuncAttributeMaxDynamicSharedMemorySize,
                         GSM_TOTAL);
    cudaFuncSetAttribute(o_gemm, cudaFuncAttributeMaxDynamicSharedMemorySize,
                         GSM_TOTAL);
    cudaFuncSetAttribute(attn_mma, cudaFuncAttributeMaxDynamicSharedMemorySize,
                         A_SMEM);

    dim3 tb(32, 8);
    dim3 tg4(32, 32, 4);

    // 0: all 4 weight transposes (+tf32 RNA rounding)
    trans4_kernel<<<tg4, tb>>>(Wq, WTq, Wk, WTk, Wv, WTv, Wo, WTo);
    // 1: query column sums
    qmean_part<<<dim3(32, BB), 256>>>(query);
    // 2: spec layer-1 partials
    spec1_kernel<<<dim3(32, 4, BB), 128>>>(Ws1);
    // 3 (profiled slot): fused Q/K/V projection GEMM (V written transposed)
    qkv_gemm<<<dim3(GN / 128, M_TOT / 128, 3), 256, GSM_TOTAL>>>(
        query, key_t, value, WTq, WTk, WTv, bq, bk, bv, pQ, pK, pVT);
    // 4: spec layer-2
    spec2_kernel<<<dim3(16, BB), 256>>>(bs1, Ws2, bs2);
    // 5: flash attention (Q in registers, pipelined K/V)
    attn_mma<<<dim3(SS / 128, NHH, BB), 256, A_SMEM>>>(msb);
    // 6: output projection + bias + residual
    o_gemm<<<dim3(GN / 128, M_TOT / 128), 256, GSM_TOTAL>>>(pCtx, WTo, bo, query, pPre);
    // 7: LayerNorm -> d_out
    ln_kernel<<<M_TOT, 256>>>(pPre, ln_g, ln_b, (float*)d_out);
}

// round 12
// speedup vs baseline: 1.4641x; 1.0712x over previous
#include <cuda_runtime.h>
#include <cuda_bf16.h>
#include <math.h>
#include <cstdint>

// Problem constants
#define BB 2
#define SS 1024
#define HH 1024
#define NHH 16
#define HDD 64
#define SP_C 0.05f
#define EPS_C 1e-5f
#define SCALE_C 0.125f   // 1/sqrt(64)

#define M_TOT (BB*SS)    // 2048

// ---------------- scratch (device globals: no allocations allowed) ----------
__device__ float g_Q[M_TOT*HH];
__device__ float g_K[M_TOT*HH];
__device__ float g_VT[BB*NHH*HDD*SS];   // V transposed per (b,h): [d][s]
__device__ float g_ctx[M_TOT*HH];
__device__ float g_pre[M_TOT*HH];
__device__ float g_WT[4*HH*HH];      // transposed tf32-rounded weights
__device__ float g_h1p[BB*32*512];   // spec layer-1 partials
__device__ float g_sp[BB*16];        // spec sigmoid-sum partials

// =====================  PTX helpers (mma.sync / cp.async)  ==================
__device__ __forceinline__ uint32_t smem_u32(const void* p) {
    uint32_t a;
    asm("{ .reg .u64 t; cvta.to.shared.u64 t, %1; cvt.u32.u64 %0, t; }"
        : "=r"(a) : "l"(p));
    return a;
}

__device__ __forceinline__ void cp16(uint32_t s, const float* g) {
    asm volatile("cp.async.cg.shared.global [%0], [%1], 16;"
                 :: "r"(s), "l"(__cvta_generic_to_global(g)));
}
#define CP_COMMIT() asm volatile("cp.async.commit_group;" ::: "memory")
#define CP_WAIT0()  asm volatile("cp.async.wait_group 0;" ::: "memory")
#define CP_WAIT1()  asm volatile("cp.async.wait_group 1;" ::: "memory")

__device__ __forceinline__ void ldsm4(uint32_t* r, uint32_t addr) {
    asm volatile("ldmatrix.sync.aligned.m8n8.x4.shared.b16 {%0,%1,%2,%3}, [%4];"
                 : "=r"(r[0]), "=r"(r[1]), "=r"(r[2]), "=r"(r[3]) : "r"(addr));
}
__device__ __forceinline__ float f2tf_f(float x) {
    uint32_t y;
    asm("cvt.rna.tf32.f32 %0, %1;" : "=r"(y) : "f"(x));
    return __uint_as_float(y);
}
__device__ __forceinline__ float tanh_fast(float x) {
    float y;
    asm("tanh.approx.f32 %0, %1;" : "=f"(y) : "f"(x));
    return y;
}
// mma.sync tf32 reads only the top 19 bits of operand registers (HW
// truncation); only weights are pre-rounded (RNA, free in transpose).
__device__ __forceinline__ void mma8(float* d, const uint32_t* a, const uint32_t* b) {
    asm volatile("mma.sync.aligned.m16n8k8.row.col.f32.tf32.tf32.f32 "
                 "{%0,%1,%2,%3}, {%4,%5,%6,%7}, {%8,%9}, {%0,%1,%2,%3};"
                 : "+f"(d[0]), "+f"(d[1]), "+f"(d[2]), "+f"(d[3])
                 : "r"(a[0]), "r"(a[1]), "r"(a[2]), "r"(a[3]),
                   "r"(b[0]), "r"(b[1]));
}

// ======================  mma.sync tf32 GEMM body (2-stage)  =================
#define GK 1024
#define GN 1024
#define BKC 32
#define NKT (GK/BKC)
#define STAGE_B (128*36*4)    // 18432 B per matrix per stage
#define GSM_TOTAL (4*STAGE_B) // 73728 B

// If toVT != nullptr, epilogue writes the per-(b,h)-transposed V layout.
__device__ __forceinline__ void gemm_body(
    char* smem, const float* __restrict__ A, const float* __restrict__ BT,
    const float* __restrict__ bias, const float* __restrict__ res,
    float* __restrict__ C, float* __restrict__ toVT, int bx, int by)
{
    uint32_t sb = smem_u32(smem);
    const int tid = threadIdx.x;
    const int lane = tid & 31;
    const int wid = tid >> 5;
    const int warp_m = wid >> 2;
    const int warp_n = wid & 3;
    const int row0 = by * 128;
    const int col0 = bx * 128;

    const float* Abase = A  + (size_t)row0 * GK;
    const float* Bbase = BT + (size_t)col0 * GK;

    auto load_stage = [&](int stage, int kt) {
        uint32_t as = sb + (stage * 2 + 0) * STAGE_B;
        uint32_t bs = sb + (stage * 2 + 1) * STAGE_B;
        const float* Ak = Abase + kt * BKC;
        const float* Bk = Bbase + kt * BKC;
        #pragma unroll
        for (int i = 0; i < 4; i++) {
            int c = tid + i * 256;
            int r = c >> 3, sg = c & 7;
            cp16(as + (uint32_t)(r * 144 + sg * 16), Ak + (size_t)r * GK + sg * 4);
            cp16(bs + (uint32_t)(r * 144 + sg * 16), Bk + (size_t)r * GK + sg * 4);
        }
        CP_COMMIT();
    };

    uint32_t a_off[4], bp_off[2];
    #pragma unroll
    for (int mf = 0; mf < 4; mf++)
        a_off[mf] = (uint32_t)((warp_m * 64 + mf * 16 + (lane & 15)) * 144
                               + (lane >> 4) * 16);
    #pragma unroll
    for (int p = 0; p < 2; p++)
        bp_off[p] = (uint32_t)((warp_n * 32 + p * 16 + ((lane >> 4) << 3) + (lane & 7)) * 144
                               + ((lane >> 3) & 1) * 16);

    float acc[4][4][4] = {};

    load_stage(0, 0);
    int buf = 0;
    for (int kt = 0; kt < NKT; kt++) {
        if (kt + 1 < NKT) {
            load_stage(buf ^ 1, kt + 1);
            CP_WAIT1();
        } else {
            CP_WAIT0();
        }
        __syncthreads();

        uint32_t as = sb + (buf * 2 + 0) * STAGE_B;
        uint32_t bs = sb + (buf * 2 + 1) * STAGE_B;
        #pragma unroll
        for (int ks = 0; ks < 4; ks++) {
            uint32_t a[4][4], bfr[2][4];
            #pragma unroll
            for (int mf = 0; mf < 4; mf++)
                ldsm4(a[mf], as + a_off[mf] + ks * 32);
            #pragma unroll
            for (int p = 0; p < 2; p++)
                ldsm4(bfr[p], bs + bp_off[p] + ks * 32);
            #pragma unroll
            for (int mf = 0; mf < 4; mf++) {
                mma8(acc[mf][0], a[mf], &bfr[0][0]);
                mma8(acc[mf][1], a[mf], &bfr[0][2]);
                mma8(acc[mf][2], a[mf], &bfr[1][0]);
                mma8(acc[mf][3], a[mf], &bfr[1][2]);
            }
        }
        __syncthreads();
        buf ^= 1;
    }

    #pragma unroll
    for (int nf = 0; nf < 4; nf++) {
        int c = col0 + warp_n * 32 + nf * 8 + 2 * (lane & 3);
        float bx_ = __ldg(bias + c), by_ = __ldg(bias + c + 1);
        #pragma unroll
        for (int mf = 0; mf < 4; mf++) {
            int r = row0 + warp_m * 64 + mf * 16 + (lane >> 2);
            float2 v0 = make_float2(acc[mf][nf][0] + bx_, acc[mf][nf][1] + by_);
            float2 v1 = make_float2(acc[mf][nf][2] + bx_, acc[mf][nf][3] + by_);
            if (res) {
                float2 r0 = *(const float2*)(res + (size_t)r * GN + c);
                float2 r1 = *(const float2*)(res + (size_t)(r + 8) * GN + c);
                v0.x += r0.x; v0.y += r0.y;
                v1.x += r1.x; v1.y += r1.y;
            }
            if (toVT) {
                int b_ = r >> 10, s = r & 1023;
                int h_ = c >> 6, d = c & 63;
                size_t i0 = ((size_t)((b_ * 16 + h_) * 64 + d)) << 10;
                toVT[i0 + s]            = v0.x;
                toVT[i0 + 1024 + s]     = v0.y;
                toVT[i0 + s + 8]        = v1.x;
                toVT[i0 + 1024 + s + 8] = v1.y;
            } else {
                *(float2*)(C + (size_t)r * GN + c) = v0;
                *(float2*)(C + (size_t)(r + 8) * GN + c) = v1;
            }
        }
    }
}

__global__ void __launch_bounds__(256, 2)
qkv_gemm(const float* q, const float* k, const float* v,
         const float* wq, const float* wk, const float* wv,
         const float* bq, const float* bk, const float* bv,
         float* oq, float* ok, float* ovt)
{
    extern __shared__ char smem[];
    int z = blockIdx.z;
    const float* A  = (z == 0) ? q  : (z == 1) ? k  : v;
    const float* BT = (z == 0) ? wq : (z == 1) ? wk : wv;
    const float* bi = (z == 0) ? bq : (z == 1) ? bk : bv;
    float* C        = (z == 0) ? oq : (z == 1) ? ok : nullptr;
    float* VT       = (z == 2) ? ovt : nullptr;
    gemm_body(smem, A, BT, bi, nullptr, C, VT, blockIdx.x, blockIdx.y);
}

__global__ void __launch_bounds__(256, 2)
o_gemm(const float* A, const float* BT, const float* bias,
       const float* res, float* C)
{
    extern __shared__ char smem[];
    gemm_body(smem, A, BT, bias, res, C, nullptr, blockIdx.x, blockIdx.y);
}

// ==== fused pre-pass: weight transposes (+tf32 round) AND spec layer-1 ======
// grid.x in [0,4096): transpose block (z = bx>>10, 32x32 tile index in rest)
// grid.x in [4096,4160): spec1-direct block (b, 32-row chunk); reads query.
__global__ void fused_pre(const float* __restrict__ s0, float* __restrict__ d0,
                          const float* __restrict__ s1, float* __restrict__ d1,
                          const float* __restrict__ s2, float* __restrict__ d2,
                          const float* __restrict__ s3, float* __restrict__ d3,
                          const float* __restrict__ query,
                          const float* __restrict__ Ws1)
{
    __shared__ float t[32][33];
    __shared__ float sin_s[32];
    __shared__ float red[256];
    int bx = blockIdx.x;
    int tid = threadIdx.x;

    if (bx < 4096) {
        int zz = bx >> 10;
        int rem = bx & 1023;
        int txb = rem & 31, tyb = rem >> 5;
        const float* src = (zz == 0) ? s0 : (zz == 1) ? s1 : (zz == 2) ? s2 : s3;
        float* dst       = (zz == 0) ? d0 : (zz == 1) ? d1 : (zz == 2) ? d2 : d3;
        int lx = tid & 31, ly = tid >> 5;
        int x = txb * 32 + lx;
        int y0 = tyb * 32;
        #pragma unroll
        for (int i = ly; i < 32; i += 8)
            t[i][lx] = src[(size_t)(y0 + i) * HH + x];
        __syncthreads();
        int xo = tyb * 32 + lx;
        int yo0 = txb * 32;
        #pragma unroll
        for (int i = ly; i < 32; i += 8)
            dst[(size_t)(yo0 + i) * HH + xo] = f2tf_f(t[lx][i]);
    } else {
        int idx = bx - 4096;          // 0..63
        int b = idx >> 5, ch = idx & 31;
        int r0 = ch * 32;
        // phase 1: column means of query over seq for rows r0..r0+31
        {
            int row = tid >> 3, seg = tid & 7;   // 32 rows x 8 segments
            const float* qp = query + ((size_t)b * SS + seg * 128) * HH + r0 + row;
            float s = 0.f;
            #pragma unroll 4
            for (int j = 0; j < 128; j++) s += qp[(size_t)j * HH];
            red[row * 8 + seg] = s;
        }
        __syncthreads();
        if (tid < 32) {
            float s = 0.f;
            #pragma unroll
            for (int j = 0; j < 8; j++) s += red[tid * 8 + j];
            sin_s[tid] = s * (1.0f / SS);
        }
        __syncthreads();
        // phase 2: partial matvec rows r0..r0+31 of Ws1 [1024,512]
        #pragma unroll
        for (int c = tid; c < 512; c += 256) {
            float acc = 0.f;
            #pragma unroll 4
            for (int j = 0; j < 32; j++)
                acc += sin_s[j] * Ws1[(size_t)(r0 + j) * 512 + c];
            g_h1p[(size_t)(b * 32 + ch) * 512 + c] = acc;
        }
    }
}

// -------- spec layer-2: grid(16 colblocks, BB), 256 thr --------------------
__global__ void spec2_kernel(const float* __restrict__ bs1,
                             const float* __restrict__ Ws2,
                             const float* __restrict__ bs2)
{
    __shared__ float h1[512];
    __shared__ float zp[4][64];
    __shared__ float red[64];
    int b = blockIdx.y, cb = blockIdx.x;
    int tid = threadIdx.x;          // 256
    for (int c = tid; c < 512; c += 256) {
        float s = bs1[c];
        #pragma unroll
        for (int ch = 0; ch < 32; ch++) s += g_h1p[(size_t)(b * 32 + ch) * 512 + c];
        h1[c] = fmaxf(s, 0.f);
    }
    __syncthreads();
    int col = cb * 64 + (tid & 63);
    int qq = tid >> 6;              // 0..3
    float z = 0.f;
    #pragma unroll 4
    for (int i = qq * 128; i < qq * 128 + 128; i++)
        z += h1[i] * Ws2[(size_t)i * HH + col];
    zp[qq][tid & 63] = z;
    __syncthreads();
    if (tid < 64) {
        float zz = bs2[cb * 64 + tid] + zp[0][tid] + zp[1][tid] + zp[2][tid] + zp[3][tid];
        red[tid] = 1.0f / (1.0f + __expf(-zz));
    }
    __syncthreads();
    for (int off = 32; off > 0; off >>= 1) {
        if (tid < off) red[tid] += red[tid + off];
        __syncthreads();
    }
    if (tid == 0) g_sp[b * 16 + cb] = red[0];
}

// ==  flash attention: Q in registers, 32-key tiles, double-buffered K/V  ====
// smem: K0,K1 (32x272B) V0,V1 (64x144B) P (128x144B) = 54272 B
// Q staged through [0, 34816) at prologue only (overlaps K/V buffers).
#define ASTR 272                       // Q-staging / K row stride
#define PSTR 144                       // P / V row stride
#define K0_OFF 0
#define K1_OFF 8704
#define V0_OFF 17408
#define V1_OFF 26624
#define P_OFF  35840
#define A_SMEM 54272

__global__ void __launch_bounds__(256, 2)
attn_mma(const float* __restrict__ msb)
{
    extern __shared__ char smem[];
    __shared__ float red[256];
    __shared__ float mh_s;
    uint32_t sb = smem_u32(smem);
    const int tid = threadIdx.x;
    const int lane = tid & 31;
    const int w = tid >> 5;
    const int b = blockIdx.z, h = blockIdx.y, q0 = blockIdx.x << 7;

    const uint32_t Pa = sb + P_OFF + (uint32_t)((16 * w + (lane & 15)) * PSTR + (lane >> 4) * 16);
    const uint32_t krow = (uint32_t)(((((lane >> 4) << 3) + (lane & 7)) * ASTR) + ((lane >> 3) & 1) * 16);
    const uint32_t vrow = (uint32_t)(((((lane >> 4) << 3) + (lane & 7)) * PSTR) + ((lane >> 3) & 1) * 16);
    const uint32_t Kb[2] = { sb + K0_OFF + krow, sb + K1_OFF + krow };
    const uint32_t Vb[2] = { sb + V0_OFF + vrow, sb + V1_OFF + vrow };
    const uint32_t koff[2] = { K0_OFF, K1_OFF };
    const uint32_t voff[2] = { V0_OFF, V1_OFF };

    const float* Kg0 = g_K + (size_t)b * SS * HH + h * HDD;
    const float* Vg0 = g_VT + (size_t)(b * NHH + h) * HDD * SS;

    auto load_tile = [&](int bufsel, int kt) {
        const float* Kg = Kg0 + (size_t)kt * 32 * HH;
        const float* Vg = Vg0 + kt * 32;
        #pragma unroll
        for (int i = 0; i < 2; i++) {
            int f = tid + i * 256;
            int rk = f >> 4, ck = f & 15;
            cp16(sb + koff[bufsel] + (uint32_t)(rk * ASTR + ck * 16),
                 Kg + (size_t)rk * HH + ck * 4);
            int rv = f >> 3, cv = f & 7;
            cp16(sb + voff[bufsel] + (uint32_t)(rv * PSTR + cv * 16),
                 Vg + (size_t)rv * SS + cv * 4);
        }
        CP_COMMIT();
    };

    // ---- prologue: stage Q into smem[0..34816), msb reduce, Q -> regs ----
    {
        const float* Qg = g_Q + ((size_t)b * SS + q0) * HH + h * HDD;
        #pragma unroll
        for (int i = 0; i < 8; i++) {
            int f = tid + i * 256;
            int r = f >> 4, c4 = f & 15;
            cp16(sb + (uint32_t)(r * ASTR + c4 * 16),
                 Qg + (size_t)r * HH + c4 * 4);
        }
        CP_COMMIT();
    }
    {
        const float* p = msb + (size_t)h * HDD * HDD;
        float s = 0.f;
        for (int i = tid; i < HDD * HDD; i += 256) s += p[i];
        red[tid] = s;
        __syncthreads();
        for (int off = 128; off > 0; off >>= 1) {
            if (tid < off) red[tid] += red[tid + off];
            __syncthreads();
        }
        if (tid == 0) mh_s = red[0] * (1.0f / (HDD * HDD));
    }
    CP_WAIT0();
    __syncthreads();

    uint32_t qf[8][4];
    {
        uint32_t Qa = sb + (uint32_t)((16 * w + (lane & 15)) * ASTR + (lane >> 4) * 16);
        #pragma unroll
        for (int ks = 0; ks < 8; ks++) ldsm4(qf[ks], Qa + ks * 32);
    }
    __syncthreads();            // all warps done reading Q staging
    load_tile(0, 0);

    const float mh = mh_s;
    float sp = 0.f;
    #pragma unroll
    for (int j = 0; j < 16; j++) sp += g_sp[b * 16 + j];
    sp *= (1.0f / HH);

    // folded gate constants: p = s*c1 + (s*c3)*tanh(s*a2)
    const float a2 = 0.5f * SCALE_C * mh;
    const float c1 = SCALE_C * sp * (1.0f + 0.5f * SP_C);
    const float c3 = SCALE_C * sp * (0.5f * SP_C);

    CP_WAIT0();
    __syncthreads();

    float oacc[8][4] = {};
    float m0 = -1e30f, m1 = -1e30f, l0 = 0.f, l1 = 0.f;

    for (int kt = 0; kt < 32; kt++) {
        int cur = kt & 1;
        if (kt + 1 < 32) load_tile(cur ^ 1, kt + 1);   // overlaps compute

        // ---- S = Q @ K^T  (16 q-rows x 32 keys) ----
        float sacc[4][4] = {};
        #pragma unroll
        for (int ks = 0; ks < 8; ks++) {
            #pragma unroll
            for (int kb = 0; kb < 2; kb++) {
                uint32_t bb[4];
                ldsm4(bb, Kb[cur] + kb * 16 * ASTR + ks * 32);
                mma8(sacc[2 * kb],     qf[ks], bb);
                mma8(sacc[2 * kb + 1], qf[ks], bb + 2);
            }
        }

        // ---- gate (tanh-based sigmoid) + online softmax ----
        float tm0 = -1e30f, tm1 = -1e30f;
        #pragma unroll
        for (int nf = 0; nf < 4; nf++) {
            #pragma unroll
            for (int j = 0; j < 4; j++) {
                float s = sacc[nf][j];
                float th = tanh_fast(s * a2);
                float p = fmaf(s * c3, th, s * c1);
                sacc[nf][j] = p;
                if (j < 2) tm0 = fmaxf(tm0, p); else tm1 = fmaxf(tm1, p);
            }
        }
        tm0 = fmaxf(tm0, __shfl_xor_sync(0xffffffff, tm0, 1));
        tm0 = fmaxf(tm0, __shfl_xor_sync(0xffffffff, tm0, 2));
        tm1 = fmaxf(tm1, __shfl_xor_sync(0xffffffff, tm1, 1));
        tm1 = fmaxf(tm1, __shfl_xor_sync(0xffffffff, tm1, 2));

        float nm0 = fmaxf(m0, tm0), nm1 = fmaxf(m1, tm1);
        float sc0 = __expf(m0 - nm0), sc1 = __expf(m1 - nm1);
        float su0 = 0.f, su1 = 0.f;
        #pragma unroll
        for (int nf = 0; nf < 4; nf++) {
            float p0 = __expf(sacc[nf][0] - nm0);
            float p1 = __expf(sacc[nf][1] - nm0);
            float p2 = __expf(sacc[nf][2] - nm1);
            float p3 = __expf(sacc[nf][3] - nm1);
            su0 += p0 + p1; su1 += p2 + p3;
            sacc[nf][0] = p0; sacc[nf][1] = p1;
            sacc[nf][2] = p2; sacc[nf][3] = p3;
        }
        su0 += __shfl_xor_sync(0xffffffff, su0, 1);
        su0 += __shfl_xor_sync(0xffffffff, su0, 2);
        su1 += __shfl_xor_sync(0xffffffff, su1, 1);
        su1 += __shfl_xor_sync(0xffffffff, su1, 2);
        l0 = l0 * sc0 + su0;
        l1 = l1 * sc1 + su1;
        m0 = nm0; m1 = nm1;

        #pragma unroll
        for (int nf = 0; nf < 8; nf++) {
            oacc[nf][0] *= sc0; oacc[nf][1] *= sc0;
            oacc[nf][2] *= sc1; oacc[nf][3] *= sc1;
        }

        // ---- write P to smem (warp-local rows; ldmatrix is warp-sync) ----
        {
            int r0 = 16 * w + (lane >> 2);
            uint32_t p0a = (uint32_t)(P_OFF + r0 * PSTR + 2 * (lane & 3) * 4);
            #pragma unroll
            for (int nf = 0; nf < 4; nf++) {
                *(float2*)(smem + p0a + nf * 32) =
                    make_float2(sacc[nf][0], sacc[nf][1]);
                *(float2*)(smem + p0a + 8 * PSTR + nf * 32) =
                    make_float2(sacc[nf][2], sacc[nf][3]);
            }
        }
        __syncwarp();

        // ---- O += P @ V ----
        #pragma unroll
        for (int ks = 0; ks < 4; ks++) {
            uint32_t a[4];
            ldsm4(a, Pa + ks * 32);
            #pragma unroll
            for (int db = 0; db < 4; db++) {
                uint32_t bb[4];
                ldsm4(bb, Vb[cur] + db * 16 * PSTR + ks * 32);
                mma8(oacc[2 * db],     a, bb);
                mma8(oacc[2 * db + 1], a, bb + 2);
            }
        }

        if (kt + 1 < 32) CP_WAIT0();
        __syncthreads();
    }

    // ---- epilogue: normalize + store ctx ----
    float inv0 = 1.0f / l0, inv1 = 1.0f / l1;
    float* Og = g_ctx + ((size_t)b * SS + q0) * HH + h * HDD;
    int r0 = 16 * w + (lane >> 2);
    #pragma unroll
    for (int nf = 0; nf < 8; nf++) {
        int c = 8 * nf + 2 * (lane & 3);
        *(float2*)&Og[(size_t)r0 * HH + c] =
            make_float2(oacc[nf][0] * inv0, oacc[nf][1] * inv0);
        *(float2*)&Og[(size_t)(r0 + 8) * HH + c] =
            make_float2(oacc[nf][2] * inv1, oacc[nf][3] * inv1);
    }
}

// ---------------- row LayerNorm ----------------
__global__ void ln_kernel(const float* __restrict__ x,
                          const float* __restrict__ g,
                          const float* __restrict__ bta,
                          float* __restrict__ out)
{
    __shared__ float r1[256];
    __shared__ float r2[256];
    int row = blockIdx.x, tid = threadIdx.x;
    const float4* xr = (const float4*)(x + (size_t)row * HH);
    float4 a = xr[tid];
    float s = a.x + a.y + a.z + a.w;
    float ss = a.x * a.x + a.y * a.y + a.z * a.z + a.w * a.w;
    r1[tid] = s; r2[tid] = ss;
    __syncthreads();
    for (int off = 128; off > 0; off >>= 1) {
        if (tid < off) { r1[tid] += r1[tid + off]; r2[tid] += r2[tid + off]; }
        __syncthreads();
    }
    float mu = r1[0] * (1.0f / HH);
    float var = r2[0] * (1.0f / HH) - mu * mu;
    float rstd = rsqrtf(var + EPS_C);
    float4 gg = ((const float4*)g)[tid];
    float4 bb = ((const float4*)bta)[tid];
    float4 o;
    o.x = (a.x - mu) * rstd * gg.x + bb.x;
    o.y = (a.y - mu) * rstd * gg.y + bb.y;
    o.z = (a.z - mu) * rstd * gg.z + bb.z;
    o.w = (a.w - mu) * rstd * gg.w + bb.w;
    ((float4*)(out + (size_t)row * HH))[tid] = o;
}

// ---------------- launch ----------------
extern "C" void kernel_launch(void* const* d_in, const int* in_sizes, int n_in,
                              void* d_out, int out_size)
{
    const float* query = (const float*)d_in[0];
    const float* key_t = (const float*)d_in[1];
    const float* value = (const float*)d_in[2];
    const float* Wq = (const float*)d_in[3];
    const float* bq = (const float*)d_in[4];
    const float* Wk = (const float*)d_in[5];
    const float* bk = (const float*)d_in[6];
    const float* Wv = (const float*)d_in[7];
    const float* bv = (const float*)d_in[8];
    const float* msb = (const float*)d_in[9];
    const float* Ws1 = (const float*)d_in[10];
    const float* bs1 = (const float*)d_in[11];
    const float* Ws2 = (const float*)d_in[12];
    const float* bs2 = (const float*)d_in[13];
    const float* Wo = (const float*)d_in[14];
    const float* bo = (const float*)d_in[15];
    const float* ln_g = (const float*)d_in[16];
    const float* ln_b = (const float*)d_in[17];

    float *pQ, *pK, *pVT, *pCtx, *pPre, *pWT;
    cudaGetSymbolAddress((void**)&pQ, g_Q);
    cudaGetSymbolAddress((void**)&pK, g_K);
    cudaGetSymbolAddress((void**)&pVT, g_VT);
    cudaGetSymbolAddress((void**)&pCtx, g_ctx);
    cudaGetSymbolAddress((void**)&pPre, g_pre);
    cudaGetSymbolAddress((void**)&pWT, g_WT);

    float* WTq = pWT + 0 * HH * HH;
    float* WTk = pWT + 1 * HH * HH;
    float* WTv = pWT + 2 * HH * HH;
    float* WTo = pWT + 3 * HH * HH;

    cudaFuncSetAttribute(qkv_gemm, cudaFuncAttributeMaxDynamicSharedMemorySize,
                         GSM_TOTAL);
    cudaFuncSetAttribute(o_gemm, cudaFuncAttributeMaxDynamicSharedMemorySize,
                         GSM_TOTAL);
    cudaFuncSetAttribute(attn_mma, cudaFuncAttributeMaxDynamicSharedMemorySize,
                         A_SMEM);

    // 0: fused weight transposes + spec layer-1 (reads query directly)
    fused_pre<<<4160, 256>>>(Wq, WTq, Wk, WTk, Wv, WTv, Wo, WTo, query, Ws1);
    // 1: spec layer-2
    spec2_kernel<<<dim3(16, BB), 256>>>(bs1, Ws2, bs2);
    // 2: fused Q/K/V projection GEMM (V written transposed)
    qkv_gemm<<<dim3(GN / 128, M_TOT / 128, 3), 256, GSM_TOTAL>>>(
        query, key_t, value, WTq, WTk, WTv, bq, bk, bv, pQ, pK, pVT);
    // 3 (profiled slot): flash attention
    attn_mma<<<dim3(SS / 128, NHH, BB), 256, A_SMEM>>>(msb);
    // 4: output projection + bias + residual
    o_gemm<<<dim3(GN / 128, M_TOT / 128), 256, GSM_TOTAL>>>(pCtx, WTo, bo, query, pPre);
    // 5: LayerNorm -> d_out
    ln_kernel<<<M_TOT, 256>>>(pPre, ln_g, ln_b, (float*)d_out);
}

// round 14
// speedup vs baseline: 1.5338x; 1.0476x over previous
#include <cuda_runtime.h>
#include <cuda_bf16.h>
#include <cuda_fp16.h>
#include <math.h>
#include <cstdint>

// Problem constants
#define BB 2
#define SS 1024
#define HH 1024
#define NHH 16
#define HDD 64
#define SP_C 0.05f
#define EPS_C 1e-5f
#define SCALE_C 0.125f   // 1/sqrt(64)

#define M_TOT (BB*SS)    // 2048

// ---------------- scratch (device globals: no allocations allowed) ----------
__device__ float g_Q[M_TOT*HH];
__device__ float g_K[M_TOT*HH];
__device__ __half g_VTh[BB*NHH*HDD*SS];  // V transposed per (b,h): [d][s], f16
__device__ float g_ctx[M_TOT*HH];
__device__ float g_pre[M_TOT*HH];
__device__ float g_WT[4*HH*HH];      // transposed tf32-rounded weights
__device__ float g_h1p[BB*32*512];   // spec layer-1 partials
__device__ float g_sp[BB*16];        // spec sigmoid-sum partials

// =====================  PTX helpers (mma.sync / cp.async)  ==================
__device__ __forceinline__ uint32_t smem_u32(const void* p) {
    uint32_t a;
    asm("{ .reg .u64 t; cvta.to.shared.u64 t, %1; cvt.u32.u64 %0, t; }"
        : "=r"(a) : "l"(p));
    return a;
}

__device__ __forceinline__ void cp16(uint32_t s, const void* g) {
    asm volatile("cp.async.cg.shared.global [%0], [%1], 16;"
                 :: "r"(s), "l"(__cvta_generic_to_global(g)));
}
#define CP_COMMIT() asm volatile("cp.async.commit_group;" ::: "memory")
#define CP_WAIT0()  asm volatile("cp.async.wait_group 0;" ::: "memory")
#define CP_WAIT1()  asm volatile("cp.async.wait_group 1;" ::: "memory")

__device__ __forceinline__ void ldsm4(uint32_t* r, uint32_t addr) {
    asm volatile("ldmatrix.sync.aligned.m8n8.x4.shared.b16 {%0,%1,%2,%3}, [%4];"
                 : "=r"(r[0]), "=r"(r[1]), "=r"(r[2]), "=r"(r[3]) : "r"(addr));
}
__device__ __forceinline__ float f2tf_f(float x) {
    uint32_t y;
    asm("cvt.rna.tf32.f32 %0, %1;" : "=r"(y) : "f"(x));
    return __uint_as_float(y);
}
__device__ __forceinline__ float tanh_fast(float x) {
    float y;
    asm("tanh.approx.f32 %0, %1;" : "=f"(y) : "f"(x));
    return y;
}
__device__ __forceinline__ uint32_t pack_h2(float lo, float hi) {
    uint32_t r;
    asm("cvt.rn.f16x2.f32 %0, %1, %2;" : "=r"(r) : "f"(hi), "f"(lo));
    return r;
}
// mma.sync tf32 reads only the top 19 bits of operand registers (HW
// truncation); only weights are pre-rounded (RNA, free in transpose).
__device__ __forceinline__ void mma8(float* d, const uint32_t* a, const uint32_t* b) {
    asm volatile("mma.sync.aligned.m16n8k8.row.col.f32.tf32.tf32.f32 "
                 "{%0,%1,%2,%3}, {%4,%5,%6,%7}, {%8,%9}, {%0,%1,%2,%3};"
                 : "+f"(d[0]), "+f"(d[1]), "+f"(d[2]), "+f"(d[3])
                 : "r"(a[0]), "r"(a[1]), "r"(a[2]), "r"(a[3]),
                   "r"(b[0]), "r"(b[1]));
}
__device__ __forceinline__ void mma16f(float* d, const uint32_t* a, const uint32_t* b) {
    asm volatile("mma.sync.aligned.m16n8k16.row.col.f32.f16.f16.f32 "
                 "{%0,%1,%2,%3}, {%4,%5,%6,%7}, {%8,%9}, {%0,%1,%2,%3};"
                 : "+f"(d[0]), "+f"(d[1]), "+f"(d[2]), "+f"(d[3])
                 : "r"(a[0]), "r"(a[1]), "r"(a[2]), "r"(a[3]),
                   "r"(b[0]), "r"(b[1]));
}

// ======================  mma.sync tf32 GEMM body (2-stage)  =================
#define GK 1024
#define GN 1024
#define BKC 32
#define NKT (GK/BKC)
#define STAGE_B (128*36*4)    // 18432 B per matrix per stage
#define GSM_TOTAL (4*STAGE_B) // 73728 B

// If toVT != nullptr, epilogue writes the per-(b,h)-transposed f16 V layout.
__device__ __forceinline__ void gemm_body(
    char* smem, const float* __restrict__ A, const float* __restrict__ BT,
    const float* __restrict__ bias, const float* __restrict__ res,
    float* __restrict__ C, __half* __restrict__ toVT, int bx, int by)
{
    uint32_t sb = smem_u32(smem);
    const int tid = threadIdx.x;
    const int lane = tid & 31;
    const int wid = tid >> 5;
    const int warp_m = wid >> 2;
    const int warp_n = wid & 3;
    const int row0 = by * 128;
    const int col0 = bx * 128;

    const float* Abase = A  + (size_t)row0 * GK;
    const float* Bbase = BT + (size_t)col0 * GK;

    auto load_stage = [&](int stage, int kt) {
        uint32_t as = sb + (stage * 2 + 0) * STAGE_B;
        uint32_t bs = sb + (stage * 2 + 1) * STAGE_B;
        const float* Ak = Abase + kt * BKC;
        const float* Bk = Bbase + kt * BKC;
        #pragma unroll
        for (int i = 0; i < 4; i++) {
            int c = tid + i * 256;
            int r = c >> 3, sg = c & 7;
            cp16(as + (uint32_t)(r * 144 + sg * 16), Ak + (size_t)r * GK + sg * 4);
            cp16(bs + (uint32_t)(r * 144 + sg * 16), Bk + (size_t)r * GK + sg * 4);
        }
        CP_COMMIT();
    };

    uint32_t a_off[4], bp_off[2];
    #pragma unroll
    for (int mf = 0; mf < 4; mf++)
        a_off[mf] = (uint32_t)((warp_m * 64 + mf * 16 + (lane & 15)) * 144
                               + (lane >> 4) * 16);
    #pragma unroll
    for (int p = 0; p < 2; p++)
        bp_off[p] = (uint32_t)((warp_n * 32 + p * 16 + ((lane >> 4) << 3) + (lane & 7)) * 144
                               + ((lane >> 3) & 1) * 16);

    float acc[4][4][4] = {};

    load_stage(0, 0);
    int buf = 0;
    for (int kt = 0; kt < NKT; kt++) {
        if (kt + 1 < NKT) {
            load_stage(buf ^ 1, kt + 1);
            CP_WAIT1();
        } else {
            CP_WAIT0();
        }
        __syncthreads();

        uint32_t as = sb + (buf * 2 + 0) * STAGE_B;
        uint32_t bs = sb + (buf * 2 + 1) * STAGE_B;
        #pragma unroll
        for (int ks = 0; ks < 4; ks++) {
            uint32_t a[4][4], bfr[2][4];
            #pragma unroll
            for (int mf = 0; mf < 4; mf++)
                ldsm4(a[mf], as + a_off[mf] + ks * 32);
            #pragma unroll
            for (int p = 0; p < 2; p++)
                ldsm4(bfr[p], bs + bp_off[p] + ks * 32);
            #pragma unroll
            for (int mf = 0; mf < 4; mf++) {
                mma8(acc[mf][0], a[mf], &bfr[0][0]);
                mma8(acc[mf][1], a[mf], &bfr[0][2]);
                mma8(acc[mf][2], a[mf], &bfr[1][0]);
                mma8(acc[mf][3], a[mf], &bfr[1][2]);
            }
        }
        __syncthreads();
        buf ^= 1;
    }

    #pragma unroll
    for (int nf = 0; nf < 4; nf++) {
        int c = col0 + warp_n * 32 + nf * 8 + 2 * (lane & 3);
        float bx_ = __ldg(bias + c), by_ = __ldg(bias + c + 1);
        #pragma unroll
        for (int mf = 0; mf < 4; mf++) {
            int r = row0 + warp_m * 64 + mf * 16 + (lane >> 2);
            float2 v0 = make_float2(acc[mf][nf][0] + bx_, acc[mf][nf][1] + by_);
            float2 v1 = make_float2(acc[mf][nf][2] + bx_, acc[mf][nf][3] + by_);
            if (res) {
                float2 r0 = *(const float2*)(res + (size_t)r * GN + c);
                float2 r1 = *(const float2*)(res + (size_t)(r + 8) * GN + c);
                v0.x += r0.x; v0.y += r0.y;
                v1.x += r1.x; v1.y += r1.y;
            }
            if (toVT) {
                int b_ = r >> 10, s = r & 1023;
                int h_ = c >> 6, d = c & 63;
                size_t i0 = ((size_t)((b_ * 16 + h_) * 64 + d)) << 10;
                toVT[i0 + s]            = __float2half(v0.x);
                toVT[i0 + 1024 + s]     = __float2half(v0.y);
                toVT[i0 + s + 8]        = __float2half(v1.x);
                toVT[i0 + 1024 + s + 8] = __float2half(v1.y);
            } else {
                *(float2*)(C + (size_t)r * GN + c) = v0;
                *(float2*)(C + (size_t)(r + 8) * GN + c) = v1;
            }
        }
    }
}

__global__ void __launch_bounds__(256, 2)
qkv_gemm(const float* q, const float* k, const float* v,
         const float* wq, const float* wk, const float* wv,
         const float* bq, const float* bk, const float* bv,
         float* oq, float* ok, __half* ovt)
{
    extern __shared__ char smem[];
    int z = blockIdx.z;
    const float* A  = (z == 0) ? q  : (z == 1) ? k  : v;
    const float* BT = (z == 0) ? wq : (z == 1) ? wk : wv;
    const float* bi = (z == 0) ? bq : (z == 1) ? bk : bv;
    float* C        = (z == 0) ? oq : (z == 1) ? ok : nullptr;
    __half* VT      = (z == 2) ? ovt : nullptr;
    gemm_body(smem, A, BT, bi, nullptr, C, VT, blockIdx.x, blockIdx.y);
}

__global__ void __launch_bounds__(256, 2)
o_gemm(const float* A, const float* BT, const float* bias,
       const float* res, float* C)
{
    extern __shared__ char smem[];
    gemm_body(smem, A, BT, bias, res, C, nullptr, blockIdx.x, blockIdx.y);
}

// ==== fused pre-pass: weight transposes (+tf32 round) AND spec layer-1 ======
__global__ void fused_pre(const float* __restrict__ s0, float* __restrict__ d0,
                          const float* __restrict__ s1, float* __restrict__ d1,
                          const float* __restrict__ s2, float* __restrict__ d2,
                          const float* __restrict__ s3, float* __restrict__ d3,
                          const float* __restrict__ query,
                          const float* __restrict__ Ws1)
{
    __shared__ float t[32][33];
    __shared__ float sin_s[32];
    __shared__ float red[256];
    int bx = blockIdx.x;
    int tid = threadIdx.x;

    if (bx < 4096) {
        int zz = bx >> 10;
        int rem = bx & 1023;
        int txb = rem & 31, tyb = rem >> 5;
        const float* src = (zz == 0) ? s0 : (zz == 1) ? s1 : (zz == 2) ? s2 : s3;
        float* dst       = (zz == 0) ? d0 : (zz == 1) ? d1 : (zz == 2) ? d2 : d3;
        int lx = tid & 31, ly = tid >> 5;
        int x = txb * 32 + lx;
        int y0 = tyb * 32;
        #pragma unroll
        for (int i = ly; i < 32; i += 8)
            t[i][lx] = src[(size_t)(y0 + i) * HH + x];
        __syncthreads();
        int xo = tyb * 32 + lx;
        int yo0 = txb * 32;
        #pragma unroll
        for (int i = ly; i < 32; i += 8)
            dst[(size_t)(yo0 + i) * HH + xo] = f2tf_f(t[lx][i]);
    } else {
        int idx = bx - 4096;          // 0..63
        int b = idx >> 5, ch = idx & 31;
        int r0 = ch * 32;
        {
            int row = tid >> 3, seg = tid & 7;
            const float* qp = query + ((size_t)b * SS + seg * 128) * HH + r0 + row;
            float s = 0.f;
            #pragma unroll 4
            for (int j = 0; j < 128; j++) s += qp[(size_t)j * HH];
            red[row * 8 + seg] = s;
        }
        __syncthreads();
        if (tid < 32) {
            float s = 0.f;
            #pragma unroll
            for (int j = 0; j < 8; j++) s += red[tid * 8 + j];
            sin_s[tid] = s * (1.0f / SS);
        }
        __syncthreads();
        #pragma unroll
        for (int c = tid; c < 512; c += 256) {
            float acc = 0.f;
            #pragma unroll 4
            for (int j = 0; j < 32; j++)
                acc += sin_s[j] * Ws1[(size_t)(r0 + j) * 512 + c];
            g_h1p[(size_t)(b * 32 + ch) * 512 + c] = acc;
        }
    }
}

// -------- spec layer-2: grid(16 colblocks, BB), 256 thr --------------------
__global__ void spec2_kernel(const float* __restrict__ bs1,
                             const float* __restrict__ Ws2,
                             const float* __restrict__ bs2)
{
    __shared__ float h1[512];
    __shared__ float zp[4][64];
    __shared__ float red[64];
    int b = blockIdx.y, cb = blockIdx.x;
    int tid = threadIdx.x;
    for (int c = tid; c < 512; c += 256) {
        float s = bs1[c];
        #pragma unroll
        for (int ch = 0; ch < 32; ch++) s += g_h1p[(size_t)(b * 32 + ch) * 512 + c];
        h1[c] = fmaxf(s, 0.f);
    }
    __syncthreads();
    int col = cb * 64 + (tid & 63);
    int qq = tid >> 6;
    float z = 0.f;
    #pragma unroll 4
    for (int i = qq * 128; i < qq * 128 + 128; i++)
        z += h1[i] * Ws2[(size_t)i * HH + col];
    zp[qq][tid & 63] = z;
    __syncthreads();
    if (tid < 64) {
        float zz = bs2[cb * 64 + tid] + zp[0][tid] + zp[1][tid] + zp[2][tid] + zp[3][tid];
        red[tid] = 1.0f / (1.0f + __expf(-zz));
    }
    __syncthreads();
    for (int off = 32; off > 0; off >>= 1) {
        if (tid < off) red[tid] += red[tid + off];
        __syncthreads();
    }
    if (tid == 0) g_sp[b * 16 + cb] = red[0];
}

// ==  flash attention: tf32 QK^T + f16 PV; Q in regs; 32-key double-buffer ===
// smem: K0,K1 (32x272B f32) V0,V1 (64x80B f16) P (128x80B f16) = 37888 B
// HSTR=80 B: multiple of 16 (cp.async/ldsm aligned); stride 20 words ->
// 8-row ldmatrix phase words {0,20,8,28,16,4,24,12} mod 32 cover all banks.
#define ASTR 272                       // Q-staging / K row stride (f32)
#define HSTR 80                        // P / V row stride (f16)
#define K0_OFF 0
#define K1_OFF 8704
#define V0_OFF 17408
#define V1_OFF 22528
#define P_OFF  27648
#define A_SMEM 37888

__global__ void __launch_bounds__(256, 2)
attn_mma(const float* __restrict__ msb)
{
    extern __shared__ char smem[];
    __shared__ float red[256];
    __shared__ float mh_s;
    uint32_t sb = smem_u32(smem);
    const int tid = threadIdx.x;
    const int lane = tid & 31;
    const int w = tid >> 5;
    const int b = blockIdx.z, h = blockIdx.y, q0 = blockIdx.x << 7;

    // P A-fragment ldsm address (m16k16 f16): row = 16w + (lane&15), col-half (lane>>4)
    const uint32_t Pa = sb + P_OFF + (uint32_t)((16 * w + (lane & 15)) * HSTR + (lane >> 4) * 16);
    const uint32_t krow = (uint32_t)(((((lane >> 4) << 3) + (lane & 7)) * ASTR) + ((lane >> 3) & 1) * 16);
    const uint32_t vrow = (uint32_t)(((((lane >> 4) << 3) + (lane & 7)) * HSTR) + ((lane >> 3) & 1) * 16);
    const uint32_t Kb[2] = { sb + K0_OFF + krow, sb + K1_OFF + krow };
    const uint32_t Vb[2] = { sb + V0_OFF + vrow, sb + V1_OFF + vrow };
    const uint32_t koff[2] = { K0_OFF, K1_OFF };
    const uint32_t voff[2] = { V0_OFF, V1_OFF };

    const float* Kg0 = g_K + (size_t)b * SS * HH + h * HDD;
    const __half* Vg0 = g_VTh + (size_t)(b * NHH + h) * HDD * SS;

    // K: 32 rows x 64 f32 (2 cp16/thread); V: 64 rows x 32 f16 (1 cp16/thread)
    auto load_tile = [&](int bufsel, int kt) {
        const float* Kg = Kg0 + (size_t)kt * 32 * HH;
        const __half* Vg = Vg0 + kt * 32;
        #pragma unroll
        for (int i = 0; i < 2; i++) {
            int f = tid + i * 256;
            int rk = f >> 4, ck = f & 15;
            cp16(sb + koff[bufsel] + (uint32_t)(rk * ASTR + ck * 16),
                 Kg + (size_t)rk * HH + ck * 4);
        }
        {
            int rv = tid >> 2, cv = tid & 3;
            cp16(sb + voff[bufsel] + (uint32_t)(rv * HSTR + cv * 16),
                 Vg + (size_t)rv * SS + cv * 8);
        }
        CP_COMMIT();
    };

    // ---- prologue: stage Q into smem[0..34816), msb reduce, Q -> regs ----
    {
        const float* Qg = g_Q + ((size_t)b * SS + q0) * HH + h * HDD;
        #pragma unroll
        for (int i = 0; i < 8; i++) {
            int f = tid + i * 256;
            int r = f >> 4, c4 = f & 15;
            cp16(sb + (uint32_t)(r * ASTR + c4 * 16),
                 Qg + (size_t)r * HH + c4 * 4);
        }
        CP_COMMIT();
    }
    {
        const float* p = msb + (size_t)h * HDD * HDD;
        float s = 0.f;
        for (int i = tid; i < HDD * HDD; i += 256) s += p[i];
        red[tid] = s;
        __syncthreads();
        for (int off = 128; off > 0; off >>= 1) {
            if (tid < off) red[tid] += red[tid + off];
            __syncthreads();
        }
        if (tid == 0) mh_s = red[0] * (1.0f / (HDD * HDD));
    }
    CP_WAIT0();
    __syncthreads();

    uint32_t qf[8][4];
    {
        uint32_t Qa = sb + (uint32_t)((16 * w + (lane & 15)) * ASTR + (lane >> 4) * 16);
        #pragma unroll
        for (int ks = 0; ks < 8; ks++) ldsm4(qf[ks], Qa + ks * 32);
    }
    __syncthreads();            // all warps done reading Q staging
    load_tile(0, 0);

    const float mh = mh_s;
    float sp = 0.f;
    #pragma unroll
    for (int j = 0; j < 16; j++) sp += g_sp[b * 16 + j];
    sp *= (1.0f / HH);

    // folded gate constants: p = s*c1 + (s*c3)*tanh(s*a2)
    const float a2 = 0.5f * SCALE_C * mh;
    const float c1 = SCALE_C * sp * (1.0f + 0.5f * SP_C);
    const float c3 = SCALE_C * sp * (0.5f * SP_C);

    CP_WAIT0();
    __syncthreads();

    float oacc[8][4] = {};
    float m0 = -1e30f, m1 = -1e30f, l0 = 0.f, l1 = 0.f;

    for (int kt = 0; kt < 32; kt++) {
        int cur = kt & 1;
        if (kt + 1 < 32) load_tile(cur ^ 1, kt + 1);   // overlaps compute

        // ---- S = Q @ K^T  (tf32, 16 q-rows x 32 keys) ----
        float sacc[4][4] = {};
        #pragma unroll
        for (int ks = 0; ks < 8; ks++) {
            #pragma unroll
            for (int kb = 0; kb < 2; kb++) {
                uint32_t bb[4];
                ldsm4(bb, Kb[cur] + kb * 16 * ASTR + ks * 32);
                mma8(sacc[2 * kb],     qf[ks], bb);
                mma8(sacc[2 * kb + 1], qf[ks], bb + 2);
            }
        }

        // ---- gate (tanh-based sigmoid) + online softmax ----
        float tm0 = -1e30f, tm1 = -1e30f;
        #pragma unroll
        for (int nf = 0; nf < 4; nf++) {
            #pragma unroll
            for (int j = 0; j < 4; j++) {
                float s = sacc[nf][j];
                float th = tanh_fast(s * a2);
                float p = fmaf(s * c3, th, s * c1);
                sacc[nf][j] = p;
                if (j < 2) tm0 = fmaxf(tm0, p); else tm1 = fmaxf(tm1, p);
            }
        }
        tm0 = fmaxf(tm0, __shfl_xor_sync(0xffffffff, tm0, 1));
        tm0 = fmaxf(tm0, __shfl_xor_sync(0xffffffff, tm0, 2));
        tm1 = fmaxf(tm1, __shfl_xor_sync(0xffffffff, tm1, 1));
        tm1 = fmaxf(tm1, __shfl_xor_sync(0xffffffff, tm1, 2));

        float nm0 = fmaxf(m0, tm0), nm1 = fmaxf(m1, tm1);
        float sc0 = __expf(m0 - nm0), sc1 = __expf(m1 - nm1);
        float su0 = 0.f, su1 = 0.f;
        #pragma unroll
        for (int nf = 0; nf < 4; nf++) {
            float p0 = __expf(sacc[nf][0] - nm0);
            float p1 = __expf(sacc[nf][1] - nm0);
            float p2 = __expf(sacc[nf][2] - nm1);
            float p3 = __expf(sacc[nf][3] - nm1);
            su0 += p0 + p1; su1 += p2 + p3;
            sacc[nf][0] = p0; sacc[nf][1] = p1;
            sacc[nf][2] = p2; sacc[nf][3] = p3;
        }
        su0 += __shfl_xor_sync(0xffffffff, su0, 1);
        su0 += __shfl_xor_sync(0xffffffff, su0, 2);
        su1 += __shfl_xor_sync(0xffffffff, su1, 1);
        su1 += __shfl_xor_sync(0xffffffff, su1, 2);
        l0 = l0 * sc0 + su0;
        l1 = l1 * sc1 + su1;
        m0 = nm0; m1 = nm1;

        #pragma unroll
        for (int nf = 0; nf < 8; nf++) {
            oacc[nf][0] *= sc0; oacc[nf][1] *= sc0;
            oacc[nf][2] *= sc1; oacc[nf][3] *= sc1;
        }

        // ---- write P as packed f16 (warp-local rows; ldmatrix warp-sync) --
        {
            int r0 = 16 * w + (lane >> 2);
            uint32_t p0a = (uint32_t)(P_OFF + r0 * HSTR + (lane & 3) * 4);
            #pragma unroll
            for (int nf = 0; nf < 4; nf++) {
                *(uint32_t*)(smem + p0a + nf * 16) =
                    pack_h2(sacc[nf][0], sacc[nf][1]);
                *(uint32_t*)(smem + p0a + 8 * HSTR + nf * 16) =
                    pack_h2(sacc[nf][2], sacc[nf][3]);
            }
        }
        __syncwarp();

        // ---- O += P @ V  (f16 mma, k16) ----
        #pragma unroll
        for (int kb = 0; kb < 2; kb++) {
            uint32_t a[4];
            ldsm4(a, Pa + kb * 32);
            #pragma unroll
            for (int db = 0; db < 4; db++) {
                uint32_t bb[4];
                ldsm4(bb, Vb[cur] + db * 16 * HSTR + kb * 32);
                mma16f(oacc[2 * db],     a, bb);
                mma16f(oacc[2 * db + 1], a, bb + 2);
            }
        }

        if (kt + 1 < 32) CP_WAIT0();
        __syncthreads();
    }

    // ---- epilogue: normalize + store ctx ----
    float inv0 = 1.0f / l0, inv1 = 1.0f / l1;
    float* Og = g_ctx + ((size_t)b * SS + q0) * HH + h * HDD;
    int r0 = 16 * w + (lane >> 2);
    #pragma unroll
    for (int nf = 0; nf < 8; nf++) {
        int c = 8 * nf + 2 * (lane & 3);
        *(float2*)&Og[(size_t)r0 * HH + c] =
            make_float2(oacc[nf][0] * inv0, oacc[nf][1] * inv0);
        *(float2*)&Og[(size_t)(r0 + 8) * HH + c] =
            make_float2(oacc[nf][2] * inv1, oacc[nf][3] * inv1);
    }
}

// ---------------- row LayerNorm ----------------
__global__ void ln_kernel(const float* __restrict__ x,
                          const float* __restrict__ g,
                          const float* __restrict__ bta,
                          float* __restrict__ out)
{
    __shared__ float r1[256];
    __shared__ float r2[256];
    int row = blockIdx.x, tid = threadIdx.x;
    const float4* xr = (const float4*)(x + (size_t)row * HH);
    float4 a = xr[tid];
    float s = a.x + a.y + a.z + a.w;
    float ss = a.x * a.x + a.y * a.y + a.z * a.z + a.w * a.w;
    r1[tid] = s; r2[tid] = ss;
    __syncthreads();
    for (int off = 128; off > 0; off >>= 1) {
        if (tid < off) { r1[tid] += r1[tid + off]; r2[tid] += r2[tid + off]; }
        __syncthreads();
    }
    float mu = r1[0] * (1.0f / HH);
    float var = r2[0] * (1.0f / HH) - mu * mu;
    float rstd = rsqrtf(var + EPS_C);
    float4 gg = ((const float4*)g)[tid];
    float4 bb = ((const float4*)bta)[tid];
    float4 o;
    o.x = (a.x - mu) * rstd * gg.x + bb.x;
    o.y = (a.y - mu) * rstd * gg.y + bb.y;
    o.z = (a.z - mu) * rstd * gg.z + bb.z;
    o.w = (a.w - mu) * rstd * gg.w + bb.w;
    ((float4*)(out + (size_t)row * HH))[tid] = o;
}

// ---------------- launch ----------------
extern "C" void kernel_launch(void* const* d_in, const int* in_sizes, int n_in,
                              void* d_out, int out_size)
{
    const float* query = (const float*)d_in[0];
    const float* key_t = (const float*)d_in[1];
    const float* value = (const float*)d_in[2];
    const float* Wq = (const float*)d_in[3];
    const float* bq = (const float*)d_in[4];
    const float* Wk = (const float*)d_in[5];
    const float* bk = (const float*)d_in[6];
    const float* Wv = (const float*)d_in[7];
    const float* bv = (const float*)d_in[8];
    const float* msb = (const float*)d_in[9];
    const float* Ws1 = (const float*)d_in[10];
    const float* bs1 = (const float*)d_in[11];
    const float* Ws2 = (const float*)d_in[12];
    const float* bs2 = (const float*)d_in[13];
    const float* Wo = (const float*)d_in[14];
    const float* bo = (const float*)d_in[15];
    const float* ln_g = (const float*)d_in[16];
    const float* ln_b = (const float*)d_in[17];

    float *pQ, *pK, *pCtx, *pPre, *pWT;
    __half* pVTh;
    cudaGetSymbolAddress((void**)&pQ, g_Q);
    cudaGetSymbolAddress((void**)&pK, g_K);
    cudaGetSymbolAddress((void**)&pVTh, g_VTh);
    cudaGetSymbolAddress((void**)&pCtx, g_ctx);
    cudaGetSymbolAddress((void**)&pPre, g_pre);
    cudaGetSymbolAddress((void**)&pWT, g_WT);

    float* WTq = pWT + 0 * HH * HH;
    float* WTk = pWT + 1 * HH * HH;
    float* WTv = pWT + 2 * HH * HH;
    float* WTo = pWT + 3 * HH * HH;

    cudaFuncSetAttribute(qkv_gemm, cudaFuncAttributeMaxDynamicSharedMemorySize,
                         GSM_TOTAL);
    cudaFuncSetAttribute(o_gemm, cudaFuncAttributeMaxDynamicSharedMemorySize,
                         GSM_TOTAL);
    cudaFuncSetAttribute(attn_mma, cudaFuncAttributeMaxDynamicSharedMemorySize,
                         A_SMEM);

    // 0: fused weight transposes + spec layer-1 (reads query directly)
    fused_pre<<<4160, 256>>>(Wq, WTq, Wk, WTk, Wv, WTv, Wo, WTo, query, Ws1);
    // 1: spec layer-2
    spec2_kernel<<<dim3(16, BB), 256>>>(bs1, Ws2, bs2);
    // 2: fused Q/K/V projection GEMM (V written transposed as f16)
    qkv_gemm<<<dim3(GN / 128, M_TOT / 128, 3), 256, GSM_TOTAL>>>(
        query, key_t, value, WTq, WTk, WTv, bq, bk, bv, pQ, pK, pVTh);
    // 3 (profiled slot): flash attention (tf32 QK^T, f16 PV)
    attn_mma<<<dim3(SS / 128, NHH, BB), 256, A_SMEM>>>(msb);
    // 4: output projection + bias + residual
    o_gemm<<<dim3(GN / 128, M_TOT / 128), 256, GSM_TOTAL>>>(pCtx, WTo, bo, query, pPre);
    // 5: LayerNorm -> d_out
    ln_kernel<<<M_TOT, 256>>>(pPre, ln_g, ln_b, (float*)d_out);
}

// round 15
// speedup vs baseline: 1.5915x; 1.0376x over previous
#include <cuda_runtime.h>
#include <cuda_bf16.h>
#include <cuda_fp16.h>
#include <math.h>
#include <cstdint>

// Problem constants
#define BB 2
#define SS 1024
#define HH 1024
#define NHH 16
#define HDD 64
#define SP_C 0.05f
#define EPS_C 1e-5f
#define SCALE_C 0.125f   // 1/sqrt(64)

#define M_TOT (BB*SS)    // 2048

// ---------------- scratch (device globals: no allocations allowed) ----------
__device__ __half g_Qh[M_TOT*HH];       // Q projection, f16
__device__ __half g_Kh[M_TOT*HH];       // K projection, f16
__device__ __half g_VTh[BB*NHH*HDD*SS]; // V transposed per (b,h): [d][s], f16
__device__ float g_ctx[M_TOT*HH];
__device__ float g_pre[M_TOT*HH];
__device__ float g_WT[4*HH*HH];      // transposed tf32-rounded weights
__device__ float g_h1p[BB*32*512];   // spec layer-1 partials
__device__ float g_sp[BB*16];        // spec sigmoid-sum partials

// =====================  PTX helpers (mma.sync / cp.async)  ==================
__device__ __forceinline__ uint32_t smem_u32(const void* p) {
    uint32_t a;
    asm("{ .reg .u64 t; cvta.to.shared.u64 t, %1; cvt.u32.u64 %0, t; }"
        : "=r"(a) : "l"(p));
    return a;
}

__device__ __forceinline__ void cp16(uint32_t s, const void* g) {
    asm volatile("cp.async.cg.shared.global [%0], [%1], 16;"
                 :: "r"(s), "l"(__cvta_generic_to_global(g)));
}
#define CP_COMMIT() asm volatile("cp.async.commit_group;" ::: "memory")
#define CP_WAIT0()  asm volatile("cp.async.wait_group 0;" ::: "memory")
#define CP_WAIT1()  asm volatile("cp.async.wait_group 1;" ::: "memory")

__device__ __forceinline__ void ldsm4(uint32_t* r, uint32_t addr) {
    asm volatile("ldmatrix.sync.aligned.m8n8.x4.shared.b16 {%0,%1,%2,%3}, [%4];"
                 : "=r"(r[0]), "=r"(r[1]), "=r"(r[2]), "=r"(r[3]) : "r"(addr));
}
__device__ __forceinline__ float f2tf_f(float x) {
    uint32_t y;
    asm("cvt.rna.tf32.f32 %0, %1;" : "=r"(y) : "f"(x));
    return __uint_as_float(y);
}
__device__ __forceinline__ float tanh_fast(float x) {
    float y;
    asm("tanh.approx.f32 %0, %1;" : "=f"(y) : "f"(x));
    return y;
}
__device__ __forceinline__ uint32_t pack_h2(float lo, float hi) {
    uint32_t r;
    asm("cvt.rn.f16x2.f32 %0, %1, %2;" : "=r"(r) : "f"(hi), "f"(lo));
    return r;
}
// mma.sync tf32 reads only the top 19 bits of operand registers (HW
// truncation); only weights are pre-rounded (RNA, free in transpose).
__device__ __forceinline__ void mma8(float* d, const uint32_t* a, const uint32_t* b) {
    asm volatile("mma.sync.aligned.m16n8k8.row.col.f32.tf32.tf32.f32 "
                 "{%0,%1,%2,%3}, {%4,%5,%6,%7}, {%8,%9}, {%0,%1,%2,%3};"
                 : "+f"(d[0]), "+f"(d[1]), "+f"(d[2]), "+f"(d[3])
                 : "r"(a[0]), "r"(a[1]), "r"(a[2]), "r"(a[3]),
                   "r"(b[0]), "r"(b[1]));
}
__device__ __forceinline__ void mma16f(float* d, const uint32_t* a, const uint32_t* b) {
    asm volatile("mma.sync.aligned.m16n8k16.row.col.f32.f16.f16.f32 "
                 "{%0,%1,%2,%3}, {%4,%5,%6,%7}, {%8,%9}, {%0,%1,%2,%3};"
                 : "+f"(d[0]), "+f"(d[1]), "+f"(d[2]), "+f"(d[3])
                 : "r"(a[0]), "r"(a[1]), "r"(a[2]), "r"(a[3]),
                   "r"(b[0]), "r"(b[1]));
}

// ======================  mma.sync tf32 GEMM body (2-stage)  =================
#define GK 1024
#define GN 1024
#define BKC 32
#define NKT (GK/BKC)
#define STAGE_B (128*36*4)    // 18432 B per matrix per stage
#define GSM_TOTAL (4*STAGE_B) // 73728 B

// Epilogue targets: Ch != nullptr -> row-major f16; toVT != nullptr ->
// per-(b,h)-transposed f16 V layout; else row-major f32 C.
__device__ __forceinline__ void gemm_body(
    char* smem, const float* __restrict__ A, const float* __restrict__ BT,
    const float* __restrict__ bias, const float* __restrict__ res,
    float* __restrict__ C, __half* __restrict__ Ch,
    __half* __restrict__ toVT, int bx, int by)
{
    uint32_t sb = smem_u32(smem);
    const int tid = threadIdx.x;
    const int lane = tid & 31;
    const int wid = tid >> 5;
    const int warp_m = wid >> 2;
    const int warp_n = wid & 3;
    const int row0 = by * 128;
    const int col0 = bx * 128;

    const float* Abase = A  + (size_t)row0 * GK;
    const float* Bbase = BT + (size_t)col0 * GK;

    auto load_stage = [&](int stage, int kt) {
        uint32_t as = sb + (stage * 2 + 0) * STAGE_B;
        uint32_t bs = sb + (stage * 2 + 1) * STAGE_B;
        const float* Ak = Abase + kt * BKC;
        const float* Bk = Bbase + kt * BKC;
        #pragma unroll
        for (int i = 0; i < 4; i++) {
            int c = tid + i * 256;
            int r = c >> 3, sg = c & 7;
            cp16(as + (uint32_t)(r * 144 + sg * 16), Ak + (size_t)r * GK + sg * 4);
            cp16(bs + (uint32_t)(r * 144 + sg * 16), Bk + (size_t)r * GK + sg * 4);
        }
        CP_COMMIT();
    };

    uint32_t a_off[4], bp_off[2];
    #pragma unroll
    for (int mf = 0; mf < 4; mf++)
        a_off[mf] = (uint32_t)((warp_m * 64 + mf * 16 + (lane & 15)) * 144
                               + (lane >> 4) * 16);
    #pragma unroll
    for (int p = 0; p < 2; p++)
        bp_off[p] = (uint32_t)((warp_n * 32 + p * 16 + ((lane >> 4) << 3) + (lane & 7)) * 144
                               + ((lane >> 3) & 1) * 16);

    float acc[4][4][4] = {};

    load_stage(0, 0);
    int buf = 0;
    for (int kt = 0; kt < NKT; kt++) {
        if (kt + 1 < NKT) {
            load_stage(buf ^ 1, kt + 1);
            CP_WAIT1();
        } else {
            CP_WAIT0();
        }
        __syncthreads();

        uint32_t as = sb + (buf * 2 + 0) * STAGE_B;
        uint32_t bs = sb + (buf * 2 + 1) * STAGE_B;
        #pragma unroll
        for (int ks = 0; ks < 4; ks++) {
            uint32_t a[4][4], bfr[2][4];
            #pragma unroll
            for (int mf = 0; mf < 4; mf++)
                ldsm4(a[mf], as + a_off[mf] + ks * 32);
            #pragma unroll
            for (int p = 0; p < 2; p++)
                ldsm4(bfr[p], bs + bp_off[p] + ks * 32);
            #pragma unroll
            for (int mf = 0; mf < 4; mf++) {
                mma8(acc[mf][0], a[mf], &bfr[0][0]);
                mma8(acc[mf][1], a[mf], &bfr[0][2]);
                mma8(acc[mf][2], a[mf], &bfr[1][0]);
                mma8(acc[mf][3], a[mf], &bfr[1][2]);
            }
        }
        __syncthreads();
        buf ^= 1;
    }

    #pragma unroll
    for (int nf = 0; nf < 4; nf++) {
        int c = col0 + warp_n * 32 + nf * 8 + 2 * (lane & 3);
        float bx_ = __ldg(bias + c), by_ = __ldg(bias + c + 1);
        #pragma unroll
        for (int mf = 0; mf < 4; mf++) {
            int r = row0 + warp_m * 64 + mf * 16 + (lane >> 2);
            float2 v0 = make_float2(acc[mf][nf][0] + bx_, acc[mf][nf][1] + by_);
            float2 v1 = make_float2(acc[mf][nf][2] + bx_, acc[mf][nf][3] + by_);
            if (res) {
                float2 r0 = *(const float2*)(res + (size_t)r * GN + c);
                float2 r1 = *(const float2*)(res + (size_t)(r + 8) * GN + c);
                v0.x += r0.x; v0.y += r0.y;
                v1.x += r1.x; v1.y += r1.y;
            }
            if (toVT) {
                int b_ = r >> 10, s = r & 1023;
                int h_ = c >> 6, d = c & 63;
                size_t i0 = ((size_t)((b_ * 16 + h_) * 64 + d)) << 10;
                toVT[i0 + s]            = __float2half(v0.x);
                toVT[i0 + 1024 + s]     = __float2half(v0.y);
                toVT[i0 + s + 8]        = __float2half(v1.x);
                toVT[i0 + 1024 + s + 8] = __float2half(v1.y);
            } else if (Ch) {
                *(uint32_t*)(Ch + (size_t)r * GN + c)       = pack_h2(v0.x, v0.y);
                *(uint32_t*)(Ch + (size_t)(r + 8) * GN + c) = pack_h2(v1.x, v1.y);
            } else {
                *(float2*)(C + (size_t)r * GN + c) = v0;
                *(float2*)(C + (size_t)(r + 8) * GN + c) = v1;
            }
        }
    }
}

__global__ void __launch_bounds__(256, 2)
qkv_gemm(const float* q, const float* k, const float* v,
         const float* wq, const float* wk, const float* wv,
         const float* bq, const float* bk, const float* bv,
         __half* oqh, __half* okh, __half* ovt)
{
    extern __shared__ char smem[];
    int z = blockIdx.z;
    const float* A  = (z == 0) ? q  : (z == 1) ? k  : v;
    const float* BT = (z == 0) ? wq : (z == 1) ? wk : wv;
    const float* bi = (z == 0) ? bq : (z == 1) ? bk : bv;
    __half* Ch      = (z == 0) ? oqh : (z == 1) ? okh : nullptr;
    __half* VT      = (z == 2) ? ovt : nullptr;
    gemm_body(smem, A, BT, bi, nullptr, nullptr, Ch, VT, blockIdx.x, blockIdx.y);
}

__global__ void __launch_bounds__(256, 2)
o_gemm(const float* A, const float* BT, const float* bias,
       const float* res, float* C)
{
    extern __shared__ char smem[];
    gemm_body(smem, A, BT, bias, res, C, nullptr, nullptr, blockIdx.x, blockIdx.y);
}

// ==== fused pre-pass: weight transposes (+tf32 round) AND spec layer-1 ======
__global__ void fused_pre(const float* __restrict__ s0, float* __restrict__ d0,
                          const float* __restrict__ s1, float* __restrict__ d1,
                          const float* __restrict__ s2, float* __restrict__ d2,
                          const float* __restrict__ s3, float* __restrict__ d3,
                          const float* __restrict__ query,
                          const float* __restrict__ Ws1)
{
    __shared__ float t[32][33];
    __shared__ float sin_s[32];
    __shared__ float red[256];
    int bx = blockIdx.x;
    int tid = threadIdx.x;

    if (bx < 4096) {
        int zz = bx >> 10;
        int rem = bx & 1023;
        int txb = rem & 31, tyb = rem >> 5;
        const float* src = (zz == 0) ? s0 : (zz == 1) ? s1 : (zz == 2) ? s2 : s3;
        float* dst       = (zz == 0) ? d0 : (zz == 1) ? d1 : (zz == 2) ? d2 : d3;
        int lx = tid & 31, ly = tid >> 5;
        int x = txb * 32 + lx;
        int y0 = tyb * 32;
        #pragma unroll
        for (int i = ly; i < 32; i += 8)
            t[i][lx] = src[(size_t)(y0 + i) * HH + x];
        __syncthreads();
        int xo = tyb * 32 + lx;
        int yo0 = txb * 32;
        #pragma unroll
        for (int i = ly; i < 32; i += 8)
            dst[(size_t)(yo0 + i) * HH + xo] = f2tf_f(t[lx][i]);
    } else {
        int idx = bx - 4096;          // 0..63
        int b = idx >> 5, ch = idx & 31;
        int r0 = ch * 32;
        {
            int row = tid >> 3, seg = tid & 7;
            const float* qp = query + ((size_t)b * SS + seg * 128) * HH + r0 + row;
            float s = 0.f;
            #pragma unroll 4
            for (int j = 0; j < 128; j++) s += qp[(size_t)j * HH];
            red[row * 8 + seg] = s;
        }
        __syncthreads();
        if (tid < 32) {
            float s = 0.f;
            #pragma unroll
            for (int j = 0; j < 8; j++) s += red[tid * 8 + j];
            sin_s[tid] = s * (1.0f / SS);
        }
        __syncthreads();
        #pragma unroll
        for (int c = tid; c < 512; c += 256) {
            float acc = 0.f;
            #pragma unroll 4
            for (int j = 0; j < 32; j++)
                acc += sin_s[j] * Ws1[(size_t)(r0 + j) * 512 + c];
            g_h1p[(size_t)(b * 32 + ch) * 512 + c] = acc;
        }
    }
}

// -------- spec layer-2: grid(16 colblocks, BB), 256 thr --------------------
__global__ void spec2_kernel(const float* __restrict__ bs1,
                             const float* __restrict__ Ws2,
                             const float* __restrict__ bs2)
{
    __shared__ float h1[512];
    __shared__ float zp[4][64];
    __shared__ float red[64];
    int b = blockIdx.y, cb = blockIdx.x;
    int tid = threadIdx.x;
    for (int c = tid; c < 512; c += 256) {
        float s = bs1[c];
        #pragma unroll
        for (int ch = 0; ch < 32; ch++) s += g_h1p[(size_t)(b * 32 + ch) * 512 + c];
        h1[c] = fmaxf(s, 0.f);
    }
    __syncthreads();
    int col = cb * 64 + (tid & 63);
    int qq = tid >> 6;
    float z = 0.f;
    #pragma unroll 4
    for (int i = qq * 128; i < qq * 128 + 128; i++)
        z += h1[i] * Ws2[(size_t)i * HH + col];
    zp[qq][tid & 63] = z;
    __syncthreads();
    if (tid < 64) {
        float zz = bs2[cb * 64 + tid] + zp[0][tid] + zp[1][tid] + zp[2][tid] + zp[3][tid];
        red[tid] = 1.0f / (1.0f + __expf(-zz));
    }
    __syncthreads();
    for (int off = 32; off > 0; off >>= 1) {
        if (tid < off) red[tid] += red[tid + off];
        __syncthreads();
    }
    if (tid == 0) g_sp[b * 16 + cb] = red[0];
}

// ==  flash attention: ALL f16 operands, f32 accum; 32-key double-buffer  ====
// smem: K0,K1 (32x144B) V0,V1 (64x80B) P (128x80B) = 29696 B
// Q staged through [0, 18432) at prologue only.
// KSTR=144 (36 words === 4 mod 32, conflict-free); HSTR=80 (20 words).
#define KSTR 144                       // Q-staging / K row stride (f16: 64 halves)
#define HSTR 80                        // P / V row stride (f16: 32 halves)
#define K0_OFF 0
#define K1_OFF 4608
#define V0_OFF 9216
#define V1_OFF 14336
#define P_OFF  19456
#define A_SMEM 29696

__global__ void __launch_bounds__(256, 2)
attn_mma(const float* __restrict__ msb)
{
    extern __shared__ char smem[];
    __shared__ float red[256];
    __shared__ float mh_s;
    uint32_t sb = smem_u32(smem);
    const int tid = threadIdx.x;
    const int lane = tid & 31;
    const int w = tid >> 5;
    const int b = blockIdx.z, h = blockIdx.y, q0 = blockIdx.x << 7;

    // A-frag (m16k16 f16): row = 16w + (lane&15), k-half (lane>>4)*16B
    const uint32_t Pa = sb + P_OFF + (uint32_t)((16 * w + (lane & 15)) * HSTR + (lane >> 4) * 16);
    const uint32_t krow = (uint32_t)(((((lane >> 4) << 3) + (lane & 7)) * KSTR) + ((lane >> 3) & 1) * 16);
    const uint32_t vrow = (uint32_t)(((((lane >> 4) << 3) + (lane & 7)) * HSTR) + ((lane >> 3) & 1) * 16);
    const uint32_t Kb[2] = { sb + K0_OFF + krow, sb + K1_OFF + krow };
    const uint32_t Vb[2] = { sb + V0_OFF + vrow, sb + V1_OFF + vrow };
    const uint32_t koff[2] = { K0_OFF, K1_OFF };
    const uint32_t voff[2] = { V0_OFF, V1_OFF };

    const __half* Kg0 = g_Kh + (size_t)b * SS * HH + h * HDD;
    const __half* Vg0 = g_VTh + (size_t)(b * NHH + h) * HDD * SS;

    // K: 32 rows x 128B (1 cp16/thread); V: 64 rows x 64B (1 cp16/thread)
    auto load_tile = [&](int bufsel, int kt) {
        const __half* Kg = Kg0 + (size_t)kt * 32 * HH;
        const __half* Vg = Vg0 + kt * 32;
        {
            int rk = tid >> 3, ck = tid & 7;
            cp16(sb + koff[bufsel] + (uint32_t)(rk * KSTR + ck * 16),
                 Kg + (size_t)rk * HH + ck * 8);
        }
        {
            int rv = tid >> 2, cv = tid & 3;
            cp16(sb + voff[bufsel] + (uint32_t)(rv * HSTR + cv * 16),
                 Vg + (size_t)rv * SS + cv * 8);
        }
        CP_COMMIT();
    };

    // ---- prologue: stage Q (f16) into smem[0..18432), msb reduce ----
    {
        const __half* Qg = g_Qh + ((size_t)b * SS + q0) * HH + h * HDD;
        #pragma unroll
        for (int i = 0; i < 4; i++) {
            int f = tid + i * 256;
            int r = f >> 3, c8 = f & 7;
            cp16(sb + (uint32_t)(r * KSTR + c8 * 16),
                 Qg + (size_t)r * HH + c8 * 8);
        }
        CP_COMMIT();
    }
    {
        const float* p = msb + (size_t)h * HDD * HDD;
        float s = 0.f;
        for (int i = tid; i < HDD * HDD; i += 256) s += p[i];
        red[tid] = s;
        __syncthreads();
        for (int off = 128; off > 0; off >>= 1) {
            if (tid < off) red[tid] += red[tid + off];
            __syncthreads();
        }
        if (tid == 0) mh_s = red[0] * (1.0f / (HDD * HDD));
    }
    CP_WAIT0();
    __syncthreads();

    uint32_t qf[4][4];
    {
        uint32_t Qa = sb + (uint32_t)((16 * w + (lane & 15)) * KSTR + (lane >> 4) * 16);
        #pragma unroll
        for (int ks = 0; ks < 4; ks++) ldsm4(qf[ks], Qa + ks * 32);
    }
    __syncthreads();            // all warps done reading Q staging
    load_tile(0, 0);

    const float mh = mh_s;
    float sp = 0.f;
    #pragma unroll
    for (int j = 0; j < 16; j++) sp += g_sp[b * 16 + j];
    sp *= (1.0f / HH);

    // folded gate constants: p = s*c1 + (s*c3)*tanh(s*a2)
    const float a2 = 0.5f * SCALE_C * mh;
    const float c1 = SCALE_C * sp * (1.0f + 0.5f * SP_C);
    const float c3 = SCALE_C * sp * (0.5f * SP_C);

    CP_WAIT0();
    __syncthreads();

    float oacc[8][4] = {};
    float m0 = -1e30f, m1 = -1e30f, l0 = 0.f, l1 = 0.f;

    for (int kt = 0; kt < 32; kt++) {
        int cur = kt & 1;
        if (kt + 1 < 32) load_tile(cur ^ 1, kt + 1);   // overlaps compute

        // ---- S = Q @ K^T  (f16 mma k16, 16 q-rows x 32 keys) ----
        float sacc[4][4] = {};
        #pragma unroll
        for (int ks = 0; ks < 4; ks++) {
            #pragma unroll
            for (int kb = 0; kb < 2; kb++) {
                uint32_t bb[4];
                ldsm4(bb, Kb[cur] + kb * 16 * KSTR + ks * 32);
                mma16f(sacc[2 * kb],     qf[ks], bb);
                mma16f(sacc[2 * kb + 1], qf[ks], bb + 2);
            }
        }

        // ---- gate (tanh-based sigmoid) + online softmax ----
        float tm0 = -1e30f, tm1 = -1e30f;
        #pragma unroll
        for (int nf = 0; nf < 4; nf++) {
            #pragma unroll
            for (int j = 0; j < 4; j++) {
                float s = sacc[nf][j];
                float th = tanh_fast(s * a2);
                float p = fmaf(s * c3, th, s * c1);
                sacc[nf][j] = p;
                if (j < 2) tm0 = fmaxf(tm0, p); else tm1 = fmaxf(tm1, p);
            }
        }
        tm0 = fmaxf(tm0, __shfl_xor_sync(0xffffffff, tm0, 1));
        tm0 = fmaxf(tm0, __shfl_xor_sync(0xffffffff, tm0, 2));
        tm1 = fmaxf(tm1, __shfl_xor_sync(0xffffffff, tm1, 1));
        tm1 = fmaxf(tm1, __shfl_xor_sync(0xffffffff, tm1, 2));

        float nm0 = fmaxf(m0, tm0), nm1 = fmaxf(m1, tm1);
        float sc0 = __expf(m0 - nm0), sc1 = __expf(m1 - nm1);
        float su0 = 0.f, su1 = 0.f;
        #pragma unroll
        for (int nf = 0; nf < 4; nf++) {
            float p0 = __expf(sacc[nf][0] - nm0);
            float p1 = __expf(sacc[nf][1] - nm0);
            float p2 = __expf(sacc[nf][2] - nm1);
            float p3 = __expf(sacc[nf][3] - nm1);
            su0 += p0 + p1; su1 += p2 + p3;
            sacc[nf][0] = p0; sacc[nf][1] = p1;
            sacc[nf][2] = p2; sacc[nf][3] = p3;
        }
        su0 += __shfl_xor_sync(0xffffffff, su0, 1);
        su0 += __shfl_xor_sync(0xffffffff, su0, 2);
        su1 += __shfl_xor_sync(0xffffffff, su1, 1);
        su1 += __shfl_xor_sync(0xffffffff, su1, 2);
        l0 = l0 * sc0 + su0;
        l1 = l1 * sc1 + su1;
        m0 = nm0; m1 = nm1;

        #pragma unroll
        for (int nf = 0; nf < 8; nf++) {
            oacc[nf][0] *= sc0; oacc[nf][1] *= sc0;
            oacc[nf][2] *= sc1; oacc[nf][3] *= sc1;
        }

        // ---- write P as packed f16 (warp-local rows; ldmatrix warp-sync) --
        {
            int r0 = 16 * w + (lane >> 2);
            uint32_t p0a = (uint32_t)(P_OFF + r0 * HSTR + (lane & 3) * 4);
            #pragma unroll
            for (int nf = 0; nf < 4; nf++) {
                *(uint32_t*)(smem + p0a + nf * 16) =
                    pack_h2(sacc[nf][0], sacc[nf][1]);
                *(uint32_t*)(smem + p0a + 8 * HSTR + nf * 16) =
                    pack_h2(sacc[nf][2], sacc[nf][3]);
            }
        }
        __syncwarp();

        // ---- O += P @ V  (f16 mma, k16) ----
        #pragma unroll
        for (int kb = 0; kb < 2; kb++) {
            uint32_t a[4];
            ldsm4(a, Pa + kb * 32);
            #pragma unroll
            for (int db = 0; db < 4; db++) {
                uint32_t bb[4];
                ldsm4(bb, Vb[cur] + db * 16 * HSTR + kb * 32);
                mma16f(oacc[2 * db],     a, bb);
                mma16f(oacc[2 * db + 1], a, bb + 2);
            }
        }

        if (kt + 1 < 32) CP_WAIT0();
        __syncthreads();
    }

    // ---- epilogue: normalize + store ctx ----
    float inv0 = 1.0f / l0, inv1 = 1.0f / l1;
    float* Og = g_ctx + ((size_t)b * SS + q0) * HH + h * HDD;
    int r0 = 16 * w + (lane >> 2);
    #pragma unroll
    for (int nf = 0; nf < 8; nf++) {
        int c = 8 * nf + 2 * (lane & 3);
        *(float2*)&Og[(size_t)r0 * HH + c] =
            make_float2(oacc[nf][0] * inv0, oacc[nf][1] * inv0);
        *(float2*)&Og[(size_t)(r0 + 8) * HH + c] =
            make_float2(oacc[nf][2] * inv1, oacc[nf][3] * inv1);
    }
}

// ---------------- row LayerNorm ----------------
__global__ void ln_kernel(const float* __restrict__ x,
                          const float* __restrict__ g,
                          const float* __restrict__ bta,
                          float* __restrict__ out)
{
    __shared__ float r1[256];
    __shared__ float r2[256];
    int row = blockIdx.x, tid = threadIdx.x;
    const float4* xr = (const float4*)(x + (size_t)row * HH);
    float4 a = xr[tid];
    float s = a.x + a.y + a.z + a.w;
    float ss = a.x * a.x + a.y * a.y + a.z * a.z + a.w * a.w;
    r1[tid] = s; r2[tid] = ss;
    __syncthreads();
    for (int off = 128; off > 0; off >>= 1) {
        if (tid < off) { r1[tid] += r1[tid + off]; r2[tid] += r2[tid + off]; }
        __syncthreads();
    }
    float mu = r1[0] * (1.0f / HH);
    float var = r2[0] * (1.0f / HH) - mu * mu;
    float rstd = rsqrtf(var + EPS_C);
    float4 gg = ((const float4*)g)[tid];
    float4 bb = ((const float4*)bta)[tid];
    float4 o;
    o.x = (a.x - mu) * rstd * gg.x + bb.x;
    o.y = (a.y - mu) * rstd * gg.y + bb.y;
    o.z = (a.z - mu) * rstd * gg.z + bb.z;
    o.w = (a.w - mu) * rstd * gg.w + bb.w;
    ((float4*)(out + (size_t)row * HH))[tid] = o;
}

// ---------------- launch ----------------
extern "C" void kernel_launch(void* const* d_in, const int* in_sizes, int n_in,
                              void* d_out, int out_size)
{
    const float* query = (const float*)d_in[0];
    const float* key_t = (const float*)d_in[1];
    const float* value = (const float*)d_in[2];
    const float* Wq = (const float*)d_in[3];
    const float* bq = (const float*)d_in[4];
    const float* Wk = (const float*)d_in[5];
    const float* bk = (const float*)d_in[6];
    const float* Wv = (const float*)d_in[7];
    const float* bv = (const float*)d_in[8];
    const float* msb = (const float*)d_in[9];
    const float* Ws1 = (const float*)d_in[10];
    const float* bs1 = (const float*)d_in[11];
    const float* Ws2 = (const float*)d_in[12];
    const float* bs2 = (const float*)d_in[13];
    const float* Wo = (const float*)d_in[14];
    const float* bo = (const float*)d_in[15];
    const float* ln_g = (const float*)d_in[16];
    const float* ln_b = (const float*)d_in[17];

    float *pCtx, *pPre, *pWT;
    __half *pQh, *pKh, *pVTh;
    cudaGetSymbolAddress((void**)&pQh, g_Qh);
    cudaGetSymbolAddress((void**)&pKh, g_Kh);
    cudaGetSymbolAddress((void**)&pVTh, g_VTh);
    cudaGetSymbolAddress((void**)&pCtx, g_ctx);
    cudaGetSymbolAddress((void**)&pPre, g_pre);
    cudaGetSymbolAddress((void**)&pWT, g_WT);

    float* WTq = pWT + 0 * HH * HH;
    float* WTk = pWT + 1 * HH * HH;
    float* WTv = pWT + 2 * HH * HH;
    float* WTo = pWT + 3 * HH * HH;

    cudaFuncSetAttribute(qkv_gemm, cudaFuncAttributeMaxDynamicSharedMemorySize,
                         GSM_TOTAL);
    cudaFuncSetAttribute(o_gemm, cudaFuncAttributeMaxDynamicSharedMemorySize,
                         GSM_TOTAL);
    cudaFuncSetAttribute(attn_mma, cudaFuncAttributeMaxDynamicSharedMemorySize,
                         A_SMEM);

    // 0: fused weight transposes + spec layer-1 (reads query directly)
    fused_pre<<<4160, 256>>>(Wq, WTq, Wk, WTk, Wv, WTv, Wo, WTo, query, Ws1);
    // 1: spec layer-2
    spec2_kernel<<<dim3(16, BB), 256>>>(bs1, Ws2, bs2);
    // 2: fused Q/K/V projection GEMM (Q/K written f16, V transposed f16)
    qkv_gemm<<<dim3(GN / 128, M_TOT / 128, 3), 256, GSM_TOTAL>>>(
        query, key_t, value, WTq, WTk, WTv, bq, bk, bv, pQh, pKh, pVTh);
    // 3 (profiled slot): flash attention (all-f16 operands, f32 accum)
    attn_mma<<<dim3(SS / 128, NHH, BB), 256, A_SMEM>>>(msb);
    // 4: output projection + bias + residual
    o_gemm<<<dim3(GN / 128, M_TOT / 128), 256, GSM_TOTAL>>>(pCtx, WTo, bo, query, pPre);
    // 5: LayerNorm -> d_out
    ln_kernel<<<M_TOT, 256>>>(pPre, ln_g, ln_b, (float*)d_out);
}

// round 16
// speedup vs baseline: 2.0502x; 1.2883x over previous
#include <cuda_runtime.h>
#include <cuda_bf16.h>
#include <cuda_fp16.h>
#include <math.h>
#include <cstdint>

// Problem constants
#define BB 2
#define SS 1024
#define HH 1024
#define NHH 16
#define HDD 64
#define SP_C 0.05f
#define EPS_C 1e-5f
#define SCALE_C 0.125f   // 1/sqrt(64)

#define M_TOT (BB*SS)    // 2048

// ---------------- scratch (device globals: no allocations allowed) ----------
__device__ __half g_x16[3*M_TOT*HH];    // f16 copies of query/key_t/value
__device__ __half g_Qh[M_TOT*HH];       // Q projection, f16
__device__ __half g_Kh[M_TOT*HH];       // K projection, f16
__device__ __half g_VTh[BB*NHH*HDD*SS]; // V transposed per (b,h): [d][s], f16
__device__ __half g_ctxh[M_TOT*HH];     // attention output, f16
__device__ float g_pre[M_TOT*HH];
__device__ __half g_WTh[4*HH*HH];       // transposed f16 weights
__device__ float g_h1p[BB*32*512];      // spec layer-1 partials
__device__ float g_sp[BB*16];           // spec sigmoid-sum partials

// =====================  PTX helpers (mma.sync / cp.async)  ==================
__device__ __forceinline__ uint32_t smem_u32(const void* p) {
    uint32_t a;
    asm("{ .reg .u64 t; cvta.to.shared.u64 t, %1; cvt.u32.u64 %0, t; }"
        : "=r"(a) : "l"(p));
    return a;
}

__device__ __forceinline__ void cp16(uint32_t s, const void* g) {
    asm volatile("cp.async.cg.shared.global [%0], [%1], 16;"
                 :: "r"(s), "l"(__cvta_generic_to_global(g)));
}
#define CP_COMMIT() asm volatile("cp.async.commit_group;" ::: "memory")
#define CP_WAIT0()  asm volatile("cp.async.wait_group 0;" ::: "memory")
#define CP_WAIT1()  asm volatile("cp.async.wait_group 1;" ::: "memory")

__device__ __forceinline__ void ldsm4(uint32_t* r, uint32_t addr) {
    asm volatile("ldmatrix.sync.aligned.m8n8.x4.shared.b16 {%0,%1,%2,%3}, [%4];"
                 : "=r"(r[0]), "=r"(r[1]), "=r"(r[2]), "=r"(r[3]) : "r"(addr));
}
__device__ __forceinline__ float tanh_fast(float x) {
    float y;
    asm("tanh.approx.f32 %0, %1;" : "=f"(y) : "f"(x));
    return y;
}
__device__ __forceinline__ uint32_t pack_h2(float lo, float hi) {
    uint32_t r;
    asm("cvt.rn.f16x2.f32 %0, %1, %2;" : "=r"(r) : "f"(hi), "f"(lo));
    return r;
}
__device__ __forceinline__ void mma16f(float* d, const uint32_t* a, const uint32_t* b) {
    asm volatile("mma.sync.aligned.m16n8k16.row.col.f32.f16.f16.f32 "
                 "{%0,%1,%2,%3}, {%4,%5,%6,%7}, {%8,%9}, {%0,%1,%2,%3};"
                 : "+f"(d[0]), "+f"(d[1]), "+f"(d[2]), "+f"(d[3])
                 : "r"(a[0]), "r"(a[1]), "r"(a[2]), "r"(a[3]),
                   "r"(b[0]), "r"(b[1]));
}

// ======================  f16 mma GEMM body (2-stage, BK=64)  ================
#define GK 1024
#define GN 1024
#define BK64 64
#define NKT16 (GK/BK64)       // 16
#define STAGE_B (128*144)     // 18432 B per matrix per stage (64 halves + pad)
#define GSM_TOTAL (4*STAGE_B) // 73728 B

// Epilogue targets: Ch -> row-major f16; toVT -> per-(b,h)-transposed f16 V;
// else row-major f32 C (with optional f32 residual).
__device__ __forceinline__ void gemm16_body(
    char* smem, const __half* __restrict__ A, const __half* __restrict__ BT,
    const float* __restrict__ bias, const float* __restrict__ res,
    float* __restrict__ C, __half* __restrict__ Ch,
    __half* __restrict__ toVT, int bx, int by)
{
    uint32_t sb = smem_u32(smem);
    const int tid = threadIdx.x;
    const int lane = tid & 31;
    const int wid = tid >> 5;
    const int warp_m = wid >> 2;
    const int warp_n = wid & 3;
    const int row0 = by * 128;
    const int col0 = bx * 128;

    const __half* Abase = A  + (size_t)row0 * GK;
    const __half* Bbase = BT + (size_t)col0 * GK;

    auto load_stage = [&](int stage, int kt) {
        uint32_t as = sb + (stage * 2 + 0) * STAGE_B;
        uint32_t bs = sb + (stage * 2 + 1) * STAGE_B;
        const __half* Ak = Abase + kt * BK64;
        const __half* Bk = Bbase + kt * BK64;
        #pragma unroll
        for (int i = 0; i < 4; i++) {
            int c = tid + i * 256;
            int r = c >> 3, sg = c & 7;        // 128 rows x 8 segs of 16B
            cp16(as + (uint32_t)(r * 144 + sg * 16), Ak + (size_t)r * GK + sg * 8);
            cp16(bs + (uint32_t)(r * 144 + sg * 16), Bk + (size_t)r * GK + sg * 8);
        }
        CP_COMMIT();
    };

    // A-frag m16k16; B paired ldsm4 covers two n8 fragments.
    uint32_t a_off[4], bp_off[2];
    #pragma unroll
    for (int mf = 0; mf < 4; mf++)
        a_off[mf] = (uint32_t)((warp_m * 64 + mf * 16 + (lane & 15)) * 144
                               + (lane >> 4) * 16);
    #pragma unroll
    for (int p = 0; p < 2; p++)
        bp_off[p] = (uint32_t)((warp_n * 32 + p * 16 + ((lane >> 4) << 3) + (lane & 7)) * 144
                               + ((lane >> 3) & 1) * 16);

    float acc[4][4][4] = {};

    load_stage(0, 0);
    int buf = 0;
    for (int kt = 0; kt < NKT16; kt++) {
        if (kt + 1 < NKT16) {
            load_stage(buf ^ 1, kt + 1);
            CP_WAIT1();
        } else {
            CP_WAIT0();
        }
        __syncthreads();

        uint32_t as = sb + (buf * 2 + 0) * STAGE_B;
        uint32_t bs = sb + (buf * 2 + 1) * STAGE_B;
        #pragma unroll
        for (int ks = 0; ks < 4; ks++) {      // 4 x k16 per BK=64
            uint32_t a[4][4], bfr[2][4];
            #pragma unroll
            for (int mf = 0; mf < 4; mf++)
                ldsm4(a[mf], as + a_off[mf] + ks * 32);
            #pragma unroll
            for (int p = 0; p < 2; p++)
                ldsm4(bfr[p], bs + bp_off[p] + ks * 32);
            #pragma unroll
            for (int mf = 0; mf < 4; mf++) {
                mma16f(acc[mf][0], a[mf], &bfr[0][0]);
                mma16f(acc[mf][1], a[mf], &bfr[0][2]);
                mma16f(acc[mf][2], a[mf], &bfr[1][0]);
                mma16f(acc[mf][3], a[mf], &bfr[1][2]);
            }
        }
        __syncthreads();
        buf ^= 1;
    }

    #pragma unroll
    for (int nf = 0; nf < 4; nf++) {
        int c = col0 + warp_n * 32 + nf * 8 + 2 * (lane & 3);
        float bx_ = __ldg(bias + c), by_ = __ldg(bias + c + 1);
        #pragma unroll
        for (int mf = 0; mf < 4; mf++) {
            int r = row0 + warp_m * 64 + mf * 16 + (lane >> 2);
            float2 v0 = make_float2(acc[mf][nf][0] + bx_, acc[mf][nf][1] + by_);
            float2 v1 = make_float2(acc[mf][nf][2] + bx_, acc[mf][nf][3] + by_);
            if (res) {
                float2 r0 = *(const float2*)(res + (size_t)r * GN + c);
                float2 r1 = *(const float2*)(res + (size_t)(r + 8) * GN + c);
                v0.x += r0.x; v0.y += r0.y;
                v1.x += r1.x; v1.y += r1.y;
            }
            if (toVT) {
                int b_ = r >> 10, s = r & 1023;
                int h_ = c >> 6, d = c & 63;
                size_t i0 = ((size_t)((b_ * 16 + h_) * 64 + d)) << 10;
                toVT[i0 + s]            = __float2half(v0.x);
                toVT[i0 + 1024 + s]     = __float2half(v0.y);
                toVT[i0 + s + 8]        = __float2half(v1.x);
                toVT[i0 + 1024 + s + 8] = __float2half(v1.y);
            } else if (Ch) {
                *(uint32_t*)(Ch + (size_t)r * GN + c)       = pack_h2(v0.x, v0.y);
                *(uint32_t*)(Ch + (size_t)(r + 8) * GN + c) = pack_h2(v1.x, v1.y);
            } else {
                *(float2*)(C + (size_t)r * GN + c) = v0;
                *(float2*)(C + (size_t)(r + 8) * GN + c) = v1;
            }
        }
    }
}

__global__ void __launch_bounds__(256, 2)
qkv_gemm(const __half* x16, const __half* wth,
         const float* bq, const float* bk, const float* bv,
         __half* oqh, __half* okh, __half* ovt)
{
    extern __shared__ char smem[];
    int z = blockIdx.z;
    const __half* A  = x16 + (size_t)z * M_TOT * HH;
    const __half* BT = wth + (size_t)z * HH * HH;
    const float* bi  = (z == 0) ? bq : (z == 1) ? bk : bv;
    __half* Ch       = (z == 0) ? oqh : (z == 1) ? okh : nullptr;
    __half* VT       = (z == 2) ? ovt : nullptr;
    gemm16_body(smem, A, BT, bi, nullptr, nullptr, Ch, VT, blockIdx.x, blockIdx.y);
}

__global__ void __launch_bounds__(256, 2)
o_gemm(const __half* A, const __half* BT, const float* bias,
       const float* res, float* C)
{
    extern __shared__ char smem[];
    gemm16_body(smem, A, BT, bias, res, C, nullptr, nullptr, blockIdx.x, blockIdx.y);
}

// == fused pre-pass: weight transposes->f16, spec layer-1, activation->f16 ===
// bx in [0,4096): weight transpose tiles; [4096,4160): spec1; [4160,7232): cvt
__global__ void fused_pre(const float* __restrict__ s0,
                          const float* __restrict__ s1,
                          const float* __restrict__ s2,
                          const float* __restrict__ s3,
                          __half* __restrict__ wth,
                          const float* __restrict__ query,
                          const float* __restrict__ key_t,
                          const float* __restrict__ value,
                          __half* __restrict__ x16,
                          const float* __restrict__ Ws1)
{
    __shared__ float t[32][33];
    __shared__ float sin_s[32];
    __shared__ float red[256];
    int bx = blockIdx.x;
    int tid = threadIdx.x;

    if (bx < 4096) {
        int zz = bx >> 10;
        int rem = bx & 1023;
        int txb = rem & 31, tyb = rem >> 5;
        const float* src = (zz == 0) ? s0 : (zz == 1) ? s1 : (zz == 2) ? s2 : s3;
        __half* dst = wth + (size_t)zz * HH * HH;
        int lx = tid & 31, ly = tid >> 5;
        int x = txb * 32 + lx;
        int y0 = tyb * 32;
        #pragma unroll
        for (int i = ly; i < 32; i += 8)
            t[i][lx] = src[(size_t)(y0 + i) * HH + x];
        __syncthreads();
        int xo = tyb * 32 + lx;
        int yo0 = txb * 32;
        #pragma unroll
        for (int i = ly; i < 32; i += 8)
            dst[(size_t)(yo0 + i) * HH + xo] = __float2half(t[lx][i]);
    } else if (bx < 4160) {
        int idx = bx - 4096;          // 0..63
        int b = idx >> 5, ch = idx & 31;
        int r0 = ch * 32;
        {
            int row = tid >> 3, seg = tid & 7;
            const float* qp = query + ((size_t)b * SS + seg * 128) * HH + r0 + row;
            float s = 0.f;
            #pragma unroll 4
            for (int j = 0; j < 128; j++) s += qp[(size_t)j * HH];
            red[row * 8 + seg] = s;
        }
        __syncthreads();
        if (tid < 32) {
            float s = 0.f;
            #pragma unroll
            for (int j = 0; j < 8; j++) s += red[tid * 8 + j];
            sin_s[tid] = s * (1.0f / SS);
        }
        __syncthreads();
        #pragma unroll
        for (int c = tid; c < 512; c += 256) {
            float acc = 0.f;
            #pragma unroll 4
            for (int j = 0; j < 32; j++)
                acc += sin_s[j] * Ws1[(size_t)(r0 + j) * 512 + c];
            g_h1p[(size_t)(b * 32 + ch) * 512 + c] = acc;
        }
    } else {
        // activation f32 -> f16: 3 tensors x 1024 blocks x 2048 elements
        int cb = bx - 4160;
        int tt = cb >> 10, bi = cb & 1023;
        const float* src = (tt == 0) ? query : (tt == 1) ? key_t : value;
        __half* dst = x16 + (size_t)tt * M_TOT * HH;
        size_t base = (size_t)bi * 2048 + tid * 8;
        float4 f0 = *(const float4*)(src + base);
        float4 f1 = *(const float4*)(src + base + 4);
        uint4 o;
        o.x = pack_h2(f0.x, f0.y);
        o.y = pack_h2(f0.z, f0.w);
        o.z = pack_h2(f1.x, f1.y);
        o.w = pack_h2(f1.z, f1.w);
        *(uint4*)(dst + base) = o;
    }
}

// -------- spec layer-2: grid(16 colblocks, BB), 256 thr --------------------
__global__ void spec2_kernel(const float* __restrict__ bs1,
                             const float* __restrict__ Ws2,
                             const float* __restrict__ bs2)
{
    __shared__ float h1[512];
    __shared__ float zp[4][64];
    __shared__ float red[64];
    int b = blockIdx.y, cb = blockIdx.x;
    int tid = threadIdx.x;
    for (int c = tid; c < 512; c += 256) {
        float s = bs1[c];
        #pragma unroll
        for (int ch = 0; ch < 32; ch++) s += g_h1p[(size_t)(b * 32 + ch) * 512 + c];
        h1[c] = fmaxf(s, 0.f);
    }
    __syncthreads();
    int col = cb * 64 + (tid & 63);
    int qq = tid >> 6;
    float z = 0.f;
    #pragma unroll 4
    for (int i = qq * 128; i < qq * 128 + 128; i++)
        z += h1[i] * Ws2[(size_t)i * HH + col];
    zp[qq][tid & 63] = z;
    __syncthreads();
    if (tid < 64) {
        float zz = bs2[cb * 64 + tid] + zp[0][tid] + zp[1][tid] + zp[2][tid] + zp[3][tid];
        red[tid] = 1.0f / (1.0f + __expf(-zz));
    }
    __syncthreads();
    for (int off = 32; off > 0; off >>= 1) {
        if (tid < off) red[tid] += red[tid + off];
        __syncthreads();
    }
    if (tid == 0) g_sp[b * 16 + cb] = red[0];
}

// ==  flash attention: ALL f16 operands, f32 accum; 32-key double-buffer  ====
// smem: K0,K1 (32x144B) V0,V1 (64x80B) P (128x80B) = 29696 B
#define KSTR 144                       // Q-staging / K row stride (f16: 64 halves)
#define HSTR 80                        // P / V row stride (f16: 32 halves)
#define K0_OFF 0
#define K1_OFF 4608
#define V0_OFF 9216
#define V1_OFF 14336
#define P_OFF  19456
#define A_SMEM 29696

__global__ void __launch_bounds__(256, 2)
attn_mma(const float* __restrict__ msb)
{
    extern __shared__ char smem[];
    __shared__ float red[256];
    __shared__ float mh_s;
    uint32_t sb = smem_u32(smem);
    const int tid = threadIdx.x;
    const int lane = tid & 31;
    const int w = tid >> 5;
    const int b = blockIdx.z, h = blockIdx.y, q0 = blockIdx.x << 7;

    const uint32_t Pa = sb + P_OFF + (uint32_t)((16 * w + (lane & 15)) * HSTR + (lane >> 4) * 16);
    const uint32_t krow = (uint32_t)(((((lane >> 4) << 3) + (lane & 7)) * KSTR) + ((lane >> 3) & 1) * 16);
    const uint32_t vrow = (uint32_t)(((((lane >> 4) << 3) + (lane & 7)) * HSTR) + ((lane >> 3) & 1) * 16);
    const uint32_t Kb[2] = { sb + K0_OFF + krow, sb + K1_OFF + krow };
    const uint32_t Vb[2] = { sb + V0_OFF + vrow, sb + V1_OFF + vrow };
    const uint32_t koff[2] = { K0_OFF, K1_OFF };
    const uint32_t voff[2] = { V0_OFF, V1_OFF };

    const __half* Kg0 = g_Kh + (size_t)b * SS * HH + h * HDD;
    const __half* Vg0 = g_VTh + (size_t)(b * NHH + h) * HDD * SS;

    auto load_tile = [&](int bufsel, int kt) {
        const __half* Kg = Kg0 + (size_t)kt * 32 * HH;
        const __half* Vg = Vg0 + kt * 32;
        {
            int rk = tid >> 3, ck = tid & 7;
            cp16(sb + koff[bufsel] + (uint32_t)(rk * KSTR + ck * 16),
                 Kg + (size_t)rk * HH + ck * 8);
        }
        {
            int rv = tid >> 2, cv = tid & 3;
            cp16(sb + voff[bufsel] + (uint32_t)(rv * HSTR + cv * 16),
                 Vg + (size_t)rv * SS + cv * 8);
        }
        CP_COMMIT();
    };

    // ---- prologue: stage Q (f16), msb reduce ----
    {
        const __half* Qg = g_Qh + ((size_t)b * SS + q0) * HH + h * HDD;
        #pragma unroll
        for (int i = 0; i < 4; i++) {
            int f = tid + i * 256;
            int r = f >> 3, c8 = f & 7;
            cp16(sb + (uint32_t)(r * KSTR + c8 * 16),
                 Qg + (size_t)r * HH + c8 * 8);
        }
        CP_COMMIT();
    }
    {
        const float* p = msb + (size_t)h * HDD * HDD;
        float s = 0.f;
        for (int i = tid; i < HDD * HDD; i += 256) s += p[i];
        red[tid] = s;
        __syncthreads();
        for (int off = 128; off > 0; off >>= 1) {
            if (tid < off) red[tid] += red[tid + off];
            __syncthreads();
        }
        if (tid == 0) mh_s = red[0] * (1.0f / (HDD * HDD));
    }
    CP_WAIT0();
    __syncthreads();

    uint32_t qf[4][4];
    {
        uint32_t Qa = sb + (uint32_t)((16 * w + (lane & 15)) * KSTR + (lane >> 4) * 16);
        #pragma unroll
        for (int ks = 0; ks < 4; ks++) ldsm4(qf[ks], Qa + ks * 32);
    }
    __syncthreads();
    load_tile(0, 0);

    const float mh = mh_s;
    float sp = 0.f;
    #pragma unroll
    for (int j = 0; j < 16; j++) sp += g_sp[b * 16 + j];
    sp *= (1.0f / HH);

    const float a2 = 0.5f * SCALE_C * mh;
    const float c1 = SCALE_C * sp * (1.0f + 0.5f * SP_C);
    const float c3 = SCALE_C * sp * (0.5f * SP_C);

    CP_WAIT0();
    __syncthreads();

    float oacc[8][4] = {};
    float m0 = -1e30f, m1 = -1e30f, l0 = 0.f, l1 = 0.f;

    for (int kt = 0; kt < 32; kt++) {
        int cur = kt & 1;
        if (kt + 1 < 32) load_tile(cur ^ 1, kt + 1);

        // ---- S = Q @ K^T ----
        float sacc[4][4] = {};
        #pragma unroll
        for (int ks = 0; ks < 4; ks++) {
            #pragma unroll
            for (int kb = 0; kb < 2; kb++) {
                uint32_t bb[4];
                ldsm4(bb, Kb[cur] + kb * 16 * KSTR + ks * 32);
                mma16f(sacc[2 * kb],     qf[ks], bb);
                mma16f(sacc[2 * kb + 1], qf[ks], bb + 2);
            }
        }

        // ---- gate + online softmax ----
        float tm0 = -1e30f, tm1 = -1e30f;
        #pragma unroll
        for (int nf = 0; nf < 4; nf++) {
            #pragma unroll
            for (int j = 0; j < 4; j++) {
                float s = sacc[nf][j];
                float th = tanh_fast(s * a2);
                float p = fmaf(s * c3, th, s * c1);
                sacc[nf][j] = p;
                if (j < 2) tm0 = fmaxf(tm0, p); else tm1 = fmaxf(tm1, p);
            }
        }
        tm0 = fmaxf(tm0, __shfl_xor_sync(0xffffffff, tm0, 1));
        tm0 = fmaxf(tm0, __shfl_xor_sync(0xffffffff, tm0, 2));
        tm1 = fmaxf(tm1, __shfl_xor_sync(0xffffffff, tm1, 1));
        tm1 = fmaxf(tm1, __shfl_xor_sync(0xffffffff, tm1, 2));

        float nm0 = fmaxf(m0, tm0), nm1 = fmaxf(m1, tm1);
        float sc0 = __expf(m0 - nm0), sc1 = __expf(m1 - nm1);
        float su0 = 0.f, su1 = 0.f;
        #pragma unroll
        for (int nf = 0; nf < 4; nf++) {
            float p0 = __expf(sacc[nf][0] - nm0);
            float p1 = __expf(sacc[nf][1] - nm0);
            float p2 = __expf(sacc[nf][2] - nm1);
            float p3 = __expf(sacc[nf][3] - nm1);
            su0 += p0 + p1; su1 += p2 + p3;
            sacc[nf][0] = p0; sacc[nf][1] = p1;
            sacc[nf][2] = p2; sacc[nf][3] = p3;
        }
        su0 += __shfl_xor_sync(0xffffffff, su0, 1);
        su0 += __shfl_xor_sync(0xffffffff, su0, 2);
        su1 += __shfl_xor_sync(0xffffffff, su1, 1);
        su1 += __shfl_xor_sync(0xffffffff, su1, 2);
        l0 = l0 * sc0 + su0;
        l1 = l1 * sc1 + su1;
        m0 = nm0; m1 = nm1;

        #pragma unroll
        for (int nf = 0; nf < 8; nf++) {
            oacc[nf][0] *= sc0; oacc[nf][1] *= sc0;
            oacc[nf][2] *= sc1; oacc[nf][3] *= sc1;
        }

        // ---- write P as packed f16 ----
        {
            int r0 = 16 * w + (lane >> 2);
            uint32_t p0a = (uint32_t)(P_OFF + r0 * HSTR + (lane & 3) * 4);
            #pragma unroll
            for (int nf = 0; nf < 4; nf++) {
                *(uint32_t*)(smem + p0a + nf * 16) =
                    pack_h2(sacc[nf][0], sacc[nf][1]);
                *(uint32_t*)(smem + p0a + 8 * HSTR + nf * 16) =
                    pack_h2(sacc[nf][2], sacc[nf][3]);
            }
        }
        __syncwarp();

        // ---- O += P @ V ----
        #pragma unroll
        for (int kb = 0; kb < 2; kb++) {
            uint32_t a[4];
            ldsm4(a, Pa + kb * 32);
            #pragma unroll
            for (int db = 0; db < 4; db++) {
                uint32_t bb[4];
                ldsm4(bb, Vb[cur] + db * 16 * HSTR + kb * 32);
                mma16f(oacc[2 * db],     a, bb);
                mma16f(oacc[2 * db + 1], a, bb + 2);
            }
        }

        if (kt + 1 < 32) CP_WAIT0();
        __syncthreads();
    }

    // ---- epilogue: normalize + store ctx as f16 ----
    float inv0 = 1.0f / l0, inv1 = 1.0f / l1;
    __half* Og = g_ctxh + ((size_t)b * SS + q0) * HH + h * HDD;
    int r0 = 16 * w + (lane >> 2);
    #pragma unroll
    for (int nf = 0; nf < 8; nf++) {
        int c = 8 * nf + 2 * (lane & 3);
        *(uint32_t*)&Og[(size_t)r0 * HH + c] =
            pack_h2(oacc[nf][0] * inv0, oacc[nf][1] * inv0);
        *(uint32_t*)&Og[(size_t)(r0 + 8) * HH + c] =
            pack_h2(oacc[nf][2] * inv1, oacc[nf][3] * inv1);
    }
}

// ---------------- row LayerNorm ----------------
__global__ void ln_kernel(const float* __restrict__ x,
                          const float* __restrict__ g,
                          const float* __restrict__ bta,
                          float* __restrict__ out)
{
    __shared__ float r1[256];
    __shared__ float r2[256];
    int row = blockIdx.x, tid = threadIdx.x;
    const float4* xr = (const float4*)(x + (size_t)row * HH);
    float4 a = xr[tid];
    float s = a.x + a.y + a.z + a.w;
    float ss = a.x * a.x + a.y * a.y + a.z * a.z + a.w * a.w;
    r1[tid] = s; r2[tid] = ss;
    __syncthreads();
    for (int off = 128; off > 0; off >>= 1) {
        if (tid < off) { r1[tid] += r1[tid + off]; r2[tid] += r2[tid + off]; }
        __syncthreads();
    }
    float mu = r1[0] * (1.0f / HH);
    float var = r2[0] * (1.0f / HH) - mu * mu;
    float rstd = rsqrtf(var + EPS_C);
    float4 gg = ((const float4*)g)[tid];
    float4 bb = ((const float4*)bta)[tid];
    float4 o;
    o.x = (a.x - mu) * rstd * gg.x + bb.x;
    o.y = (a.y - mu) * rstd * gg.y + bb.y;
    o.z = (a.z - mu) * rstd * gg.z + bb.z;
    o.w = (a.w - mu) * rstd * gg.w + bb.w;
    ((float4*)(out + (size_t)row * HH))[tid] = o;
}

// ---------------- launch ----------------
extern "C" void kernel_launch(void* const* d_in, const int* in_sizes, int n_in,
                              void* d_out, int out_size)
{
    const float* query = (const float*)d_in[0];
    const float* key_t = (const float*)d_in[1];
    const float* value = (const float*)d_in[2];
    const float* Wq = (const float*)d_in[3];
    const float* bq = (const float*)d_in[4];
    const float* Wk = (const float*)d_in[5];
    const float* bk = (const float*)d_in[6];
    const float* Wv = (const float*)d_in[7];
    const float* bv = (const float*)d_in[8];
    const float* msb = (const float*)d_in[9];
    const float* Ws1 = (const float*)d_in[10];
    const float* bs1 = (const float*)d_in[11];
    const float* Ws2 = (const float*)d_in[12];
    const float* bs2 = (const float*)d_in[13];
    const float* Wo = (const float*)d_in[14];
    const float* bo = (const float*)d_in[15];
    const float* ln_g = (const float*)d_in[16];
    const float* ln_b = (const float*)d_in[17];

    float *pPre;
    __half *pQh, *pKh, *pVTh, *pCtxh, *pWTh, *pX16;
    cudaGetSymbolAddress((void**)&pQh, g_Qh);
    cudaGetSymbolAddress((void**)&pKh, g_Kh);
    cudaGetSymbolAddress((void**)&pVTh, g_VTh);
    cudaGetSymbolAddress((void**)&pCtxh, g_ctxh);
    cudaGetSymbolAddress((void**)&pPre, g_pre);
    cudaGetSymbolAddress((void**)&pWTh, g_WTh);
    cudaGetSymbolAddress((void**)&pX16, g_x16);

    __half* WToh = pWTh + (size_t)3 * HH * HH;

    cudaFuncSetAttribute(qkv_gemm, cudaFuncAttributeMaxDynamicSharedMemorySize,
                         GSM_TOTAL);
    cudaFuncSetAttribute(o_gemm, cudaFuncAttributeMaxDynamicSharedMemorySize,
                         GSM_TOTAL);
    cudaFuncSetAttribute(attn_mma, cudaFuncAttributeMaxDynamicSharedMemorySize,
                         A_SMEM);

    // 0: fused pre-pass (weights->f16 transposed, spec1, activations->f16)
    fused_pre<<<7232, 256>>>(Wq, Wk, Wv, Wo, pWTh,
                             query, key_t, value, pX16, Ws1);
    // 1: spec layer-2
    spec2_kernel<<<dim3(16, BB), 256>>>(bs1, Ws2, bs2);
    // 2: fused Q/K/V projection GEMM (f16 operands)
    qkv_gemm<<<dim3(GN / 128, M_TOT / 128, 3), 256, GSM_TOTAL>>>(
        pX16, pWTh, bq, bk, bv, pQh, pKh, pVTh);
    // 3 (profiled slot): flash attention
    attn_mma<<<dim3(SS / 128, NHH, BB), 256, A_SMEM>>>(msb);
    // 4: output projection (f16 operands) + bias + residual (f32)
    o_gemm<<<dim3(GN / 128, M_TOT / 128), 256, GSM_TOTAL>>>(
        pCtxh, WToh, bo, query, pPre);
    // 5: LayerNorm -> d_out
    ln_kernel<<<M_TOT, 256>>>(pPre, ln_g, ln_b, (float*)d_out);
}